// round 4
// baseline (speedup 1.0000x reference)
#include <cuda_runtime.h>
#include <cuda_bf16.h>
#include <cstdint>

// ---------------- problem constants ----------------
#define NB      2048
#define NTOK    49
#define DIMC    512
#define QKV_N   1536
#define NHEAD   16
#define HDIM    32
#define NWIN    64
#define M_TOTAL (NB * NTOK)   // 100352

// ---------------- scratch (no allocs allowed) ----------------
__device__ float         g_qkv[(size_t)M_TOTAL * QKV_N];
__device__ __nv_bfloat16 g_xhi[(size_t)M_TOTAL * DIMC];
__device__ __nv_bfloat16 g_xlo[(size_t)M_TOTAL * DIMC];
__device__ __nv_bfloat16 g_ahi[(size_t)M_TOTAL * DIMC];
__device__ __nv_bfloat16 g_alo[(size_t)M_TOTAL * DIMC];
__device__ __nv_bfloat16 g_wq_hi[(size_t)QKV_N * DIMC];
__device__ __nv_bfloat16 g_wq_lo[(size_t)QKV_N * DIMC];
__device__ __nv_bfloat16 g_wp_hi[(size_t)DIMC * DIMC];
__device__ __nv_bfloat16 g_wp_lo[(size_t)DIMC * DIMC];

// ---------------- helpers ----------------
__device__ __forceinline__ uint32_t smem_to_u32(const void* p) {
    uint32_t a;
    asm("{ .reg .u64 t; cvta.to.shared.u64 t, %1; cvt.u32.u64 %0, t; }" : "=r"(a) : "l"(p));
    return a;
}
__device__ __forceinline__ void cp_async16(uint32_t saddr, const void* gaddr) {
    asm volatile("cp.async.cg.shared.global [%0], [%1], 16;" :: "r"(saddr), "l"(gaddr));
}
#define CP_COMMIT() asm volatile("cp.async.commit_group;")
#define CP_WAIT0()  asm volatile("cp.async.wait_group 0;")
#define CP_WAIT1()  asm volatile("cp.async.wait_group 1;")

__device__ __forceinline__ void ldsm4(uint32_t* r, uint32_t addr) {
    asm volatile("ldmatrix.sync.aligned.m8n8.x4.shared.b16 {%0,%1,%2,%3}, [%4];"
                 : "=r"(r[0]), "=r"(r[1]), "=r"(r[2]), "=r"(r[3]) : "r"(addr));
}
__device__ __forceinline__ void mma16816(float* d, const uint32_t* a,
                                         uint32_t b0, uint32_t b1) {
    asm volatile(
        "mma.sync.aligned.m16n8k16.row.col.f32.bf16.bf16.f32 "
        "{%0,%1,%2,%3}, {%4,%5,%6,%7}, {%8,%9}, {%0,%1,%2,%3};"
        : "+f"(d[0]), "+f"(d[1]), "+f"(d[2]), "+f"(d[3])
        : "r"(a[0]), "r"(a[1]), "r"(a[2]), "r"(a[3]), "r"(b0), "r"(b1));
}
__device__ __forceinline__ void split2(float v, __nv_bfloat16& h, __nv_bfloat16& l) {
    h = __float2bfloat16(v);
    l = __float2bfloat16(v - __bfloat162float(h));
}

// ---------------- conversion kernels ----------------
__global__ void __launch_bounds__(256) convert_split_kernel(
    const float* __restrict__ src, __nv_bfloat16* __restrict__ hi,
    __nv_bfloat16* __restrict__ lo, size_t n4)
{
    size_t i = (size_t)blockIdx.x * 256 + threadIdx.x;
    if (i >= n4) return;
    float4 v = reinterpret_cast<const float4*>(src)[i];
    __nv_bfloat16 h0, h1, h2, h3, l0, l1, l2, l3;
    split2(v.x, h0, l0); split2(v.y, h1, l1); split2(v.z, h2, l2); split2(v.w, h3, l3);
    __nv_bfloat162 ph0{h0, h1}, ph1{h2, h3}, pl0{l0, l1}, pl1{l2, l3};
    uint2 uh{*reinterpret_cast<uint32_t*>(&ph0), *reinterpret_cast<uint32_t*>(&ph1)};
    uint2 ul{*reinterpret_cast<uint32_t*>(&pl0), *reinterpret_cast<uint32_t*>(&pl1)};
    reinterpret_cast<uint2*>(hi)[i] = uh;
    reinterpret_cast<uint2*>(lo)[i] = ul;
}

// transpose W [K][N] -> W^T split [N][K]
__global__ void __launch_bounds__(256) wsplit_t_kernel(
    const float* __restrict__ w, __nv_bfloat16* __restrict__ hi,
    __nv_bfloat16* __restrict__ lo, int K, int N)
{
    int idx = blockIdx.x * 256 + threadIdx.x;
    if (idx >= N * K) return;
    int n = idx / K, k = idx - n * K;
    float v = w[(size_t)k * N + n];
    __nv_bfloat16 h, l;
    split2(v, h, l);
    hi[idx] = h; lo[idx] = l;
}

// ---------------- mma.sync 3xbf16 GEMM: C = A @ B^T + bias -----------------
// 128x128x64 tiles, 8 warps (4x2), warp tile 32x64, 3-stage cp.async pipeline.
// SMEM stage: Ah(16K) Al(16K) Bh(16K) Bl(16K); rows 128B pitch,
// chunk swizzle: 16B chunk c of row r stored at (c ^ (r&7)).
#define STAGE_BYTES 65536
#define NSTAGE      3
#define GEMM_SMEM   (NSTAGE * STAGE_BYTES)

__device__ __forceinline__ uint32_t sw_addr(uint32_t base, int row, int chunk) {
    return base + row * 128 + ((chunk ^ (row & 7)) << 4);
}

__global__ void __launch_bounds__(256, 1) gemm3_kernel(
    const __nv_bfloat16* __restrict__ Ah, const __nv_bfloat16* __restrict__ Al,
    const __nv_bfloat16* __restrict__ Bh, const __nv_bfloat16* __restrict__ Bl,
    const float* __restrict__ bias, float* __restrict__ C,
    int M, int N, int K)
{
    extern __shared__ char smem[];
    const uint32_t sbase = smem_to_u32(smem);
    const int tid  = threadIdx.x;
    const int lane = tid & 31;
    const int wid  = tid >> 5;
    const int warp_m = wid & 3;
    const int warp_n = wid >> 2;
    const int m0 = blockIdx.y * 128;
    const int n0 = blockIdx.x * 128;
    const int NKT = K >> 6;

    float acc[2][8][4];
    #pragma unroll
    for (int i = 0; i < 2; i++)
        #pragma unroll
        for (int j = 0; j < 8; j++)
            #pragma unroll
            for (int t = 0; t < 4; t++) acc[i][j][t] = 0.f;

    auto load_stage = [&](int kt, int s) {
        const uint32_t sb = sbase + s * STAGE_BYTES;
        const int kofs = kt * 64;
        #pragma unroll
        for (int i = 0; i < 4; i++) {
            int f   = tid + i * 256;
            int row = f >> 3;
            int c   = f & 7;
            uint32_t sw = sw_addr(0, row, c);
            size_t ga = (size_t)(m0 + row) * K + kofs + c * 8;
            size_t gb = (size_t)(n0 + row) * K + kofs + c * 8;
            cp_async16(sb + sw,         Ah + ga);
            cp_async16(sb + 16384 + sw, Al + ga);
            cp_async16(sb + 32768 + sw, Bh + gb);
            cp_async16(sb + 49152 + sw, Bl + gb);
        }
        CP_COMMIT();
    };

    load_stage(0, 0);
    if (NKT > 1) load_stage(1, 1);

    for (int kt = 0; kt < NKT; kt++) {
        const int s = kt % NSTAGE;
        if (kt + 1 < NKT) CP_WAIT1(); else CP_WAIT0();
        __syncthreads();
        if (kt + 2 < NKT) load_stage(kt + 2, (kt + 2) % NSTAGE);

        const uint32_t sA = sbase + s * STAGE_BYTES;
        const uint32_t sB = sA + 32768;

        #pragma unroll
        for (int ks = 0; ks < 4; ks++) {
            uint32_t ah[2][4], al[2][4];
            {
                const int arow = warp_m * 32 + (lane & 15);
                const int achk = 2 * ks + (lane >> 4);
                #pragma unroll
                for (int mt = 0; mt < 2; mt++) {
                    uint32_t ad = sw_addr(sA, arow + mt * 16, achk);
                    ldsm4(ah[mt], ad);
                    ldsm4(al[mt], ad + 16384);
                }
            }
            uint32_t bh[4][4], bl[4][4];
            {
                const int brow_base = warp_n * 64 + ((lane & 16) ? 8 : 0) + (lane & 7);
                const int bchk = 2 * ks + ((lane >> 3) & 1);
                #pragma unroll
                for (int p = 0; p < 4; p++) {
                    uint32_t bd = sw_addr(sB, brow_base + p * 16, bchk);
                    ldsm4(bh[p], bd);
                    ldsm4(bl[p], bd + 16384);
                }
            }
            #pragma unroll
            for (int mt = 0; mt < 2; mt++)
                #pragma unroll
                for (int p = 0; p < 4; p++)
                    #pragma unroll
                    for (int hlf = 0; hlf < 2; hlf++) {
                        const int nt = p * 2 + hlf;
                        mma16816(acc[mt][nt], ah[mt], bh[p][hlf*2], bh[p][hlf*2+1]);
                        mma16816(acc[mt][nt], ah[mt], bl[p][hlf*2], bl[p][hlf*2+1]);
                        mma16816(acc[mt][nt], al[mt], bh[p][hlf*2], bh[p][hlf*2+1]);
                    }
        }
        __syncthreads();
    }

    const int row0 = m0 + warp_m * 32 + (lane >> 2);
    const int col0 = n0 + warp_n * 64 + (lane & 3) * 2;
    #pragma unroll
    for (int mt = 0; mt < 2; mt++)
        #pragma unroll
        for (int nt = 0; nt < 8; nt++) {
            const int c = col0 + nt * 8;
            const float b0 = bias[c], b1 = bias[c + 1];
            const int r0 = row0 + mt * 16;
            float2 v0{acc[mt][nt][0] + b0, acc[mt][nt][1] + b1};
            float2 v1{acc[mt][nt][2] + b0, acc[mt][nt][3] + b1};
            *reinterpret_cast<float2*>(C + (size_t)r0 * N + c)       = v0;
            *reinterpret_cast<float2*>(C + (size_t)(r0 + 8) * N + c) = v1;
        }
}

// ---------------- fused window attention (fp32 in, bf16 hi/lo out) ---------
__global__ void __launch_bounds__(128) attn_kernel(
    const float* __restrict__ qkv, const float* __restrict__ mask,
    const float* __restrict__ bias_table, const int* __restrict__ rel_idx,
    __nv_bfloat16* __restrict__ out_hi, __nv_bfloat16* __restrict__ out_lo)
{
    const int b = blockIdx.x;
    const int h = blockIdx.y;
    const int tid = threadIdx.x;

    __shared__ float qs[NTOK * HDIM];
    __shared__ float kt[HDIM * NTOK];
    __shared__ float vs[NTOK * HDIM];
    __shared__ float s [NTOK * 50];

    const float scale = 0.17677669529663687f;

    for (int idx = tid; idx < NTOK * 8; idx += 128) {
        int n  = idx >> 3;
        int c4 = (idx & 7) << 2;
        size_t base = ((size_t)(b * NTOK + n)) * QKV_N + h * HDIM + c4;
        float4 qv = *reinterpret_cast<const float4*>(qkv + base);
        float4 kv = *reinterpret_cast<const float4*>(qkv + base + DIMC);
        float4 vv = *reinterpret_cast<const float4*>(qkv + base + 2 * DIMC);
        *reinterpret_cast<float4*>(&qs[n * HDIM + c4]) = qv;
        *reinterpret_cast<float4*>(&vs[n * HDIM + c4]) = vv;
        kt[(c4 + 0) * NTOK + n] = kv.x;
        kt[(c4 + 1) * NTOK + n] = kv.y;
        kt[(c4 + 2) * NTOK + n] = kv.z;
        kt[(c4 + 3) * NTOK + n] = kv.w;
    }
    __syncthreads();

    const float* mrow = mask + (size_t)(b & (NWIN - 1)) * NTOK * NTOK;
    for (int e = tid; e < NTOK * NTOK; e += 128) {
        int n = e / NTOK;
        int m = e - n * NTOK;
        float acc = 0.f;
        #pragma unroll
        for (int kk = 0; kk < HDIM; kk++)
            acc += qs[n * HDIM + kk] * kt[kk * NTOK + m];
        s[n * 50 + m] = acc * scale + bias_table[rel_idx[e] * NHEAD + h] + mrow[e];
    }
    __syncthreads();

    if (tid < NTOK) {
        const int r = tid;
        float mx = -1e30f;
        for (int m = 0; m < NTOK; m++) mx = fmaxf(mx, s[r * 50 + m]);
        float sum = 0.f;
        for (int m = 0; m < NTOK; m++) {
            float e = expf(s[r * 50 + m] - mx);
            s[r * 50 + m] = e;
            sum += e;
        }
        float inv = 1.f / sum;
        for (int m = 0; m < NTOK; m++) s[r * 50 + m] *= inv;
    }
    __syncthreads();

    for (int o = tid; o < NTOK * HDIM; o += 128) {
        int n = o >> 5;
        int d = o & 31;
        float acc = 0.f;
        #pragma unroll
        for (int m = 0; m < NTOK; m++)
            acc += s[n * 50 + m] * vs[m * HDIM + d];
        size_t oi = ((size_t)(b * NTOK + n)) * DIMC + h * HDIM + d;
        __nv_bfloat16 hb, lb;
        split2(acc, hb, lb);
        out_hi[oi] = hb;
        out_lo[oi] = lb;
    }
}

// ---------------- launcher ----------------
extern "C" void kernel_launch(void* const* d_in, const int* in_sizes, int n_in,
                              void* d_out, int out_size)
{
    const float* x          = (const float*)d_in[0];
    const float* mask       = (const float*)d_in[1];
    const float* qkv_w      = (const float*)d_in[2];
    const float* qkv_b      = (const float*)d_in[3];
    const float* proj_w     = (const float*)d_in[4];
    const float* proj_b     = (const float*)d_in[5];
    const float* bias_table = (const float*)d_in[6];
    const int*   rel_idx    = (const int*)d_in[7];
    float* out = (float*)d_out;

    float *qkv;
    __nv_bfloat16 *xhi, *xlo, *ahi, *alo, *wqh, *wql, *wph, *wpl;
    cudaGetSymbolAddress((void**)&qkv, g_qkv);
    cudaGetSymbolAddress((void**)&xhi, g_xhi);
    cudaGetSymbolAddress((void**)&xlo, g_xlo);
    cudaGetSymbolAddress((void**)&ahi, g_ahi);
    cudaGetSymbolAddress((void**)&alo, g_alo);
    cudaGetSymbolAddress((void**)&wqh, g_wq_hi);
    cudaGetSymbolAddress((void**)&wql, g_wq_lo);
    cudaGetSymbolAddress((void**)&wph, g_wp_hi);
    cudaGetSymbolAddress((void**)&wpl, g_wp_lo);

    cudaFuncSetAttribute(gemm3_kernel, cudaFuncAttributeMaxDynamicSharedMemorySize, GEMM_SMEM);

    size_t n4 = (size_t)M_TOTAL * DIMC / 4;
    convert_split_kernel<<<(unsigned)((n4 + 255) / 256), 256>>>(x, xhi, xlo, n4);
    wsplit_t_kernel<<<(QKV_N * DIMC + 255) / 256, 256>>>(qkv_w, wqh, wql, DIMC, QKV_N);
    wsplit_t_kernel<<<(DIMC * DIMC + 255) / 256, 256>>>(proj_w, wph, wpl, DIMC, DIMC);

    dim3 g1(QKV_N / 128, M_TOTAL / 128);
    gemm3_kernel<<<g1, 256, GEMM_SMEM>>>(xhi, xlo, wqh, wql, qkv_b, qkv,
                                         M_TOTAL, QKV_N, DIMC);

    dim3 g2(NB, NHEAD);
    attn_kernel<<<g2, 128>>>(qkv, mask, bias_table, rel_idx, ahi, alo);

    dim3 g3(DIMC / 128, M_TOTAL / 128);
    gemm3_kernel<<<g3, 256, GEMM_SMEM>>>(ahi, alo, wph, wpl, proj_b, out,
                                         M_TOTAL, DIMC, DIMC);
}

// round 7
// speedup vs baseline: 1.0026x; 1.0026x over previous
#include <cuda_runtime.h>
#include <cuda_bf16.h>
#include <cstdint>

// ---------------- problem constants ----------------
#define NB      2048
#define NTOK    49
#define DIMC    512
#define QKV_N   1536
#define NHEAD   16
#define HDIM    32
#define NWIN    64
#define M_TOTAL (NB * NTOK)   // 100352

// ---------------- scratch (no allocs allowed) ----------------
__device__ float         g_qkv[(size_t)M_TOTAL * QKV_N];
__device__ __nv_bfloat16 g_xhi[(size_t)M_TOTAL * DIMC];
__device__ __nv_bfloat16 g_xlo[(size_t)M_TOTAL * DIMC];
__device__ __nv_bfloat16 g_ahi[(size_t)M_TOTAL * DIMC];
__device__ __nv_bfloat16 g_alo[(size_t)M_TOTAL * DIMC];
__device__ __nv_bfloat16 g_wq_hi[(size_t)QKV_N * DIMC];
__device__ __nv_bfloat16 g_wq_lo[(size_t)QKV_N * DIMC];
__device__ __nv_bfloat16 g_wp_hi[(size_t)DIMC * DIMC];
__device__ __nv_bfloat16 g_wp_lo[(size_t)DIMC * DIMC];

// ---------------- helpers ----------------
__device__ __forceinline__ uint32_t smem_to_u32(const void* p) {
    uint32_t a;
    asm("{ .reg .u64 t; cvta.to.shared.u64 t, %1; cvt.u32.u64 %0, t; }" : "=r"(a) : "l"(p));
    return a;
}
__device__ __forceinline__ void cp_async16(uint32_t saddr, const void* gaddr) {
    asm volatile("cp.async.cg.shared.global [%0], [%1], 16;" :: "r"(saddr), "l"(gaddr));
}
#define CP_COMMIT() asm volatile("cp.async.commit_group;")
#define CP_WAIT0()  asm volatile("cp.async.wait_group 0;")

__device__ __forceinline__ void ldsm4(uint32_t* r, uint32_t addr) {
    asm volatile("ldmatrix.sync.aligned.m8n8.x4.shared.b16 {%0,%1,%2,%3}, [%4];"
                 : "=r"(r[0]), "=r"(r[1]), "=r"(r[2]), "=r"(r[3]) : "r"(addr));
}
__device__ __forceinline__ void mma16816(float* d, const uint32_t* a,
                                         uint32_t b0, uint32_t b1) {
    asm volatile(
        "mma.sync.aligned.m16n8k16.row.col.f32.bf16.bf16.f32 "
        "{%0,%1,%2,%3}, {%4,%5,%6,%7}, {%8,%9}, {%0,%1,%2,%3};"
        : "+f"(d[0]), "+f"(d[1]), "+f"(d[2]), "+f"(d[3])
        : "r"(a[0]), "r"(a[1]), "r"(a[2]), "r"(a[3]), "r"(b0), "r"(b1));
}
__device__ __forceinline__ void split2(float v, __nv_bfloat16& h, __nv_bfloat16& l) {
    h = __float2bfloat16(v);
    l = __float2bfloat16(v - __bfloat162float(h));
}

// ---------------- conversion kernels ----------------
__global__ void __launch_bounds__(256) convert_split_kernel(
    const float* __restrict__ src, __nv_bfloat16* __restrict__ hi,
    __nv_bfloat16* __restrict__ lo, size_t n4)
{
    size_t i = (size_t)blockIdx.x * 256 + threadIdx.x;
    if (i >= n4) return;
    float4 v = reinterpret_cast<const float4*>(src)[i];
    __nv_bfloat16 h0, h1, h2, h3, l0, l1, l2, l3;
    split2(v.x, h0, l0); split2(v.y, h1, l1); split2(v.z, h2, l2); split2(v.w, h3, l3);
    __nv_bfloat162 ph0{h0, h1}, ph1{h2, h3}, pl0{l0, l1}, pl1{l2, l3};
    uint2 uh{*reinterpret_cast<uint32_t*>(&ph0), *reinterpret_cast<uint32_t*>(&ph1)};
    uint2 ul{*reinterpret_cast<uint32_t*>(&pl0), *reinterpret_cast<uint32_t*>(&pl1)};
    reinterpret_cast<uint2*>(hi)[i] = uh;
    reinterpret_cast<uint2*>(lo)[i] = ul;
}

// transpose W [K][N] -> W^T split [N][K]
__global__ void __launch_bounds__(256) wsplit_t_kernel(
    const float* __restrict__ w, __nv_bfloat16* __restrict__ hi,
    __nv_bfloat16* __restrict__ lo, int K, int N)
{
    int idx = blockIdx.x * 256 + threadIdx.x;
    if (idx >= N * K) return;
    int n = idx / K, k = idx - n * K;
    float v = w[(size_t)k * N + n];
    __nv_bfloat16 h, l;
    split2(v, h, l);
    hi[idx] = h; lo[idx] = l;
}

// ---------------- mma.sync 3xbf16 GEMM: C = A @ B^T + bias -----------------
// 128x128x64 tiles, 8 warps (4x2), warp tile 32x64, 2-stage cp.async pipeline,
// register-double-buffered ldmatrix fragments across ks steps.
#define STAGE_BYTES 65536
#define GEMM_SMEM   (2 * STAGE_BYTES)

__device__ __forceinline__ uint32_t sw_addr(uint32_t base, int row, int chunk) {
    return base + row * 128 + ((chunk ^ (row & 7)) << 4);
}

__global__ void __launch_bounds__(256, 1) gemm3_kernel(
    const __nv_bfloat16* __restrict__ Ah, const __nv_bfloat16* __restrict__ Al,
    const __nv_bfloat16* __restrict__ Bh, const __nv_bfloat16* __restrict__ Bl,
    const float* __restrict__ bias, float* __restrict__ C,
    int M, int N, int K)
{
    extern __shared__ char smem[];
    const uint32_t sbase = smem_to_u32(smem);
    const int tid  = threadIdx.x;
    const int lane = tid & 31;
    const int wid  = tid >> 5;
    const int warp_m = wid & 3;
    const int warp_n = wid >> 2;
    const int m0 = blockIdx.y * 128;
    const int n0 = blockIdx.x * 128;
    const int NKT = K >> 6;

    float acc[2][8][4];
    #pragma unroll
    for (int i = 0; i < 2; i++)
        #pragma unroll
        for (int j = 0; j < 8; j++)
            #pragma unroll
            for (int t = 0; t < 4; t++) acc[i][j][t] = 0.f;

    auto load_stage = [&](int kt, int s) {
        const uint32_t sb = sbase + s * STAGE_BYTES;
        const int kofs = kt * 64;
        #pragma unroll
        for (int i = 0; i < 4; i++) {
            int f   = tid + i * 256;
            int row = f >> 3;
            int c   = f & 7;
            uint32_t sw = sw_addr(0, row, c);
            size_t ga = (size_t)(m0 + row) * K + kofs + c * 8;
            size_t gb = (size_t)(n0 + row) * K + kofs + c * 8;
            cp_async16(sb + sw,         Ah + ga);
            cp_async16(sb + 16384 + sw, Al + ga);
            cp_async16(sb + 32768 + sw, Bh + gb);
            cp_async16(sb + 49152 + sw, Bl + gb);
        }
        CP_COMMIT();
    };

    // fragment double buffers
    uint32_t ah[2][2][4], al[2][2][4];   // [buf][mt][4]
    uint32_t bh[2][4][4], bl[2][4][4];   // [buf][p][4]

    const int arow = warp_m * 32 + (lane & 15);
    const int brow = warp_n * 64 + ((lane & 16) ? 8 : 0) + (lane & 7);

    auto load_frags = [&](uint32_t sA, int ks, int buf) {
        const uint32_t sB = sA + 32768;
        const int achk = 2 * ks + (lane >> 4);
        const int bchk = 2 * ks + ((lane >> 3) & 1);
        #pragma unroll
        for (int mt = 0; mt < 2; mt++) {
            uint32_t ad = sw_addr(sA, arow + mt * 16, achk);
            ldsm4(ah[buf][mt], ad);
            ldsm4(al[buf][mt], ad + 16384);
        }
        #pragma unroll
        for (int p = 0; p < 4; p++) {
            uint32_t bd = sw_addr(sB, brow + p * 16, bchk);
            ldsm4(bh[buf][p], bd);
            ldsm4(bl[buf][p], bd + 16384);
        }
    };

    auto do_mmas = [&](int buf) {
        #pragma unroll
        for (int mt = 0; mt < 2; mt++)
            #pragma unroll
            for (int p = 0; p < 4; p++)
                #pragma unroll
                for (int hlf = 0; hlf < 2; hlf++) {
                    const int nt = p * 2 + hlf;
                    mma16816(acc[mt][nt], ah[buf][mt], bh[buf][p][hlf*2], bh[buf][p][hlf*2+1]);
                    mma16816(acc[mt][nt], ah[buf][mt], bl[buf][p][hlf*2], bl[buf][p][hlf*2+1]);
                    mma16816(acc[mt][nt], al[buf][mt], bh[buf][p][hlf*2], bh[buf][p][hlf*2+1]);
                }
    };

    load_stage(0, 0);

    for (int kt = 0; kt < NKT; kt++) {
        const int s = kt & 1;
        CP_WAIT0();
        __syncthreads();
        if (kt + 1 < NKT) load_stage(kt + 1, s ^ 1);

        const uint32_t sA = sbase + s * STAGE_BYTES;

        load_frags(sA, 0, 0);
        #pragma unroll
        for (int ks = 0; ks < 4; ks++) {
            if (ks < 3) load_frags(sA, ks + 1, (ks + 1) & 1);
            do_mmas(ks & 1);
        }
        __syncthreads();
    }

    const int row0 = m0 + warp_m * 32 + (lane >> 2);
    const int col0 = n0 + warp_n * 64 + (lane & 3) * 2;
    #pragma unroll
    for (int mt = 0; mt < 2; mt++)
        #pragma unroll
        for (int nt = 0; nt < 8; nt++) {
            const int c = col0 + nt * 8;
            const float b0 = bias[c], b1 = bias[c + 1];
            const int r0 = row0 + mt * 16;
            float2 v0{acc[mt][nt][0] + b0, acc[mt][nt][1] + b1};
            float2 v1{acc[mt][nt][2] + b0, acc[mt][nt][3] + b1};
            *reinterpret_cast<float2*>(C + (size_t)r0 * N + c)       = v0;
            *reinterpret_cast<float2*>(C + (size_t)(r0 + 8) * N + c) = v1;
        }
}

// ---------------- fused window attention (fp32 in, bf16 hi/lo out) ---------
__global__ void __launch_bounds__(128) attn_kernel(
    const float* __restrict__ qkv, const float* __restrict__ mask,
    const float* __restrict__ bias_table, const int* __restrict__ rel_idx,
    __nv_bfloat16* __restrict__ out_hi, __nv_bfloat16* __restrict__ out_lo)
{
    const int b = blockIdx.x;
    const int h = blockIdx.y;
    const int tid = threadIdx.x;

    __shared__ float qs[NTOK * HDIM];
    __shared__ float kt[HDIM * NTOK];
    __shared__ float vs[NTOK * HDIM];
    __shared__ float s [NTOK * 50];

    const float scale = 0.17677669529663687f;

    for (int idx = tid; idx < NTOK * 8; idx += 128) {
        int n  = idx >> 3;
        int c4 = (idx & 7) << 2;
        size_t base = ((size_t)(b * NTOK + n)) * QKV_N + h * HDIM + c4;
        float4 qv = *reinterpret_cast<const float4*>(qkv + base);
        float4 kv = *reinterpret_cast<const float4*>(qkv + base + DIMC);
        float4 vv = *reinterpret_cast<const float4*>(qkv + base + 2 * DIMC);
        *reinterpret_cast<float4*>(&qs[n * HDIM + c4]) = qv;
        *reinterpret_cast<float4*>(&vs[n * HDIM + c4]) = vv;
        kt[(c4 + 0) * NTOK + n] = kv.x;
        kt[(c4 + 1) * NTOK + n] = kv.y;
        kt[(c4 + 2) * NTOK + n] = kv.z;
        kt[(c4 + 3) * NTOK + n] = kv.w;
    }
    __syncthreads();

    const float* mrow = mask + (size_t)(b & (NWIN - 1)) * NTOK * NTOK;
    for (int e = tid; e < NTOK * NTOK; e += 128) {
        int n = e / NTOK;
        int m = e - n * NTOK;
        float acc = 0.f;
        #pragma unroll
        for (int kk = 0; kk < HDIM; kk++)
            acc += qs[n * HDIM + kk] * kt[kk * NTOK + m];
        s[n * 50 + m] = acc * scale + bias_table[rel_idx[e] * NHEAD + h] + mrow[e];
    }
    __syncthreads();

    if (tid < NTOK) {
        const int r = tid;
        float mx = -1e30f;
        for (int m = 0; m < NTOK; m++) mx = fmaxf(mx, s[r * 50 + m]);
        float sum = 0.f;
        for (int m = 0; m < NTOK; m++) {
            float e = expf(s[r * 50 + m] - mx);
            s[r * 50 + m] = e;
            sum += e;
        }
        float inv = 1.f / sum;
        for (int m = 0; m < NTOK; m++) s[r * 50 + m] *= inv;
    }
    __syncthreads();

    for (int o = tid; o < NTOK * HDIM; o += 128) {
        int n = o >> 5;
        int d = o & 31;
        float acc = 0.f;
        #pragma unroll
        for (int m = 0; m < NTOK; m++)
            acc += s[n * 50 + m] * vs[m * HDIM + d];
        size_t oi = ((size_t)(b * NTOK + n)) * DIMC + h * HDIM + d;
        __nv_bfloat16 hb, lb;
        split2(acc, hb, lb);
        out_hi[oi] = hb;
        out_lo[oi] = lb;
    }
}

// ---------------- launcher ----------------
extern "C" void kernel_launch(void* const* d_in, const int* in_sizes, int n_in,
                              void* d_out, int out_size)
{
    const float* x          = (const float*)d_in[0];
    const float* mask       = (const float*)d_in[1];
    const float* qkv_w      = (const float*)d_in[2];
    const float* qkv_b      = (const float*)d_in[3];
    const float* proj_w     = (const float*)d_in[4];
    const float* proj_b     = (const float*)d_in[5];
    const float* bias_table = (const float*)d_in[6];
    const int*   rel_idx    = (const int*)d_in[7];
    float* out = (float*)d_out;

    float *qkv;
    __nv_bfloat16 *xhi, *xlo, *ahi, *alo, *wqh, *wql, *wph, *wpl;
    cudaGetSymbolAddress((void**)&qkv, g_qkv);
    cudaGetSymbolAddress((void**)&xhi, g_xhi);
    cudaGetSymbolAddress((void**)&xlo, g_xlo);
    cudaGetSymbolAddress((void**)&ahi, g_ahi);
    cudaGetSymbolAddress((void**)&alo, g_alo);
    cudaGetSymbolAddress((void**)&wqh, g_wq_hi);
    cudaGetSymbolAddress((void**)&wql, g_wq_lo);
    cudaGetSymbolAddress((void**)&wph, g_wp_hi);
    cudaGetSymbolAddress((void**)&wpl, g_wp_lo);

    cudaFuncSetAttribute(gemm3_kernel, cudaFuncAttributeMaxDynamicSharedMemorySize, GEMM_SMEM);

    size_t n4 = (size_t)M_TOTAL * DIMC / 4;
    convert_split_kernel<<<(unsigned)((n4 + 255) / 256), 256>>>(x, xhi, xlo, n4);
    wsplit_t_kernel<<<(QKV_N * DIMC + 255) / 256, 256>>>(qkv_w, wqh, wql, DIMC, QKV_N);
    wsplit_t_kernel<<<(DIMC * DIMC + 255) / 256, 256>>>(proj_w, wph, wpl, DIMC, DIMC);

    dim3 g1(QKV_N / 128, M_TOTAL / 128);
    gemm3_kernel<<<g1, 256, GEMM_SMEM>>>(xhi, xlo, wqh, wql, qkv_b, qkv,
                                         M_TOTAL, QKV_N, DIMC);

    dim3 g2(NB, NHEAD);
    attn_kernel<<<g2, 128>>>(qkv, mask, bias_table, rel_idx, ahi, alo);

    dim3 g3(DIMC / 128, M_TOTAL / 128);
    gemm3_kernel<<<g3, 256, GEMM_SMEM>>>(ahi, alo, wph, wpl, proj_b, out,
                                         M_TOTAL, DIMC, DIMC);
}

// round 9
// speedup vs baseline: 1.0532x; 1.0505x over previous
#include <cuda_runtime.h>
#include <cuda_bf16.h>
#include <cstdint>

// ---------------- problem constants ----------------
#define NB      2048
#define NTOK    49
#define DIMC    512
#define QKV_N   1536
#define NHEAD   16
#define HDIM    32
#define NWIN    64
#define M_TOTAL (NB * NTOK)   // 100352

// ---------------- scratch (no allocs allowed) ----------------
__device__ float         g_qkv[(size_t)M_TOTAL * QKV_N];
__device__ __nv_bfloat16 g_xhi[(size_t)M_TOTAL * DIMC];
__device__ __nv_bfloat16 g_xlo[(size_t)M_TOTAL * DIMC];
__device__ __nv_bfloat16 g_ahi[(size_t)M_TOTAL * DIMC];
__device__ __nv_bfloat16 g_alo[(size_t)M_TOTAL * DIMC];
__device__ __nv_bfloat16 g_wq_hi[(size_t)QKV_N * DIMC];
__device__ __nv_bfloat16 g_wq_lo[(size_t)QKV_N * DIMC];
__device__ __nv_bfloat16 g_wp_hi[(size_t)DIMC * DIMC];
__device__ __nv_bfloat16 g_wp_lo[(size_t)DIMC * DIMC];

// ---------------- helpers ----------------
__device__ __forceinline__ uint32_t smem_to_u32(const void* p) {
    uint32_t a;
    asm("{ .reg .u64 t; cvta.to.shared.u64 t, %1; cvt.u32.u64 %0, t; }" : "=r"(a) : "l"(p));
    return a;
}
__device__ __forceinline__ void cp_async16(uint32_t saddr, const void* gaddr) {
    asm volatile("cp.async.cg.shared.global [%0], [%1], 16;" :: "r"(saddr), "l"(gaddr));
}
#define CP_COMMIT() asm volatile("cp.async.commit_group;")
#define CP_WAIT0()  asm volatile("cp.async.wait_group 0;")

__device__ __forceinline__ void ldsm4(uint32_t* r, uint32_t addr) {
    asm volatile("ldmatrix.sync.aligned.m8n8.x4.shared.b16 {%0,%1,%2,%3}, [%4];"
                 : "=r"(r[0]), "=r"(r[1]), "=r"(r[2]), "=r"(r[3]) : "r"(addr));
}
__device__ __forceinline__ void mma16816(float* d, const uint32_t* a,
                                         uint32_t b0, uint32_t b1) {
    asm volatile(
        "mma.sync.aligned.m16n8k16.row.col.f32.bf16.bf16.f32 "
        "{%0,%1,%2,%3}, {%4,%5,%6,%7}, {%8,%9}, {%0,%1,%2,%3};"
        : "+f"(d[0]), "+f"(d[1]), "+f"(d[2]), "+f"(d[3])
        : "r"(a[0]), "r"(a[1]), "r"(a[2]), "r"(a[3]), "r"(b0), "r"(b1));
}
__device__ __forceinline__ void split2(float v, __nv_bfloat16& h, __nv_bfloat16& l) {
    h = __float2bfloat16(v);
    l = __float2bfloat16(v - __bfloat162float(h));
}

// ---------------- conversion kernels ----------------
__global__ void __launch_bounds__(256) convert_split_kernel(
    const float* __restrict__ src, __nv_bfloat16* __restrict__ hi,
    __nv_bfloat16* __restrict__ lo, size_t n4)
{
    size_t i = (size_t)blockIdx.x * 256 + threadIdx.x;
    if (i >= n4) return;
    float4 v = reinterpret_cast<const float4*>(src)[i];
    __nv_bfloat16 h0, h1, h2, h3, l0, l1, l2, l3;
    split2(v.x, h0, l0); split2(v.y, h1, l1); split2(v.z, h2, l2); split2(v.w, h3, l3);
    __nv_bfloat162 ph0{h0, h1}, ph1{h2, h3}, pl0{l0, l1}, pl1{l2, l3};
    uint2 uh{*reinterpret_cast<uint32_t*>(&ph0), *reinterpret_cast<uint32_t*>(&ph1)};
    uint2 ul{*reinterpret_cast<uint32_t*>(&pl0), *reinterpret_cast<uint32_t*>(&pl1)};
    reinterpret_cast<uint2*>(hi)[i] = uh;
    reinterpret_cast<uint2*>(lo)[i] = ul;
}

__global__ void __launch_bounds__(256) wsplit_t_kernel(
    const float* __restrict__ w, __nv_bfloat16* __restrict__ hi,
    __nv_bfloat16* __restrict__ lo, int K, int N)
{
    int idx = blockIdx.x * 256 + threadIdx.x;
    if (idx >= N * K) return;
    int n = idx / K, k = idx - n * K;
    float v = w[(size_t)k * N + n];
    __nv_bfloat16 h, l;
    split2(v, h, l);
    hi[idx] = h; lo[idx] = l;
}

// ---------------- mma.sync 3xbf16 GEMM (best known: R2 2-stage) ------------
#define STAGE_BYTES 65536
#define GEMM_SMEM   (2 * STAGE_BYTES)

__device__ __forceinline__ uint32_t sw_addr(uint32_t base, int row, int chunk) {
    return base + row * 128 + ((chunk ^ (row & 7)) << 4);
}

__global__ void __launch_bounds__(256, 1) gemm3_kernel(
    const __nv_bfloat16* __restrict__ Ah, const __nv_bfloat16* __restrict__ Al,
    const __nv_bfloat16* __restrict__ Bh, const __nv_bfloat16* __restrict__ Bl,
    const float* __restrict__ bias, float* __restrict__ C,
    int M, int N, int K)
{
    extern __shared__ char smem[];
    const uint32_t sbase = smem_to_u32(smem);
    const int tid  = threadIdx.x;
    const int lane = tid & 31;
    const int wid  = tid >> 5;
    const int warp_m = wid & 3;
    const int warp_n = wid >> 2;
    const int m0 = blockIdx.y * 128;
    const int n0 = blockIdx.x * 128;
    const int NKT = K >> 6;

    float acc[2][8][4];
    #pragma unroll
    for (int i = 0; i < 2; i++)
        #pragma unroll
        for (int j = 0; j < 8; j++)
            #pragma unroll
            for (int t = 0; t < 4; t++) acc[i][j][t] = 0.f;

    auto load_stage = [&](int kt, int s) {
        const uint32_t sb = sbase + s * STAGE_BYTES;
        const int kofs = kt * 64;
        #pragma unroll
        for (int i = 0; i < 4; i++) {
            int f   = tid + i * 256;
            int row = f >> 3;
            int c   = f & 7;
            uint32_t sw = sw_addr(0, row, c);
            size_t ga = (size_t)(m0 + row) * K + kofs + c * 8;
            size_t gb = (size_t)(n0 + row) * K + kofs + c * 8;
            cp_async16(sb + sw,         Ah + ga);
            cp_async16(sb + 16384 + sw, Al + ga);
            cp_async16(sb + 32768 + sw, Bh + gb);
            cp_async16(sb + 49152 + sw, Bl + gb);
        }
        CP_COMMIT();
    };

    load_stage(0, 0);

    for (int kt = 0; kt < NKT; kt++) {
        const int s = kt & 1;
        CP_WAIT0();
        __syncthreads();
        if (kt + 1 < NKT) load_stage(kt + 1, s ^ 1);

        const uint32_t sA = sbase + s * STAGE_BYTES;
        const uint32_t sB = sA + 32768;

        #pragma unroll
        for (int ks = 0; ks < 4; ks++) {
            uint32_t ah[2][4], al[2][4];
            {
                const int arow = warp_m * 32 + (lane & 15);
                const int achk = 2 * ks + (lane >> 4);
                #pragma unroll
                for (int mt = 0; mt < 2; mt++) {
                    uint32_t ad = sw_addr(sA, arow + mt * 16, achk);
                    ldsm4(ah[mt], ad);
                    ldsm4(al[mt], ad + 16384);
                }
            }
            uint32_t bh[4][4], bl[4][4];
            {
                const int brow_base = warp_n * 64 + ((lane & 16) ? 8 : 0) + (lane & 7);
                const int bchk = 2 * ks + ((lane >> 3) & 1);
                #pragma unroll
                for (int p = 0; p < 4; p++) {
                    uint32_t bd = sw_addr(sB, brow_base + p * 16, bchk);
                    ldsm4(bh[p], bd);
                    ldsm4(bl[p], bd + 16384);
                }
            }
            #pragma unroll
            for (int mt = 0; mt < 2; mt++)
                #pragma unroll
                for (int p = 0; p < 4; p++)
                    #pragma unroll
                    for (int hlf = 0; hlf < 2; hlf++) {
                        const int nt = p * 2 + hlf;
                        mma16816(acc[mt][nt], ah[mt], bh[p][hlf*2], bh[p][hlf*2+1]);
                        mma16816(acc[mt][nt], ah[mt], bl[p][hlf*2], bl[p][hlf*2+1]);
                        mma16816(acc[mt][nt], al[mt], bh[p][hlf*2], bh[p][hlf*2+1]);
                    }
        }
        __syncthreads();
    }

    const int row0 = m0 + warp_m * 32 + (lane >> 2);
    const int col0 = n0 + warp_n * 64 + (lane & 3) * 2;
    #pragma unroll
    for (int mt = 0; mt < 2; mt++)
        #pragma unroll
        for (int nt = 0; nt < 8; nt++) {
            const int c = col0 + nt * 8;
            const float b0 = bias[c], b1 = bias[c + 1];
            const int r0 = row0 + mt * 16;
            float2 v0{acc[mt][nt][0] + b0, acc[mt][nt][1] + b1};
            float2 v1{acc[mt][nt][2] + b0, acc[mt][nt][3] + b1};
            *reinterpret_cast<float2*>(C + (size_t)r0 * N + c)       = v0;
            *reinterpret_cast<float2*>(C + (size_t)(r0 + 8) * N + c) = v1;
        }
}

// ---------------- fused window attention v2 (register-blocked) -------------
// lane = row (2 rows: lane, lane+32); S: warp owns 16-wide m-block;
// PV: warp owns 8-wide d-block. Broadcast-heavy smem access pattern.
// NOTE: all shared arrays are 16B-aligned (float4/uint4 access).
#define QS_STRIDE 33
#define KT_STRIDE 64
#define VS_STRIDE 36
#define SS_STRIDE 51

__global__ void __launch_bounds__(128) attn_kernel(
    const float* __restrict__ qkv, const float* __restrict__ mask,
    const float* __restrict__ bias_table, const int* __restrict__ rel_idx,
    __nv_bfloat16* __restrict__ out_hi, __nv_bfloat16* __restrict__ out_lo)
{
    const int b = blockIdx.x;
    const int h = blockIdx.y;
    const int tid  = threadIdx.x;
    const int lane = tid & 31;
    const int wid  = tid >> 5;

    __shared__ __align__(16) float qs[NTOK * QS_STRIDE];   // q (pre-scaled) [r][d]
    __shared__ __align__(16) float kt[HDIM * KT_STRIDE];   // kT [d][m], m padded to 64
    __shared__ __align__(16) float vs[NTOK * VS_STRIDE];   // v  [m][d]
    __shared__ __align__(16) float ss[NTOK * SS_STRIDE];   // S -> P
    __shared__ __align__(16) float sinv[NTOK];             // 1/rowsum

    const float scale = 0.17677669529663687f;

    // ---- load q (scaled), kT, v ----
    for (int idx = tid; idx < NTOK * 8; idx += 128) {
        int n  = idx >> 3;
        int c4 = (idx & 7) << 2;
        size_t base = ((size_t)(b * NTOK + n)) * QKV_N + h * HDIM + c4;
        float4 qv = *reinterpret_cast<const float4*>(qkv + base);
        float4 kv = *reinterpret_cast<const float4*>(qkv + base + DIMC);
        float4 vv = *reinterpret_cast<const float4*>(qkv + base + 2 * DIMC);
        qs[n * QS_STRIDE + c4 + 0] = qv.x * scale;
        qs[n * QS_STRIDE + c4 + 1] = qv.y * scale;
        qs[n * QS_STRIDE + c4 + 2] = qv.z * scale;
        qs[n * QS_STRIDE + c4 + 3] = qv.w * scale;
        kt[(c4 + 0) * KT_STRIDE + n] = kv.x;
        kt[(c4 + 1) * KT_STRIDE + n] = kv.y;
        kt[(c4 + 2) * KT_STRIDE + n] = kv.z;
        kt[(c4 + 3) * KT_STRIDE + n] = kv.w;
        *reinterpret_cast<float4*>(&vs[n * VS_STRIDE + c4]) = vv;
    }
    __syncthreads();

    // ---- S = q @ kT : warp wid covers m in [16*wid, 16*wid+16) ----
    {
        const int mbase = 16 * wid;
        const int r0 = lane;
        const int r1 = lane + 32;
        const bool has2 = (r1 < NTOK);
        float acc0[16], acc1[16];
        #pragma unroll
        for (int j = 0; j < 16; j++) { acc0[j] = 0.f; acc1[j] = 0.f; }
        #pragma unroll
        for (int d = 0; d < HDIM; d++) {
            float q0 = qs[r0 * QS_STRIDE + d];
            float q1 = has2 ? qs[r1 * QS_STRIDE + d] : 0.f;
            const float* kr = &kt[d * KT_STRIDE + mbase];
            float4 k0 = *reinterpret_cast<const float4*>(kr + 0);
            float4 k1 = *reinterpret_cast<const float4*>(kr + 4);
            float4 k2 = *reinterpret_cast<const float4*>(kr + 8);
            float4 k3 = *reinterpret_cast<const float4*>(kr + 12);
            float kk[16] = {k0.x,k0.y,k0.z,k0.w, k1.x,k1.y,k1.z,k1.w,
                            k2.x,k2.y,k2.z,k2.w, k3.x,k3.y,k3.z,k3.w};
            #pragma unroll
            for (int j = 0; j < 16; j++) {
                acc0[j] += q0 * kk[j];
                acc1[j] += q1 * kk[j];
            }
        }
        #pragma unroll
        for (int j = 0; j < 16; j++) {
            if (mbase + j < NTOK) {
                ss[r0 * SS_STRIDE + mbase + j] = acc0[j];
                if (has2) ss[r1 * SS_STRIDE + mbase + j] = acc1[j];
            }
        }
    }
    __syncthreads();

    // ---- softmax rows (bias + mask folded in; 1/sum deferred) ----
    if (tid < NTOK) {
        const int r = tid;
        const float* mrow = mask + (size_t)(b & (NWIN - 1)) * NTOK * NTOK + r * NTOK;
        const int*   rrow = rel_idx + r * NTOK;
        float mx = -1e30f;
        float v[NTOK];
        #pragma unroll 7
        for (int m = 0; m < NTOK; m++) {
            float t = ss[r * SS_STRIDE + m]
                    + bias_table[rrow[m] * NHEAD + h] + mrow[m];
            v[m] = t;
            mx = fmaxf(mx, t);
        }
        float sum = 0.f;
        #pragma unroll 7
        for (int m = 0; m < NTOK; m++) {
            float e = __expf(v[m] - mx);
            ss[r * SS_STRIDE + m] = e;
            sum += e;
        }
        sinv[r] = 1.f / sum;
    }
    __syncthreads();

    // ---- O = P @ v : warp wid covers d in [8*wid, 8*wid+8) ----
    {
        const int dbase = 8 * wid;
        const int r0 = lane;
        const int r1 = lane + 32;
        const bool has2 = (r1 < NTOK);
        float acc0[8], acc1[8];
        #pragma unroll
        for (int j = 0; j < 8; j++) { acc0[j] = 0.f; acc1[j] = 0.f; }
        for (int m = 0; m < NTOK; m++) {
            float4 v0 = *reinterpret_cast<const float4*>(&vs[m * VS_STRIDE + dbase]);
            float4 v1 = *reinterpret_cast<const float4*>(&vs[m * VS_STRIDE + dbase + 4]);
            float p0 = ss[r0 * SS_STRIDE + m];
            float p1 = has2 ? ss[r1 * SS_STRIDE + m] : 0.f;
            float vv[8] = {v0.x,v0.y,v0.z,v0.w, v1.x,v1.y,v1.z,v1.w};
            #pragma unroll
            for (int j = 0; j < 8; j++) {
                acc0[j] += p0 * vv[j];
                acc1[j] += p1 * vv[j];
            }
        }
        float i0 = sinv[r0];
        float i1 = has2 ? sinv[r1] : 0.f;
        {
            __nv_bfloat16 hb[8], lb[8];
            #pragma unroll
            for (int j = 0; j < 8; j++) split2(acc0[j] * i0, hb[j], lb[j]);
            size_t base = ((size_t)(b * NTOK + r0)) * DIMC + h * HDIM + dbase;
            *reinterpret_cast<uint4*>(&out_hi[base]) = *reinterpret_cast<uint4*>(hb);
            *reinterpret_cast<uint4*>(&out_lo[base]) = *reinterpret_cast<uint4*>(lb);
        }
        if (has2) {
            __nv_bfloat16 hb[8], lb[8];
            #pragma unroll
            for (int j = 0; j < 8; j++) split2(acc1[j] * i1, hb[j], lb[j]);
            size_t base = ((size_t)(b * NTOK + r1)) * DIMC + h * HDIM + dbase;
            *reinterpret_cast<uint4*>(&out_hi[base]) = *reinterpret_cast<uint4*>(hb);
            *reinterpret_cast<uint4*>(&out_lo[base]) = *reinterpret_cast<uint4*>(lb);
        }
    }
}

// ---------------- launcher ----------------
extern "C" void kernel_launch(void* const* d_in, const int* in_sizes, int n_in,
                              void* d_out, int out_size)
{
    const float* x          = (const float*)d_in[0];
    const float* mask       = (const float*)d_in[1];
    const float* qkv_w      = (const float*)d_in[2];
    const float* qkv_b      = (const float*)d_in[3];
    const float* proj_w     = (const float*)d_in[4];
    const float* proj_b     = (const float*)d_in[5];
    const float* bias_table = (const float*)d_in[6];
    const int*   rel_idx    = (const int*)d_in[7];
    float* out = (float*)d_out;

    float *qkv;
    __nv_bfloat16 *xhi, *xlo, *ahi, *alo, *wqh, *wql, *wph, *wpl;
    cudaGetSymbolAddress((void**)&qkv, g_qkv);
    cudaGetSymbolAddress((void**)&xhi, g_xhi);
    cudaGetSymbolAddress((void**)&xlo, g_xlo);
    cudaGetSymbolAddress((void**)&ahi, g_ahi);
    cudaGetSymbolAddress((void**)&alo, g_alo);
    cudaGetSymbolAddress((void**)&wqh, g_wq_hi);
    cudaGetSymbolAddress((void**)&wql, g_wq_lo);
    cudaGetSymbolAddress((void**)&wph, g_wp_hi);
    cudaGetSymbolAddress((void**)&wpl, g_wp_lo);

    cudaFuncSetAttribute(gemm3_kernel, cudaFuncAttributeMaxDynamicSharedMemorySize, GEMM_SMEM);

    size_t n4 = (size_t)M_TOTAL * DIMC / 4;
    convert_split_kernel<<<(unsigned)((n4 + 255) / 256), 256>>>(x, xhi, xlo, n4);
    wsplit_t_kernel<<<(QKV_N * DIMC + 255) / 256, 256>>>(qkv_w, wqh, wql, DIMC, QKV_N);
    wsplit_t_kernel<<<(DIMC * DIMC + 255) / 256, 256>>>(proj_w, wph, wpl, DIMC, DIMC);

    dim3 g1(QKV_N / 128, M_TOTAL / 128);
    gemm3_kernel<<<g1, 256, GEMM_SMEM>>>(xhi, xlo, wqh, wql, qkv_b, qkv,
                                         M_TOTAL, QKV_N, DIMC);

    dim3 g2(NB, NHEAD);
    attn_kernel<<<g2, 128>>>(qkv, mask, bias_table, rel_idx, ahi, alo);

    dim3 g3(DIMC / 128, M_TOTAL / 128);
    gemm3_kernel<<<g3, 256, GEMM_SMEM>>>(ahi, alo, wph, wpl, proj_b, out,
                                         M_TOTAL, DIMC, DIMC);
}

// round 10
// speedup vs baseline: 1.2299x; 1.1677x over previous
#include <cuda_runtime.h>
#include <cuda_fp16.h>
#include <cstdint>

// ---------------- problem constants ----------------
#define NB      2048
#define NTOK    49
#define DIMC    512
#define QKV_N   1536
#define NHEAD   16
#define HDIM    32
#define NWIN    64
#define M_TOTAL (NB * NTOK)   // 100352

// ---------------- scratch (no allocs allowed) ----------------
__device__ float  g_qkv[(size_t)M_TOTAL * QKV_N];
__device__ __half g_xhi[(size_t)M_TOTAL * DIMC];
__device__ __half g_xlo[(size_t)M_TOTAL * DIMC];
__device__ __half g_ahi[(size_t)M_TOTAL * DIMC];
__device__ __half g_alo[(size_t)M_TOTAL * DIMC];
__device__ __half g_wq_h[(size_t)QKV_N * DIMC];   // qkv_w^T fp16
__device__ __half g_wp_h[(size_t)DIMC * DIMC];    // proj_w^T fp16

// ---------------- helpers ----------------
__device__ __forceinline__ uint32_t smem_to_u32(const void* p) {
    uint32_t a;
    asm("{ .reg .u64 t; cvta.to.shared.u64 t, %1; cvt.u32.u64 %0, t; }" : "=r"(a) : "l"(p));
    return a;
}
__device__ __forceinline__ void cp_async16(uint32_t saddr, const void* gaddr) {
    asm volatile("cp.async.cg.shared.global [%0], [%1], 16;" :: "r"(saddr), "l"(gaddr));
}
#define CP_COMMIT() asm volatile("cp.async.commit_group;")
#define CP_WAIT0()  asm volatile("cp.async.wait_group 0;")

__device__ __forceinline__ void ldsm4(uint32_t* r, uint32_t addr) {
    asm volatile("ldmatrix.sync.aligned.m8n8.x4.shared.b16 {%0,%1,%2,%3}, [%4];"
                 : "=r"(r[0]), "=r"(r[1]), "=r"(r[2]), "=r"(r[3]) : "r"(addr));
}
__device__ __forceinline__ void mma16816(float* d, const uint32_t* a,
                                         uint32_t b0, uint32_t b1) {
    asm volatile(
        "mma.sync.aligned.m16n8k16.row.col.f32.f16.f16.f32 "
        "{%0,%1,%2,%3}, {%4,%5,%6,%7}, {%8,%9}, {%0,%1,%2,%3};"
        : "+f"(d[0]), "+f"(d[1]), "+f"(d[2]), "+f"(d[3])
        : "r"(a[0]), "r"(a[1]), "r"(a[2]), "r"(a[3]), "r"(b0), "r"(b1));
}
__device__ __forceinline__ void split2h(float v, __half& h, __half& l) {
    h = __float2half_rn(v);
    l = __float2half_rn(v - __half2float(h));
}

// ---------------- conversion kernels ----------------
__global__ void __launch_bounds__(256) convert_split_kernel(
    const float* __restrict__ src, __half* __restrict__ hi,
    __half* __restrict__ lo, size_t n4)
{
    size_t i = (size_t)blockIdx.x * 256 + threadIdx.x;
    if (i >= n4) return;
    float4 v = reinterpret_cast<const float4*>(src)[i];
    __half h0, h1, h2, h3, l0, l1, l2, l3;
    split2h(v.x, h0, l0); split2h(v.y, h1, l1);
    split2h(v.z, h2, l2); split2h(v.w, h3, l3);
    __half2 ph0 = __halves2half2(h0, h1), ph1 = __halves2half2(h2, h3);
    __half2 pl0 = __halves2half2(l0, l1), pl1 = __halves2half2(l2, l3);
    uint2 uh{*reinterpret_cast<uint32_t*>(&ph0), *reinterpret_cast<uint32_t*>(&ph1)};
    uint2 ul{*reinterpret_cast<uint32_t*>(&pl0), *reinterpret_cast<uint32_t*>(&pl1)};
    reinterpret_cast<uint2*>(hi)[i] = uh;
    reinterpret_cast<uint2*>(lo)[i] = ul;
}

// transpose W [K][N] -> W^T fp16 [N][K]
__global__ void __launch_bounds__(256) wh_t_kernel(
    const float* __restrict__ w, __half* __restrict__ hi, int K, int N)
{
    int idx = blockIdx.x * 256 + threadIdx.x;
    if (idx >= N * K) return;
    int n = idx / K, k = idx - n * K;
    hi[idx] = __float2half_rn(w[(size_t)k * N + n]);
}

// ---------------- mma.sync 2-term fp16 GEMM: C = A @ B^T + bias ------------
// A_{hi,lo}: [M][K] fp16, B_h: [N][K] fp16, C: [M][N] fp32.
// 128x128x64 tiles, 8 warps (4x2), warp tile 32x64, 2-stage cp.async pipeline.
// Stage: Ah(16K) Al(16K) Bh(16K) = 48K.
#define STAGE_BYTES 49152
#define GEMM_SMEM   (2 * STAGE_BYTES)

__device__ __forceinline__ uint32_t sw_addr(uint32_t base, int row, int chunk) {
    return base + row * 128 + ((chunk ^ (row & 7)) << 4);
}

__global__ void __launch_bounds__(256, 1) gemm2_kernel(
    const __half* __restrict__ Ah, const __half* __restrict__ Al,
    const __half* __restrict__ Bh,
    const float* __restrict__ bias, float* __restrict__ C,
    int M, int N, int K)
{
    extern __shared__ char smem[];
    const uint32_t sbase = smem_to_u32(smem);
    const int tid  = threadIdx.x;
    const int lane = tid & 31;
    const int wid  = tid >> 5;
    const int warp_m = wid & 3;
    const int warp_n = wid >> 2;
    const int m0 = blockIdx.y * 128;
    const int n0 = blockIdx.x * 128;
    const int NKT = K >> 6;

    float acc[2][8][4];
    #pragma unroll
    for (int i = 0; i < 2; i++)
        #pragma unroll
        for (int j = 0; j < 8; j++)
            #pragma unroll
            for (int t = 0; t < 4; t++) acc[i][j][t] = 0.f;

    auto load_stage = [&](int kt, int s) {
        const uint32_t sb = sbase + s * STAGE_BYTES;
        const int kofs = kt * 64;
        #pragma unroll
        for (int i = 0; i < 4; i++) {
            int f   = tid + i * 256;
            int row = f >> 3;
            int c   = f & 7;
            uint32_t sw = sw_addr(0, row, c);
            size_t ga = (size_t)(m0 + row) * K + kofs + c * 8;
            size_t gb = (size_t)(n0 + row) * K + kofs + c * 8;
            cp_async16(sb + sw,         Ah + ga);
            cp_async16(sb + 16384 + sw, Al + ga);
            cp_async16(sb + 32768 + sw, Bh + gb);
        }
        CP_COMMIT();
    };

    load_stage(0, 0);

    for (int kt = 0; kt < NKT; kt++) {
        const int s = kt & 1;
        CP_WAIT0();
        __syncthreads();
        if (kt + 1 < NKT) load_stage(kt + 1, s ^ 1);

        const uint32_t sA = sbase + s * STAGE_BYTES;
        const uint32_t sB = sA + 32768;

        #pragma unroll
        for (int ks = 0; ks < 4; ks++) {
            uint32_t ah[2][4], al[2][4];
            {
                const int arow = warp_m * 32 + (lane & 15);
                const int achk = 2 * ks + (lane >> 4);
                #pragma unroll
                for (int mt = 0; mt < 2; mt++) {
                    uint32_t ad = sw_addr(sA, arow + mt * 16, achk);
                    ldsm4(ah[mt], ad);
                    ldsm4(al[mt], ad + 16384);
                }
            }
            uint32_t bh[4][4];
            {
                const int brow_base = warp_n * 64 + ((lane & 16) ? 8 : 0) + (lane & 7);
                const int bchk = 2 * ks + ((lane >> 3) & 1);
                #pragma unroll
                for (int p = 0; p < 4; p++) {
                    uint32_t bd = sw_addr(sB, brow_base + p * 16, bchk);
                    ldsm4(bh[p], bd);
                }
            }
            #pragma unroll
            for (int mt = 0; mt < 2; mt++)
                #pragma unroll
                for (int p = 0; p < 4; p++)
                    #pragma unroll
                    for (int hlf = 0; hlf < 2; hlf++) {
                        const int nt = p * 2 + hlf;
                        mma16816(acc[mt][nt], ah[mt], bh[p][hlf*2], bh[p][hlf*2+1]);
                        mma16816(acc[mt][nt], al[mt], bh[p][hlf*2], bh[p][hlf*2+1]);
                    }
        }
        __syncthreads();
    }

    const int row0 = m0 + warp_m * 32 + (lane >> 2);
    const int col0 = n0 + warp_n * 64 + (lane & 3) * 2;
    #pragma unroll
    for (int mt = 0; mt < 2; mt++)
        #pragma unroll
        for (int nt = 0; nt < 8; nt++) {
            const int c = col0 + nt * 8;
            const float b0 = bias[c], b1 = bias[c + 1];
            const int r0 = row0 + mt * 16;
            float2 v0{acc[mt][nt][0] + b0, acc[mt][nt][1] + b1};
            float2 v1{acc[mt][nt][2] + b0, acc[mt][nt][3] + b1};
            *reinterpret_cast<float2*>(C + (size_t)r0 * N + c)       = v0;
            *reinterpret_cast<float2*>(C + (size_t)(r0 + 8) * N + c) = v1;
        }
}

// ---------------- fused window attention v2 (register-blocked) -------------
#define QS_STRIDE 33
#define KT_STRIDE 64
#define VS_STRIDE 36
#define SS_STRIDE 51

__global__ void __launch_bounds__(128) attn_kernel(
    const float* __restrict__ qkv, const float* __restrict__ mask,
    const float* __restrict__ bias_table, const int* __restrict__ rel_idx,
    __half* __restrict__ out_hi, __half* __restrict__ out_lo)
{
    const int b = blockIdx.x;
    const int h = blockIdx.y;
    const int tid  = threadIdx.x;
    const int lane = tid & 31;
    const int wid  = tid >> 5;

    __shared__ __align__(16) float qs[NTOK * QS_STRIDE];
    __shared__ __align__(16) float kt[HDIM * KT_STRIDE];
    __shared__ __align__(16) float vs[NTOK * VS_STRIDE];
    __shared__ __align__(16) float ss[NTOK * SS_STRIDE];
    __shared__ __align__(16) float sinv[NTOK];

    const float scale = 0.17677669529663687f;

    for (int idx = tid; idx < NTOK * 8; idx += 128) {
        int n  = idx >> 3;
        int c4 = (idx & 7) << 2;
        size_t base = ((size_t)(b * NTOK + n)) * QKV_N + h * HDIM + c4;
        float4 qv = *reinterpret_cast<const float4*>(qkv + base);
        float4 kv = *reinterpret_cast<const float4*>(qkv + base + DIMC);
        float4 vv = *reinterpret_cast<const float4*>(qkv + base + 2 * DIMC);
        qs[n * QS_STRIDE + c4 + 0] = qv.x * scale;
        qs[n * QS_STRIDE + c4 + 1] = qv.y * scale;
        qs[n * QS_STRIDE + c4 + 2] = qv.z * scale;
        qs[n * QS_STRIDE + c4 + 3] = qv.w * scale;
        kt[(c4 + 0) * KT_STRIDE + n] = kv.x;
        kt[(c4 + 1) * KT_STRIDE + n] = kv.y;
        kt[(c4 + 2) * KT_STRIDE + n] = kv.z;
        kt[(c4 + 3) * KT_STRIDE + n] = kv.w;
        *reinterpret_cast<float4*>(&vs[n * VS_STRIDE + c4]) = vv;
    }
    __syncthreads();

    // ---- S = q @ kT : warp wid covers m in [16*wid, 16*wid+16) ----
    {
        const int mbase = 16 * wid;
        const int r0 = lane;
        const int r1 = lane + 32;
        const bool has2 = (r1 < NTOK);
        float acc0[16], acc1[16];
        #pragma unroll
        for (int j = 0; j < 16; j++) { acc0[j] = 0.f; acc1[j] = 0.f; }
        #pragma unroll
        for (int d = 0; d < HDIM; d++) {
            float q0 = qs[r0 * QS_STRIDE + d];
            float q1 = has2 ? qs[r1 * QS_STRIDE + d] : 0.f;
            const float* kr = &kt[d * KT_STRIDE + mbase];
            float4 k0 = *reinterpret_cast<const float4*>(kr + 0);
            float4 k1 = *reinterpret_cast<const float4*>(kr + 4);
            float4 k2 = *reinterpret_cast<const float4*>(kr + 8);
            float4 k3 = *reinterpret_cast<const float4*>(kr + 12);
            float kk[16] = {k0.x,k0.y,k0.z,k0.w, k1.x,k1.y,k1.z,k1.w,
                            k2.x,k2.y,k2.z,k2.w, k3.x,k3.y,k3.z,k3.w};
            #pragma unroll
            for (int j = 0; j < 16; j++) {
                acc0[j] += q0 * kk[j];
                acc1[j] += q1 * kk[j];
            }
        }
        #pragma unroll
        for (int j = 0; j < 16; j++) {
            if (mbase + j < NTOK) {
                ss[r0 * SS_STRIDE + mbase + j] = acc0[j];
                if (has2) ss[r1 * SS_STRIDE + mbase + j] = acc1[j];
            }
        }
    }
    __syncthreads();

    // ---- softmax rows ----
    if (tid < NTOK) {
        const int r = tid;
        const float* mrow = mask + (size_t)(b & (NWIN - 1)) * NTOK * NTOK + r * NTOK;
        const int*   rrow = rel_idx + r * NTOK;
        float mx = -1e30f;
        float v[NTOK];
        #pragma unroll 7
        for (int m = 0; m < NTOK; m++) {
            float t = ss[r * SS_STRIDE + m]
                    + bias_table[rrow[m] * NHEAD + h] + mrow[m];
            v[m] = t;
            mx = fmaxf(mx, t);
        }
        float sum = 0.f;
        #pragma unroll 7
        for (int m = 0; m < NTOK; m++) {
            float e = __expf(v[m] - mx);
            ss[r * SS_STRIDE + m] = e;
            sum += e;
        }
        sinv[r] = 1.f / sum;
    }
    __syncthreads();

    // ---- O = P @ v : warp wid covers d in [8*wid, 8*wid+8) ----
    {
        const int dbase = 8 * wid;
        const int r0 = lane;
        const int r1 = lane + 32;
        const bool has2 = (r1 < NTOK);
        float acc0[8], acc1[8];
        #pragma unroll
        for (int j = 0; j < 8; j++) { acc0[j] = 0.f; acc1[j] = 0.f; }
        for (int m = 0; m < NTOK; m++) {
            float4 v0 = *reinterpret_cast<const float4*>(&vs[m * VS_STRIDE + dbase]);
            float4 v1 = *reinterpret_cast<const float4*>(&vs[m * VS_STRIDE + dbase + 4]);
            float p0 = ss[r0 * SS_STRIDE + m];
            float p1 = has2 ? ss[r1 * SS_STRIDE + m] : 0.f;
            float vv[8] = {v0.x,v0.y,v0.z,v0.w, v1.x,v1.y,v1.z,v1.w};
            #pragma unroll
            for (int j = 0; j < 8; j++) {
                acc0[j] += p0 * vv[j];
                acc1[j] += p1 * vv[j];
            }
        }
        float i0 = sinv[r0];
        float i1 = has2 ? sinv[r1] : 0.f;
        {
            __half hb[8], lb[8];
            #pragma unroll
            for (int j = 0; j < 8; j++) split2h(acc0[j] * i0, hb[j], lb[j]);
            size_t base = ((size_t)(b * NTOK + r0)) * DIMC + h * HDIM + dbase;
            *reinterpret_cast<uint4*>(&out_hi[base]) = *reinterpret_cast<uint4*>(hb);
            *reinterpret_cast<uint4*>(&out_lo[base]) = *reinterpret_cast<uint4*>(lb);
        }
        if (has2) {
            __half hb[8], lb[8];
            #pragma unroll
            for (int j = 0; j < 8; j++) split2h(acc1[j] * i1, hb[j], lb[j]);
            size_t base = ((size_t)(b * NTOK + r1)) * DIMC + h * HDIM + dbase;
            *reinterpret_cast<uint4*>(&out_hi[base]) = *reinterpret_cast<uint4*>(hb);
            *reinterpret_cast<uint4*>(&out_lo[base]) = *reinterpret_cast<uint4*>(lb);
        }
    }
}

// ---------------- launcher ----------------
extern "C" void kernel_launch(void* const* d_in, const int* in_sizes, int n_in,
                              void* d_out, int out_size)
{
    const float* x          = (const float*)d_in[0];
    const float* mask       = (const float*)d_in[1];
    const float* qkv_w      = (const float*)d_in[2];
    const float* qkv_b      = (const float*)d_in[3];
    const float* proj_w     = (const float*)d_in[4];
    const float* proj_b     = (const float*)d_in[5];
    const float* bias_table = (const float*)d_in[6];
    const int*   rel_idx    = (const int*)d_in[7];
    float* out = (float*)d_out;

    float *qkv;
    __half *xhi, *xlo, *ahi, *alo, *wqh, *wph;
    cudaGetSymbolAddress((void**)&qkv, g_qkv);
    cudaGetSymbolAddress((void**)&xhi, g_xhi);
    cudaGetSymbolAddress((void**)&xlo, g_xlo);
    cudaGetSymbolAddress((void**)&ahi, g_ahi);
    cudaGetSymbolAddress((void**)&alo, g_alo);
    cudaGetSymbolAddress((void**)&wqh, g_wq_h);
    cudaGetSymbolAddress((void**)&wph, g_wp_h);

    cudaFuncSetAttribute(gemm2_kernel, cudaFuncAttributeMaxDynamicSharedMemorySize, GEMM_SMEM);

    size_t n4 = (size_t)M_TOTAL * DIMC / 4;
    convert_split_kernel<<<(unsigned)((n4 + 255) / 256), 256>>>(x, xhi, xlo, n4);
    wh_t_kernel<<<(QKV_N * DIMC + 255) / 256, 256>>>(qkv_w, wqh, DIMC, QKV_N);
    wh_t_kernel<<<(DIMC * DIMC + 255) / 256, 256>>>(proj_w, wph, DIMC, DIMC);

    dim3 g1(QKV_N / 128, M_TOTAL / 128);
    gemm2_kernel<<<g1, 256, GEMM_SMEM>>>(xhi, xlo, wqh, qkv_b, qkv,
                                         M_TOTAL, QKV_N, DIMC);

    dim3 g2(NB, NHEAD);
    attn_kernel<<<g2, 128>>>(qkv, mask, bias_table, rel_idx, ahi, alo);

    dim3 g3(DIMC / 128, M_TOTAL / 128);
    gemm2_kernel<<<g3, 256, GEMM_SMEM>>>(ahi, alo, wph, proj_b, out,
                                         M_TOTAL, DIMC, DIMC);
}

// round 11
// speedup vs baseline: 1.5341x; 1.2474x over previous
#include <cuda_runtime.h>
#include <cuda_fp16.h>
#include <cstdint>

// ---------------- problem constants ----------------
#define NB      2048
#define NTOK    49
#define DIMC    512
#define QKV_N   1536
#define NHEAD   16
#define HDIM    32
#define NWIN    64
#define M_TOTAL (NB * NTOK)   // 100352

// ---------------- scratch (no allocs allowed) ----------------
__device__ __half g_qvh[(size_t)M_TOTAL * QKV_N];   // qkv hi fp16
__device__ __half g_qvl[(size_t)M_TOTAL * QKV_N];   // qkv lo fp16
__device__ __half g_xhi[(size_t)M_TOTAL * DIMC];
__device__ __half g_xlo[(size_t)M_TOTAL * DIMC];
__device__ __half g_ahi[(size_t)M_TOTAL * DIMC];
__device__ __half g_alo[(size_t)M_TOTAL * DIMC];
__device__ __half g_wq_h[(size_t)QKV_N * DIMC];
__device__ __half g_wp_h[(size_t)DIMC * DIMC];
__device__ float  g_comb[(size_t)NWIN * NHEAD * 64 * 64];  // bias+mask, padded -1e30

// ---------------- helpers ----------------
__device__ __forceinline__ uint32_t smem_to_u32(const void* p) {
    uint32_t a;
    asm("{ .reg .u64 t; cvta.to.shared.u64 t, %1; cvt.u32.u64 %0, t; }" : "=r"(a) : "l"(p));
    return a;
}
__device__ __forceinline__ void cp_async16(uint32_t saddr, const void* gaddr) {
    asm volatile("cp.async.cg.shared.global [%0], [%1], 16;" :: "r"(saddr), "l"(gaddr));
}
#define CP_COMMIT() asm volatile("cp.async.commit_group;")
#define CP_WAIT0()  asm volatile("cp.async.wait_group 0;")

__device__ __forceinline__ void ldsm4(uint32_t* r, uint32_t addr) {
    asm volatile("ldmatrix.sync.aligned.m8n8.x4.shared.b16 {%0,%1,%2,%3}, [%4];"
                 : "=r"(r[0]), "=r"(r[1]), "=r"(r[2]), "=r"(r[3]) : "r"(addr));
}
__device__ __forceinline__ void mma16816(float* d, const uint32_t* a,
                                         uint32_t b0, uint32_t b1) {
    asm volatile(
        "mma.sync.aligned.m16n8k16.row.col.f32.f16.f16.f32 "
        "{%0,%1,%2,%3}, {%4,%5,%6,%7}, {%8,%9}, {%0,%1,%2,%3};"
        : "+f"(d[0]), "+f"(d[1]), "+f"(d[2]), "+f"(d[3])
        : "r"(a[0]), "r"(a[1]), "r"(a[2]), "r"(a[3]), "r"(b0), "r"(b1));
}
__device__ __forceinline__ void split2h(float v, __half& h, __half& l) {
    h = __float2half_rn(v);
    l = __float2half_rn(v - __half2float(h));
}
__device__ __forceinline__ uint32_t pack2(__half a, __half b) {
    __half2 t = __halves2half2(a, b);
    return *reinterpret_cast<uint32_t*>(&t);
}

// ---------------- conversion kernels ----------------
__global__ void __launch_bounds__(256) convert_split_kernel(
    const float* __restrict__ src, __half* __restrict__ hi,
    __half* __restrict__ lo, size_t n4)
{
    size_t i = (size_t)blockIdx.x * 256 + threadIdx.x;
    if (i >= n4) return;
    float4 v = reinterpret_cast<const float4*>(src)[i];
    __half h0, h1, h2, h3, l0, l1, l2, l3;
    split2h(v.x, h0, l0); split2h(v.y, h1, l1);
    split2h(v.z, h2, l2); split2h(v.w, h3, l3);
    uint2 uh{pack2(h0, h1), pack2(h2, h3)};
    uint2 ul{pack2(l0, l1), pack2(l2, l3)};
    reinterpret_cast<uint2*>(hi)[i] = uh;
    reinterpret_cast<uint2*>(lo)[i] = ul;
}

__global__ void __launch_bounds__(256) wh_t_kernel(
    const float* __restrict__ w, __half* __restrict__ hi, int K, int N)
{
    int idx = blockIdx.x * 256 + threadIdx.x;
    if (idx >= N * K) return;
    int n = idx / K, k = idx - n * K;
    hi[idx] = __float2half_rn(w[(size_t)k * N + n]);
}

// combined[w][h][64][64] = bias + mask (padded with -1e30)
__global__ void __launch_bounds__(256) combined_kernel(
    const float* __restrict__ bias_table, const int* __restrict__ rel_idx,
    const float* __restrict__ mask, float* __restrict__ comb)
{
    const int w = blockIdx.x, h = blockIdx.y;
    float* dst = comb + ((size_t)(w * NHEAD + h)) * 4096;
    for (int i = threadIdx.x; i < 4096; i += 256) {
        int n = i >> 6, m = i & 63;
        float v = -1e30f;
        if (n < NTOK && m < NTOK)
            v = bias_table[rel_idx[n * NTOK + m] * NHEAD + h]
              + mask[((size_t)w * NTOK + n) * NTOK + m];
        dst[i] = v;
    }
}

// ---------------- mma.sync 2-term fp16 GEMM ------------------
#define STAGE_BYTES 49152
#define GEMM_SMEM   (2 * STAGE_BYTES)

__device__ __forceinline__ uint32_t sw_addr(uint32_t base, int row, int chunk) {
    return base + row * 128 + ((chunk ^ (row & 7)) << 4);
}

template<bool HOUT>
__global__ void __launch_bounds__(256, 1) gemm2_kernel(
    const __half* __restrict__ Ah, const __half* __restrict__ Al,
    const __half* __restrict__ Bh,
    const float* __restrict__ bias, float* __restrict__ C,
    __half* __restrict__ Chi, __half* __restrict__ Clo,
    int M, int N, int K)
{
    extern __shared__ char smem[];
    const uint32_t sbase = smem_to_u32(smem);
    const int tid  = threadIdx.x;
    const int lane = tid & 31;
    const int wid  = tid >> 5;
    const int warp_m = wid & 3;
    const int warp_n = wid >> 2;
    const int m0 = blockIdx.y * 128;
    const int n0 = blockIdx.x * 128;
    const int NKT = K >> 6;

    float acc[2][8][4];
    #pragma unroll
    for (int i = 0; i < 2; i++)
        #pragma unroll
        for (int j = 0; j < 8; j++)
            #pragma unroll
            for (int t = 0; t < 4; t++) acc[i][j][t] = 0.f;

    auto load_stage = [&](int kt, int s) {
        const uint32_t sb = sbase + s * STAGE_BYTES;
        const int kofs = kt * 64;
        #pragma unroll
        for (int i = 0; i < 4; i++) {
            int f   = tid + i * 256;
            int row = f >> 3;
            int c   = f & 7;
            uint32_t sw = sw_addr(0, row, c);
            size_t ga = (size_t)(m0 + row) * K + kofs + c * 8;
            size_t gb = (size_t)(n0 + row) * K + kofs + c * 8;
            cp_async16(sb + sw,         Ah + ga);
            cp_async16(sb + 16384 + sw, Al + ga);
            cp_async16(sb + 32768 + sw, Bh + gb);
        }
        CP_COMMIT();
    };

    load_stage(0, 0);

    for (int kt = 0; kt < NKT; kt++) {
        const int s = kt & 1;
        CP_WAIT0();
        __syncthreads();
        if (kt + 1 < NKT) load_stage(kt + 1, s ^ 1);

        const uint32_t sA = sbase + s * STAGE_BYTES;
        const uint32_t sB = sA + 32768;

        #pragma unroll
        for (int ks = 0; ks < 4; ks++) {
            uint32_t ah[2][4], al[2][4];
            {
                const int arow = warp_m * 32 + (lane & 15);
                const int achk = 2 * ks + (lane >> 4);
                #pragma unroll
                for (int mt = 0; mt < 2; mt++) {
                    uint32_t ad = sw_addr(sA, arow + mt * 16, achk);
                    ldsm4(ah[mt], ad);
                    ldsm4(al[mt], ad + 16384);
                }
            }
            uint32_t bh[4][4];
            {
                const int brow_base = warp_n * 64 + ((lane & 16) ? 8 : 0) + (lane & 7);
                const int bchk = 2 * ks + ((lane >> 3) & 1);
                #pragma unroll
                for (int p = 0; p < 4; p++) {
                    uint32_t bd = sw_addr(sB, brow_base + p * 16, bchk);
                    ldsm4(bh[p], bd);
                }
            }
            #pragma unroll
            for (int mt = 0; mt < 2; mt++)
                #pragma unroll
                for (int p = 0; p < 4; p++)
                    #pragma unroll
                    for (int hlf = 0; hlf < 2; hlf++) {
                        const int nt = p * 2 + hlf;
                        mma16816(acc[mt][nt], ah[mt], bh[p][hlf*2], bh[p][hlf*2+1]);
                        mma16816(acc[mt][nt], al[mt], bh[p][hlf*2], bh[p][hlf*2+1]);
                    }
        }
        __syncthreads();
    }

    const int row0 = m0 + warp_m * 32 + (lane >> 2);
    const int col0 = n0 + warp_n * 64 + (lane & 3) * 2;
    #pragma unroll
    for (int mt = 0; mt < 2; mt++)
        #pragma unroll
        for (int nt = 0; nt < 8; nt++) {
            const int c = col0 + nt * 8;
            const float b0 = bias[c], b1 = bias[c + 1];
            const int r0 = row0 + mt * 16;
            float v00 = acc[mt][nt][0] + b0, v01 = acc[mt][nt][1] + b1;
            float v10 = acc[mt][nt][2] + b0, v11 = acc[mt][nt][3] + b1;
            if (HOUT) {
                __half h0, l0, h1, l1;
                split2h(v00, h0, l0); split2h(v01, h1, l1);
                *reinterpret_cast<uint32_t*>(Chi + (size_t)r0 * N + c) = pack2(h0, h1);
                *reinterpret_cast<uint32_t*>(Clo + (size_t)r0 * N + c) = pack2(l0, l1);
                split2h(v10, h0, l0); split2h(v11, h1, l1);
                *reinterpret_cast<uint32_t*>(Chi + (size_t)(r0 + 8) * N + c) = pack2(h0, h1);
                *reinterpret_cast<uint32_t*>(Clo + (size_t)(r0 + 8) * N + c) = pack2(l0, l1);
            } else {
                *reinterpret_cast<float2*>(C + (size_t)r0 * N + c)       = float2{v00, v01};
                *reinterpret_cast<float2*>(C + (size_t)(r0 + 8) * N + c) = float2{v10, v11};
            }
        }
}

// ---------------- tensor-core window attention --------------------
// Block = (window, head), 4 warps; warp w = m-tile rows [16w,16w+16).
// S (64x64 padded) in fragments; softmax in-register; P reinterpreted as
// A-operand for PV. Q/K/V all fp16 hi/lo (3-term mma).
#define QK_STRIDE 40     // halves per row (80B), bank-conflict-free ldmatrix
#define VT_STRIDE 72     // halves per row (144B)
#define OFF_QH 0
#define OFF_QL 2560
#define OFF_KH 5120
#define OFF_KL 7680
#define OFF_VH 10240
#define OFF_VL 12544
#define SM_HALVES 14848

__global__ void __launch_bounds__(128) attn_mma_kernel(
    const __half* __restrict__ qvh, const __half* __restrict__ qvl,
    const float* __restrict__ comb,
    __half* __restrict__ out_hi, __half* __restrict__ out_lo)
{
    const int b = blockIdx.x;
    const int h = blockIdx.y;
    const int tid  = threadIdx.x;
    const int lane = tid & 31;
    const int wid  = tid >> 5;

    __shared__ __align__(16) __half sm[SM_HALVES];

    // zero-init (padding must be 0, not garbage/NaN)
    for (int i = tid; i < SM_HALVES / 8; i += 128)
        reinterpret_cast<uint4*>(sm)[i] = uint4{0, 0, 0, 0};
    __syncthreads();

    // load Q/K (row-major, stride 40) and V transposed (Vt[d][m], stride 72)
    for (int i = tid; i < NTOK * 4; i += 128) {
        int n  = i >> 2;
        int c8 = (i & 3) << 3;
        size_t base = (size_t)(b * NTOK + n) * QKV_N + h * HDIM + c8;
        uint4 qh8 = *reinterpret_cast<const uint4*>(qvh + base);
        uint4 ql8 = *reinterpret_cast<const uint4*>(qvl + base);
        uint4 kh8 = *reinterpret_cast<const uint4*>(qvh + base + DIMC);
        uint4 kl8 = *reinterpret_cast<const uint4*>(qvl + base + DIMC);
        uint4 vh8 = *reinterpret_cast<const uint4*>(qvh + base + 2 * DIMC);
        uint4 vl8 = *reinterpret_cast<const uint4*>(qvl + base + 2 * DIMC);
        *reinterpret_cast<uint4*>(sm + OFF_QH + n * QK_STRIDE + c8) = qh8;
        *reinterpret_cast<uint4*>(sm + OFF_QL + n * QK_STRIDE + c8) = ql8;
        *reinterpret_cast<uint4*>(sm + OFF_KH + n * QK_STRIDE + c8) = kh8;
        *reinterpret_cast<uint4*>(sm + OFF_KL + n * QK_STRIDE + c8) = kl8;
        const __half* vh = reinterpret_cast<const __half*>(&vh8);
        const __half* vl = reinterpret_cast<const __half*>(&vl8);
        #pragma unroll
        for (int j = 0; j < 8; j++) {
            sm[OFF_VH + (c8 + j) * VT_STRIDE + n] = vh[j];
            sm[OFF_VL + (c8 + j) * VT_STRIDE + n] = vl[j];
        }
    }
    __syncthreads();

    const uint32_t uQH = smem_to_u32(sm + OFF_QH);
    const uint32_t uQL = smem_to_u32(sm + OFF_QL);
    const uint32_t uKH = smem_to_u32(sm + OFF_KH);
    const uint32_t uKL = smem_to_u32(sm + OFF_KL);
    const uint32_t uVH = smem_to_u32(sm + OFF_VH);
    const uint32_t uVL = smem_to_u32(sm + OFF_VL);

    // ---- S = Q @ K^T (3-term) ----
    float acc[8][4];
    #pragma unroll
    for (int nt = 0; nt < 8; nt++)
        #pragma unroll
        for (int t = 0; t < 4; t++) acc[nt][t] = 0.f;

    #pragma unroll
    for (int ks = 0; ks < 2; ks++) {
        uint32_t aqh[4], aql[4];
        const int arow = wid * 16 + (lane & 15);
        const int achk = 2 * ks + (lane >> 4);
        ldsm4(aqh, uQH + arow * (QK_STRIDE * 2) + achk * 16);
        ldsm4(aql, uQL + arow * (QK_STRIDE * 2) + achk * 16);
        #pragma unroll
        for (int p = 0; p < 4; p++) {
            uint32_t bkh[4], bkl[4];
            const int brow = p * 16 + ((lane & 16) ? 8 : 0) + (lane & 7);
            const int bchk = 2 * ks + ((lane >> 3) & 1);
            ldsm4(bkh, uKH + brow * (QK_STRIDE * 2) + bchk * 16);
            ldsm4(bkl, uKL + brow * (QK_STRIDE * 2) + bchk * 16);
            #pragma unroll
            for (int hlf = 0; hlf < 2; hlf++) {
                const int nt = p * 2 + hlf;
                mma16816(acc[nt], aqh, bkh[hlf*2], bkh[hlf*2+1]);
                mma16816(acc[nt], aql, bkh[hlf*2], bkh[hlf*2+1]);
                mma16816(acc[nt], aqh, bkl[hlf*2], bkl[hlf*2+1]);
            }
        }
    }

    // ---- scale + combined(bias+mask), softmax in fragments ----
    const float scale = 0.17677669529663687f;
    const float* cb = comb + ((size_t)((b & (NWIN - 1)) * NHEAD + h)) * 4096;
    const int r0 = wid * 16 + (lane >> 2);
    const int r1 = r0 + 8;
    const int cbase = 2 * (lane & 3);
    #pragma unroll
    for (int nt = 0; nt < 8; nt++) {
        float2 c0 = *reinterpret_cast<const float2*>(cb + r0 * 64 + nt * 8 + cbase);
        float2 c1 = *reinterpret_cast<const float2*>(cb + r1 * 64 + nt * 8 + cbase);
        acc[nt][0] = acc[nt][0] * scale + c0.x;
        acc[nt][1] = acc[nt][1] * scale + c0.y;
        acc[nt][2] = acc[nt][2] * scale + c1.x;
        acc[nt][3] = acc[nt][3] * scale + c1.y;
    }
    float mx0 = -1e30f, mx1 = -1e30f;
    #pragma unroll
    for (int nt = 0; nt < 8; nt++) {
        mx0 = fmaxf(mx0, fmaxf(acc[nt][0], acc[nt][1]));
        mx1 = fmaxf(mx1, fmaxf(acc[nt][2], acc[nt][3]));
    }
    mx0 = fmaxf(mx0, __shfl_xor_sync(0xffffffff, mx0, 1));
    mx0 = fmaxf(mx0, __shfl_xor_sync(0xffffffff, mx0, 2));
    mx1 = fmaxf(mx1, __shfl_xor_sync(0xffffffff, mx1, 1));
    mx1 = fmaxf(mx1, __shfl_xor_sync(0xffffffff, mx1, 2));
    float sum0 = 0.f, sum1 = 0.f;
    #pragma unroll
    for (int nt = 0; nt < 8; nt++) {
        acc[nt][0] = __expf(acc[nt][0] - mx0);
        acc[nt][1] = __expf(acc[nt][1] - mx0);
        acc[nt][2] = __expf(acc[nt][2] - mx1);
        acc[nt][3] = __expf(acc[nt][3] - mx1);
        sum0 += acc[nt][0] + acc[nt][1];
        sum1 += acc[nt][2] + acc[nt][3];
    }
    sum0 += __shfl_xor_sync(0xffffffff, sum0, 1);
    sum0 += __shfl_xor_sync(0xffffffff, sum0, 2);
    sum1 += __shfl_xor_sync(0xffffffff, sum1, 1);
    sum1 += __shfl_xor_sync(0xffffffff, sum1, 2);
    const float sinv0 = 1.f / sum0;
    const float sinv1 = 1.f / sum1;

    // ---- P fragments (hi/lo) from S accumulators ----
    uint32_t aph[4][4], apl[4][4];
    #pragma unroll
    for (int kk = 0; kk < 4; kk++) {
        const int n0t = 2 * kk, n1t = 2 * kk + 1;
        __half h0, l0, h1, l1;
        split2h(acc[n0t][0], h0, l0); split2h(acc[n0t][1], h1, l1);
        aph[kk][0] = pack2(h0, h1); apl[kk][0] = pack2(l0, l1);
        split2h(acc[n0t][2], h0, l0); split2h(acc[n0t][3], h1, l1);
        aph[kk][1] = pack2(h0, h1); apl[kk][1] = pack2(l0, l1);
        split2h(acc[n1t][0], h0, l0); split2h(acc[n1t][1], h1, l1);
        aph[kk][2] = pack2(h0, h1); apl[kk][2] = pack2(l0, l1);
        split2h(acc[n1t][2], h0, l0); split2h(acc[n1t][3], h1, l1);
        aph[kk][3] = pack2(h0, h1); apl[kk][3] = pack2(l0, l1);
    }

    // ---- O = P @ V (3-term) ----
    float oacc[4][4];
    #pragma unroll
    for (int nt = 0; nt < 4; nt++)
        #pragma unroll
        for (int t = 0; t < 4; t++) oacc[nt][t] = 0.f;

    #pragma unroll
    for (int ks = 0; ks < 4; ks++) {
        #pragma unroll
        for (int p = 0; p < 2; p++) {
            uint32_t bvh[4], bvl[4];
            const int brow = p * 16 + ((lane & 16) ? 8 : 0) + (lane & 7);
            const int bchk = 2 * ks + ((lane >> 3) & 1);
            ldsm4(bvh, uVH + brow * (VT_STRIDE * 2) + bchk * 16);
            ldsm4(bvl, uVL + brow * (VT_STRIDE * 2) + bchk * 16);
            #pragma unroll
            for (int hlf = 0; hlf < 2; hlf++) {
                const int nt = p * 2 + hlf;
                mma16816(oacc[nt], aph[ks], bvh[hlf*2], bvh[hlf*2+1]);
                mma16816(oacc[nt], apl[ks], bvh[hlf*2], bvh[hlf*2+1]);
                mma16816(oacc[nt], aph[ks], bvl[hlf*2], bvl[hlf*2+1]);
            }
        }
    }

    // ---- normalize + store (rows < 49 only) ----
    #pragma unroll
    for (int nt = 0; nt < 4; nt++) {
        const int d = nt * 8 + cbase;
        if (r0 < NTOK) {
            __half h0, l0, h1, l1;
            split2h(oacc[nt][0] * sinv0, h0, l0);
            split2h(oacc[nt][1] * sinv0, h1, l1);
            size_t base = (size_t)(b * NTOK + r0) * DIMC + h * HDIM + d;
            *reinterpret_cast<uint32_t*>(out_hi + base) = pack2(h0, h1);
            *reinterpret_cast<uint32_t*>(out_lo + base) = pack2(l0, l1);
        }
        if (r1 < NTOK) {
            __half h0, l0, h1, l1;
            split2h(oacc[nt][2] * sinv1, h0, l0);
            split2h(oacc[nt][3] * sinv1, h1, l1);
            size_t base = (size_t)(b * NTOK + r1) * DIMC + h * HDIM + d;
            *reinterpret_cast<uint32_t*>(out_hi + base) = pack2(h0, h1);
            *reinterpret_cast<uint32_t*>(out_lo + base) = pack2(l0, l1);
        }
    }
}

// ---------------- launcher ----------------
extern "C" void kernel_launch(void* const* d_in, const int* in_sizes, int n_in,
                              void* d_out, int out_size)
{
    const float* x          = (const float*)d_in[0];
    const float* mask       = (const float*)d_in[1];
    const float* qkv_w      = (const float*)d_in[2];
    const float* qkv_b      = (const float*)d_in[3];
    const float* proj_w     = (const float*)d_in[4];
    const float* proj_b     = (const float*)d_in[5];
    const float* bias_table = (const float*)d_in[6];
    const int*   rel_idx    = (const int*)d_in[7];
    float* out = (float*)d_out;

    __half *qvh, *qvl, *xhi, *xlo, *ahi, *alo, *wqh, *wph;
    float* comb;
    cudaGetSymbolAddress((void**)&qvh, g_qvh);
    cudaGetSymbolAddress((void**)&qvl, g_qvl);
    cudaGetSymbolAddress((void**)&xhi, g_xhi);
    cudaGetSymbolAddress((void**)&xlo, g_xlo);
    cudaGetSymbolAddress((void**)&ahi, g_ahi);
    cudaGetSymbolAddress((void**)&alo, g_alo);
    cudaGetSymbolAddress((void**)&wqh, g_wq_h);
    cudaGetSymbolAddress((void**)&wph, g_wp_h);
    cudaGetSymbolAddress((void**)&comb, g_comb);

    cudaFuncSetAttribute(gemm2_kernel<true>,  cudaFuncAttributeMaxDynamicSharedMemorySize, GEMM_SMEM);
    cudaFuncSetAttribute(gemm2_kernel<false>, cudaFuncAttributeMaxDynamicSharedMemorySize, GEMM_SMEM);

    size_t n4 = (size_t)M_TOTAL * DIMC / 4;
    convert_split_kernel<<<(unsigned)((n4 + 255) / 256), 256>>>(x, xhi, xlo, n4);
    wh_t_kernel<<<(QKV_N * DIMC + 255) / 256, 256>>>(qkv_w, wqh, DIMC, QKV_N);
    wh_t_kernel<<<(DIMC * DIMC + 255) / 256, 256>>>(proj_w, wph, DIMC, DIMC);
    combined_kernel<<<dim3(NWIN, NHEAD), 256>>>(bias_table, rel_idx, mask, comb);

    // 1) QKV projection -> fp16 hi/lo
    dim3 g1(QKV_N / 128, M_TOTAL / 128);
    gemm2_kernel<true><<<g1, 256, GEMM_SMEM>>>(xhi, xlo, wqh, qkv_b,
                                               nullptr, qvh, qvl,
                                               M_TOTAL, QKV_N, DIMC);

    // 2) tensor-core window attention -> fp16 hi/lo
    dim3 g2(NB, NHEAD);
    attn_mma_kernel<<<g2, 128>>>(qvh, qvl, comb, ahi, alo);

    // 3) output projection -> fp32
    dim3 g3(DIMC / 128, M_TOTAL / 128);
    gemm2_kernel<false><<<g3, 256, GEMM_SMEM>>>(ahi, alo, wph, proj_b,
                                                out, nullptr, nullptr,
                                                M_TOTAL, DIMC, DIMC);
}

// round 12
// speedup vs baseline: 2.2557x; 1.4704x over previous
#include <cuda_runtime.h>
#include <cuda_fp16.h>
#include <cstdint>

// ---------------- problem constants ----------------
#define NB      2048
#define NTOK    49
#define DIMC    512
#define QKV_N   1536
#define NHEAD   16
#define HDIM    32
#define NWIN    64
#define M_TOTAL (NB * NTOK)   // 100352

// ---------------- scratch (no allocs allowed) ----------------
__device__ __half g_qvh[(size_t)M_TOTAL * QKV_N];   // qkv hi fp16
__device__ __half g_qvl[(size_t)M_TOTAL * QKV_N];   // qkv lo fp16
__device__ __half g_xhi[(size_t)M_TOTAL * DIMC];
__device__ __half g_ahi[(size_t)M_TOTAL * DIMC];
__device__ __half g_alo[(size_t)M_TOTAL * DIMC];
__device__ __half g_wq_h[(size_t)QKV_N * DIMC];
__device__ __half g_wp_h[(size_t)DIMC * DIMC];
__device__ float  g_comb[(size_t)NWIN * NHEAD * 64 * 64];  // bias+mask, padded -1e30

// ---------------- helpers ----------------
__device__ __forceinline__ uint32_t smem_to_u32(const void* p) {
    uint32_t a;
    asm("{ .reg .u64 t; cvta.to.shared.u64 t, %1; cvt.u32.u64 %0, t; }" : "=r"(a) : "l"(p));
    return a;
}
__device__ __forceinline__ void cp_async16(uint32_t saddr, const void* gaddr) {
    asm volatile("cp.async.cg.shared.global [%0], [%1], 16;" :: "r"(saddr), "l"(gaddr));
}
#define CP_COMMIT() asm volatile("cp.async.commit_group;")
#define CP_WAIT0()  asm volatile("cp.async.wait_group 0;")

__device__ __forceinline__ void ldsm4(uint32_t* r, uint32_t addr) {
    asm volatile("ldmatrix.sync.aligned.m8n8.x4.shared.b16 {%0,%1,%2,%3}, [%4];"
                 : "=r"(r[0]), "=r"(r[1]), "=r"(r[2]), "=r"(r[3]) : "r"(addr));
}
__device__ __forceinline__ void mma16816(float* d, const uint32_t* a,
                                         uint32_t b0, uint32_t b1) {
    asm volatile(
        "mma.sync.aligned.m16n8k16.row.col.f32.f16.f16.f32 "
        "{%0,%1,%2,%3}, {%4,%5,%6,%7}, {%8,%9}, {%0,%1,%2,%3};"
        : "+f"(d[0]), "+f"(d[1]), "+f"(d[2]), "+f"(d[3])
        : "r"(a[0]), "r"(a[1]), "r"(a[2]), "r"(a[3]), "r"(b0), "r"(b1));
}
__device__ __forceinline__ void split2h(float v, __half& h, __half& l) {
    h = __float2half_rn(v);
    l = __float2half_rn(v - __half2float(h));
}
__device__ __forceinline__ uint32_t pack2(__half a, __half b) {
    __half2 t = __halves2half2(a, b);
    return *reinterpret_cast<uint32_t*>(&t);
}

// ---------------- conversion kernels ----------------
__global__ void __launch_bounds__(256) convert_h_kernel(
    const float* __restrict__ src, __half* __restrict__ hi, size_t n4)
{
    size_t i = (size_t)blockIdx.x * 256 + threadIdx.x;
    if (i >= n4) return;
    float4 v = reinterpret_cast<const float4*>(src)[i];
    uint2 uh{pack2(__float2half_rn(v.x), __float2half_rn(v.y)),
             pack2(__float2half_rn(v.z), __float2half_rn(v.w))};
    reinterpret_cast<uint2*>(hi)[i] = uh;
}

__global__ void __launch_bounds__(256) wh_t_kernel(
    const float* __restrict__ w, __half* __restrict__ hi, int K, int N)
{
    int idx = blockIdx.x * 256 + threadIdx.x;
    if (idx >= N * K) return;
    int n = idx / K, k = idx - n * K;
    hi[idx] = __float2half_rn(w[(size_t)k * N + n]);
}

// combined[w][h][64][64] = bias + mask (padded with -1e30)
__global__ void __launch_bounds__(256) combined_kernel(
    const float* __restrict__ bias_table, const int* __restrict__ rel_idx,
    const float* __restrict__ mask, float* __restrict__ comb)
{
    const int w = blockIdx.x, h = blockIdx.y;
    float* dst = comb + ((size_t)(w * NHEAD + h)) * 4096;
    for (int i = threadIdx.x; i < 4096; i += 256) {
        int n = i >> 6, m = i & 63;
        float v = -1e30f;
        if (n < NTOK && m < NTOK)
            v = bias_table[rel_idx[n * NTOK + m] * NHEAD + h]
              + mask[((size_t)w * NTOK + n) * NTOK + m];
        dst[i] = v;
    }
}

// ---------------- mma.sync plain fp16 GEMM: C = A @ B^T + bias -------------
// A: [M][K] fp16, B: [N][K] fp16; 128x128x64 tiles, 8 warps, 2-stage cp.async.
// Stage: A(16K) B(16K) = 32K; 2 CTAs/SM.
#define STAGE_BYTES 32768
#define GEMM_SMEM   (2 * STAGE_BYTES)

__device__ __forceinline__ uint32_t sw_addr(uint32_t base, int row, int chunk) {
    return base + row * 128 + ((chunk ^ (row & 7)) << 4);
}

template<bool HOUT>
__global__ void __launch_bounds__(256, 2) gemm1_kernel(
    const __half* __restrict__ Ah, const __half* __restrict__ Bh,
    const float* __restrict__ bias, float* __restrict__ C,
    __half* __restrict__ Chi, __half* __restrict__ Clo,
    int M, int N, int K)
{
    extern __shared__ char smem[];
    const uint32_t sbase = smem_to_u32(smem);
    const int tid  = threadIdx.x;
    const int lane = tid & 31;
    const int wid  = tid >> 5;
    const int warp_m = wid & 3;
    const int warp_n = wid >> 2;
    const int m0 = blockIdx.y * 128;
    const int n0 = blockIdx.x * 128;
    const int NKT = K >> 6;

    float acc[2][8][4];
    #pragma unroll
    for (int i = 0; i < 2; i++)
        #pragma unroll
        for (int j = 0; j < 8; j++)
            #pragma unroll
            for (int t = 0; t < 4; t++) acc[i][j][t] = 0.f;

    auto load_stage = [&](int kt, int s) {
        const uint32_t sb = sbase + s * STAGE_BYTES;
        const int kofs = kt * 64;
        #pragma unroll
        for (int i = 0; i < 4; i++) {
            int f   = tid + i * 256;
            int row = f >> 3;
            int c   = f & 7;
            uint32_t sw = sw_addr(0, row, c);
            size_t ga = (size_t)(m0 + row) * K + kofs + c * 8;
            size_t gb = (size_t)(n0 + row) * K + kofs + c * 8;
            cp_async16(sb + sw,         Ah + ga);
            cp_async16(sb + 16384 + sw, Bh + gb);
        }
        CP_COMMIT();
    };

    load_stage(0, 0);

    for (int kt = 0; kt < NKT; kt++) {
        const int s = kt & 1;
        CP_WAIT0();
        __syncthreads();
        if (kt + 1 < NKT) load_stage(kt + 1, s ^ 1);

        const uint32_t sA = sbase + s * STAGE_BYTES;
        const uint32_t sB = sA + 16384;

        #pragma unroll
        for (int ks = 0; ks < 4; ks++) {
            uint32_t ah[2][4];
            {
                const int arow = warp_m * 32 + (lane & 15);
                const int achk = 2 * ks + (lane >> 4);
                #pragma unroll
                for (int mt = 0; mt < 2; mt++)
                    ldsm4(ah[mt], sw_addr(sA, arow + mt * 16, achk));
            }
            uint32_t bh[4][4];
            {
                const int brow_base = warp_n * 64 + ((lane & 16) ? 8 : 0) + (lane & 7);
                const int bchk = 2 * ks + ((lane >> 3) & 1);
                #pragma unroll
                for (int p = 0; p < 4; p++)
                    ldsm4(bh[p], sw_addr(sB, brow_base + p * 16, bchk));
            }
            #pragma unroll
            for (int mt = 0; mt < 2; mt++)
                #pragma unroll
                for (int p = 0; p < 4; p++)
                    #pragma unroll
                    for (int hlf = 0; hlf < 2; hlf++)
                        mma16816(acc[mt][p * 2 + hlf], ah[mt],
                                 bh[p][hlf*2], bh[p][hlf*2+1]);
        }
        __syncthreads();
    }

    const int row0 = m0 + warp_m * 32 + (lane >> 2);
    const int col0 = n0 + warp_n * 64 + (lane & 3) * 2;
    #pragma unroll
    for (int mt = 0; mt < 2; mt++)
        #pragma unroll
        for (int nt = 0; nt < 8; nt++) {
            const int c = col0 + nt * 8;
            const float b0 = bias[c], b1 = bias[c + 1];
            const int r0 = row0 + mt * 16;
            float v00 = acc[mt][nt][0] + b0, v01 = acc[mt][nt][1] + b1;
            float v10 = acc[mt][nt][2] + b0, v11 = acc[mt][nt][3] + b1;
            if (HOUT) {
                __half h0, l0, h1, l1;
                split2h(v00, h0, l0); split2h(v01, h1, l1);
                *reinterpret_cast<uint32_t*>(Chi + (size_t)r0 * N + c) = pack2(h0, h1);
                *reinterpret_cast<uint32_t*>(Clo + (size_t)r0 * N + c) = pack2(l0, l1);
                split2h(v10, h0, l0); split2h(v11, h1, l1);
                *reinterpret_cast<uint32_t*>(Chi + (size_t)(r0 + 8) * N + c) = pack2(h0, h1);
                *reinterpret_cast<uint32_t*>(Clo + (size_t)(r0 + 8) * N + c) = pack2(l0, l1);
            } else {
                *reinterpret_cast<float2*>(C + (size_t)r0 * N + c)       = float2{v00, v01};
                *reinterpret_cast<float2*>(C + (size_t)(r0 + 8) * N + c) = float2{v10, v11};
            }
        }
}

// ---------------- tensor-core window attention (unchanged from R10) --------
#define QK_STRIDE 40
#define VT_STRIDE 72
#define OFF_QH 0
#define OFF_QL 2560
#define OFF_KH 5120
#define OFF_KL 7680
#define OFF_VH 10240
#define OFF_VL 12544
#define SM_HALVES 14848

__global__ void __launch_bounds__(128) attn_mma_kernel(
    const __half* __restrict__ qvh, const __half* __restrict__ qvl,
    const float* __restrict__ comb,
    __half* __restrict__ out_hi, __half* __restrict__ out_lo)
{
    const int b = blockIdx.x;
    const int h = blockIdx.y;
    const int tid  = threadIdx.x;
    const int lane = tid & 31;
    const int wid  = tid >> 5;

    __shared__ __align__(16) __half sm[SM_HALVES];

    for (int i = tid; i < SM_HALVES / 8; i += 128)
        reinterpret_cast<uint4*>(sm)[i] = uint4{0, 0, 0, 0};
    __syncthreads();

    for (int i = tid; i < NTOK * 4; i += 128) {
        int n  = i >> 2;
        int c8 = (i & 3) << 3;
        size_t base = (size_t)(b * NTOK + n) * QKV_N + h * HDIM + c8;
        uint4 qh8 = *reinterpret_cast<const uint4*>(qvh + base);
        uint4 ql8 = *reinterpret_cast<const uint4*>(qvl + base);
        uint4 kh8 = *reinterpret_cast<const uint4*>(qvh + base + DIMC);
        uint4 kl8 = *reinterpret_cast<const uint4*>(qvl + base + DIMC);
        uint4 vh8 = *reinterpret_cast<const uint4*>(qvh + base + 2 * DIMC);
        uint4 vl8 = *reinterpret_cast<const uint4*>(qvl + base + 2 * DIMC);
        *reinterpret_cast<uint4*>(sm + OFF_QH + n * QK_STRIDE + c8) = qh8;
        *reinterpret_cast<uint4*>(sm + OFF_QL + n * QK_STRIDE + c8) = ql8;
        *reinterpret_cast<uint4*>(sm + OFF_KH + n * QK_STRIDE + c8) = kh8;
        *reinterpret_cast<uint4*>(sm + OFF_KL + n * QK_STRIDE + c8) = kl8;
        const __half* vh = reinterpret_cast<const __half*>(&vh8);
        const __half* vl = reinterpret_cast<const __half*>(&vl8);
        #pragma unroll
        for (int j = 0; j < 8; j++) {
            sm[OFF_VH + (c8 + j) * VT_STRIDE + n] = vh[j];
            sm[OFF_VL + (c8 + j) * VT_STRIDE + n] = vl[j];
        }
    }
    __syncthreads();

    const uint32_t uQH = smem_to_u32(sm + OFF_QH);
    const uint32_t uQL = smem_to_u32(sm + OFF_QL);
    const uint32_t uKH = smem_to_u32(sm + OFF_KH);
    const uint32_t uKL = smem_to_u32(sm + OFF_KL);
    const uint32_t uVH = smem_to_u32(sm + OFF_VH);
    const uint32_t uVL = smem_to_u32(sm + OFF_VL);

    float acc[8][4];
    #pragma unroll
    for (int nt = 0; nt < 8; nt++)
        #pragma unroll
        for (int t = 0; t < 4; t++) acc[nt][t] = 0.f;

    #pragma unroll
    for (int ks = 0; ks < 2; ks++) {
        uint32_t aqh[4], aql[4];
        const int arow = wid * 16 + (lane & 15);
        const int achk = 2 * ks + (lane >> 4);
        ldsm4(aqh, uQH + arow * (QK_STRIDE * 2) + achk * 16);
        ldsm4(aql, uQL + arow * (QK_STRIDE * 2) + achk * 16);
        #pragma unroll
        for (int p = 0; p < 4; p++) {
            uint32_t bkh[4], bkl[4];
            const int brow = p * 16 + ((lane & 16) ? 8 : 0) + (lane & 7);
            const int bchk = 2 * ks + ((lane >> 3) & 1);
            ldsm4(bkh, uKH + brow * (QK_STRIDE * 2) + bchk * 16);
            ldsm4(bkl, uKL + brow * (QK_STRIDE * 2) + bchk * 16);
            #pragma unroll
            for (int hlf = 0; hlf < 2; hlf++) {
                const int nt = p * 2 + hlf;
                mma16816(acc[nt], aqh, bkh[hlf*2], bkh[hlf*2+1]);
                mma16816(acc[nt], aql, bkh[hlf*2], bkh[hlf*2+1]);
                mma16816(acc[nt], aqh, bkl[hlf*2], bkl[hlf*2+1]);
            }
        }
    }

    const float scale = 0.17677669529663687f;
    const float* cb = comb + ((size_t)((b & (NWIN - 1)) * NHEAD + h)) * 4096;
    const int r0 = wid * 16 + (lane >> 2);
    const int r1 = r0 + 8;
    const int cbase = 2 * (lane & 3);
    #pragma unroll
    for (int nt = 0; nt < 8; nt++) {
        float2 c0 = *reinterpret_cast<const float2*>(cb + r0 * 64 + nt * 8 + cbase);
        float2 c1 = *reinterpret_cast<const float2*>(cb + r1 * 64 + nt * 8 + cbase);
        acc[nt][0] = acc[nt][0] * scale + c0.x;
        acc[nt][1] = acc[nt][1] * scale + c0.y;
        acc[nt][2] = acc[nt][2] * scale + c1.x;
        acc[nt][3] = acc[nt][3] * scale + c1.y;
    }
    float mx0 = -1e30f, mx1 = -1e30f;
    #pragma unroll
    for (int nt = 0; nt < 8; nt++) {
        mx0 = fmaxf(mx0, fmaxf(acc[nt][0], acc[nt][1]));
        mx1 = fmaxf(mx1, fmaxf(acc[nt][2], acc[nt][3]));
    }
    mx0 = fmaxf(mx0, __shfl_xor_sync(0xffffffff, mx0, 1));
    mx0 = fmaxf(mx0, __shfl_xor_sync(0xffffffff, mx0, 2));
    mx1 = fmaxf(mx1, __shfl_xor_sync(0xffffffff, mx1, 1));
    mx1 = fmaxf(mx1, __shfl_xor_sync(0xffffffff, mx1, 2));
    float sum0 = 0.f, sum1 = 0.f;
    #pragma unroll
    for (int nt = 0; nt < 8; nt++) {
        acc[nt][0] = __expf(acc[nt][0] - mx0);
        acc[nt][1] = __expf(acc[nt][1] - mx0);
        acc[nt][2] = __expf(acc[nt][2] - mx1);
        acc[nt][3] = __expf(acc[nt][3] - mx1);
        sum0 += acc[nt][0] + acc[nt][1];
        sum1 += acc[nt][2] + acc[nt][3];
    }
    sum0 += __shfl_xor_sync(0xffffffff, sum0, 1);
    sum0 += __shfl_xor_sync(0xffffffff, sum0, 2);
    sum1 += __shfl_xor_sync(0xffffffff, sum1, 1);
    sum1 += __shfl_xor_sync(0xffffffff, sum1, 2);
    const float sinv0 = 1.f / sum0;
    const float sinv1 = 1.f / sum1;

    uint32_t aph[4][4], apl[4][4];
    #pragma unroll
    for (int kk = 0; kk < 4; kk++) {
        const int n0t = 2 * kk, n1t = 2 * kk + 1;
        __half h0, l0, h1, l1;
        split2h(acc[n0t][0], h0, l0); split2h(acc[n0t][1], h1, l1);
        aph[kk][0] = pack2(h0, h1); apl[kk][0] = pack2(l0, l1);
        split2h(acc[n0t][2], h0, l0); split2h(acc[n0t][3], h1, l1);
        aph[kk][1] = pack2(h0, h1); apl[kk][1] = pack2(l0, l1);
        split2h(acc[n1t][0], h0, l0); split2h(acc[n1t][1], h1, l1);
        aph[kk][2] = pack2(h0, h1); apl[kk][2] = pack2(l0, l1);
        split2h(acc[n1t][2], h0, l0); split2h(acc[n1t][3], h1, l1);
        aph[kk][3] = pack2(h0, h1); apl[kk][3] = pack2(l0, l1);
    }

    float oacc[4][4];
    #pragma unroll
    for (int nt = 0; nt < 4; nt++)
        #pragma unroll
        for (int t = 0; t < 4; t++) oacc[nt][t] = 0.f;

    #pragma unroll
    for (int ks = 0; ks < 4; ks++) {
        #pragma unroll
        for (int p = 0; p < 2; p++) {
            uint32_t bvh[4], bvl[4];
            const int brow = p * 16 + ((lane & 16) ? 8 : 0) + (lane & 7);
            const int bchk = 2 * ks + ((lane >> 3) & 1);
            ldsm4(bvh, uVH + brow * (VT_STRIDE * 2) + bchk * 16);
            ldsm4(bvl, uVL + brow * (VT_STRIDE * 2) + bchk * 16);
            #pragma unroll
            for (int hlf = 0; hlf < 2; hlf++) {
                const int nt = p * 2 + hlf;
                mma16816(oacc[nt], aph[ks], bvh[hlf*2], bvh[hlf*2+1]);
                mma16816(oacc[nt], apl[ks], bvh[hlf*2], bvh[hlf*2+1]);
                mma16816(oacc[nt], aph[ks], bvl[hlf*2], bvl[hlf*2+1]);
            }
        }
    }

    #pragma unroll
    for (int nt = 0; nt < 4; nt++) {
        const int d = nt * 8 + cbase;
        if (r0 < NTOK) {
            __half h0, l0, h1, l1;
            split2h(oacc[nt][0] * sinv0, h0, l0);
            split2h(oacc[nt][1] * sinv0, h1, l1);
            size_t base = (size_t)(b * NTOK + r0) * DIMC + h * HDIM + d;
            *reinterpret_cast<uint32_t*>(out_hi + base) = pack2(h0, h1);
            *reinterpret_cast<uint32_t*>(out_lo + base) = pack2(l0, l1);
        }
        if (r1 < NTOK) {
            __half h0, l0, h1, l1;
            split2h(oacc[nt][2] * sinv1, h0, l0);
            split2h(oacc[nt][3] * sinv1, h1, l1);
            size_t base = (size_t)(b * NTOK + r1) * DIMC + h * HDIM + d;
            *reinterpret_cast<uint32_t*>(out_hi + base) = pack2(h0, h1);
            *reinterpret_cast<uint32_t*>(out_lo + base) = pack2(l0, l1);
        }
    }
}

// ---------------- launcher ----------------
extern "C" void kernel_launch(void* const* d_in, const int* in_sizes, int n_in,
                              void* d_out, int out_size)
{
    const float* x          = (const float*)d_in[0];
    const float* mask       = (const float*)d_in[1];
    const float* qkv_w      = (const float*)d_in[2];
    const float* qkv_b      = (const float*)d_in[3];
    const float* proj_w     = (const float*)d_in[4];
    const float* proj_b     = (const float*)d_in[5];
    const float* bias_table = (const float*)d_in[6];
    const int*   rel_idx    = (const int*)d_in[7];
    float* out = (float*)d_out;

    __half *qvh, *qvl, *xhi, *ahi, *alo, *wqh, *wph;
    float* comb;
    cudaGetSymbolAddress((void**)&qvh, g_qvh);
    cudaGetSymbolAddress((void**)&qvl, g_qvl);
    cudaGetSymbolAddress((void**)&xhi, g_xhi);
    cudaGetSymbolAddress((void**)&ahi, g_ahi);
    cudaGetSymbolAddress((void**)&alo, g_alo);
    cudaGetSymbolAddress((void**)&wqh, g_wq_h);
    cudaGetSymbolAddress((void**)&wph, g_wp_h);
    cudaGetSymbolAddress((void**)&comb, g_comb);

    cudaFuncSetAttribute(gemm1_kernel<true>,  cudaFuncAttributeMaxDynamicSharedMemorySize, GEMM_SMEM);
    cudaFuncSetAttribute(gemm1_kernel<false>, cudaFuncAttributeMaxDynamicSharedMemorySize, GEMM_SMEM);

    size_t n4 = (size_t)M_TOTAL * DIMC / 4;
    convert_h_kernel<<<(unsigned)((n4 + 255) / 256), 256>>>(x, xhi, n4);
    wh_t_kernel<<<(QKV_N * DIMC + 255) / 256, 256>>>(qkv_w, wqh, DIMC, QKV_N);
    wh_t_kernel<<<(DIMC * DIMC + 255) / 256, 256>>>(proj_w, wph, DIMC, DIMC);
    combined_kernel<<<dim3(NWIN, NHEAD), 256>>>(bias_table, rel_idx, mask, comb);

    // 1) QKV projection -> fp16 hi/lo
    dim3 g1(QKV_N / 128, M_TOTAL / 128);
    gemm1_kernel<true><<<g1, 256, GEMM_SMEM>>>(xhi, wqh, qkv_b,
                                               nullptr, qvh, qvl,
                                               M_TOTAL, QKV_N, DIMC);

    // 2) tensor-core window attention -> fp16 hi/lo
    dim3 g2(NB, NHEAD);
    attn_mma_kernel<<<g2, 128>>>(qvh, qvl, comb, ahi, alo);

    // 3) output projection -> fp32 (uses hi plane only)
    dim3 g3(DIMC / 128, M_TOTAL / 128);
    gemm1_kernel<false><<<g3, 256, GEMM_SMEM>>>(ahi, wph, proj_b,
                                                out, nullptr, nullptr,
                                                M_TOTAL, DIMC, DIMC);
}

// round 13
// speedup vs baseline: 3.1976x; 1.4175x over previous
#include <cuda_runtime.h>
#include <cuda_fp16.h>
#include <cstdint>

// ---------------- problem constants ----------------
#define NB      2048
#define NTOK    49
#define DIMC    512
#define QKV_N   1536
#define NHEAD   16
#define HDIM    32
#define NWIN    64
#define M_TOTAL (NB * NTOK)   // 100352

// ---------------- scratch (no allocs allowed) ----------------
__device__ __half g_qvh[(size_t)M_TOTAL * QKV_N];   // qkv fp16
__device__ __half g_xhi[(size_t)M_TOTAL * DIMC];
__device__ __half g_ahi[(size_t)M_TOTAL * DIMC];
__device__ __half g_wq_h[(size_t)QKV_N * DIMC];
__device__ __half g_wp_h[(size_t)DIMC * DIMC];
__device__ float  g_comb[(size_t)NWIN * NHEAD * 64 * 64];  // bias+mask, padded -1e30

// ---------------- helpers ----------------
__device__ __forceinline__ uint32_t smem_to_u32(const void* p) {
    uint32_t a;
    asm("{ .reg .u64 t; cvta.to.shared.u64 t, %1; cvt.u32.u64 %0, t; }" : "=r"(a) : "l"(p));
    return a;
}
__device__ __forceinline__ void cp_async16(uint32_t saddr, const void* gaddr) {
    asm volatile("cp.async.cg.shared.global [%0], [%1], 16;" :: "r"(saddr), "l"(gaddr));
}
#define CP_COMMIT() asm volatile("cp.async.commit_group;")
#define CP_WAIT0()  asm volatile("cp.async.wait_group 0;")

__device__ __forceinline__ void ldsm4(uint32_t* r, uint32_t addr) {
    asm volatile("ldmatrix.sync.aligned.m8n8.x4.shared.b16 {%0,%1,%2,%3}, [%4];"
                 : "=r"(r[0]), "=r"(r[1]), "=r"(r[2]), "=r"(r[3]) : "r"(addr));
}
__device__ __forceinline__ void mma16816(float* d, const uint32_t* a,
                                         uint32_t b0, uint32_t b1) {
    asm volatile(
        "mma.sync.aligned.m16n8k16.row.col.f32.f16.f16.f32 "
        "{%0,%1,%2,%3}, {%4,%5,%6,%7}, {%8,%9}, {%0,%1,%2,%3};"
        : "+f"(d[0]), "+f"(d[1]), "+f"(d[2]), "+f"(d[3])
        : "r"(a[0]), "r"(a[1]), "r"(a[2]), "r"(a[3]), "r"(b0), "r"(b1));
}
__device__ __forceinline__ uint32_t pack2(__half a, __half b) {
    __half2 t = __halves2half2(a, b);
    return *reinterpret_cast<uint32_t*>(&t);
}

// ---------------- conversion kernels ----------------
__global__ void __launch_bounds__(256) convert_h_kernel(
    const float* __restrict__ src, __half* __restrict__ hi, size_t n4)
{
    size_t i = (size_t)blockIdx.x * 256 + threadIdx.x;
    if (i >= n4) return;
    float4 v = reinterpret_cast<const float4*>(src)[i];
    uint2 uh{pack2(__float2half_rn(v.x), __float2half_rn(v.y)),
             pack2(__float2half_rn(v.z), __float2half_rn(v.w))};
    reinterpret_cast<uint2*>(hi)[i] = uh;
}

__global__ void __launch_bounds__(256) wh_t_kernel(
    const float* __restrict__ w, __half* __restrict__ hi, int K, int N)
{
    int idx = blockIdx.x * 256 + threadIdx.x;
    if (idx >= N * K) return;
    int n = idx / K, k = idx - n * K;
    hi[idx] = __float2half_rn(w[(size_t)k * N + n]);
}

// combined[w][h][64][64] = bias + mask (padded with -1e30)
__global__ void __launch_bounds__(256) combined_kernel(
    const float* __restrict__ bias_table, const int* __restrict__ rel_idx,
    const float* __restrict__ mask, float* __restrict__ comb)
{
    const int w = blockIdx.x, h = blockIdx.y;
    float* dst = comb + ((size_t)(w * NHEAD + h)) * 4096;
    for (int i = threadIdx.x; i < 4096; i += 256) {
        int n = i >> 6, m = i & 63;
        float v = -1e30f;
        if (n < NTOK && m < NTOK)
            v = bias_table[rel_idx[n * NTOK + m] * NHEAD + h]
              + mask[((size_t)w * NTOK + n) * NTOK + m];
        dst[i] = v;
    }
}

// ---------------- mma.sync plain fp16 GEMM: C = A @ B^T + bias -------------
#define STAGE_BYTES 32768
#define GEMM_SMEM   (2 * STAGE_BYTES)

__device__ __forceinline__ uint32_t sw_addr(uint32_t base, int row, int chunk) {
    return base + row * 128 + ((chunk ^ (row & 7)) << 4);
}

template<bool HOUT>
__global__ void __launch_bounds__(256, 2) gemm1_kernel(
    const __half* __restrict__ Ah, const __half* __restrict__ Bh,
    const float* __restrict__ bias, float* __restrict__ C,
    __half* __restrict__ Chi,
    int M, int N, int K)
{
    extern __shared__ char smem[];
    const uint32_t sbase = smem_to_u32(smem);
    const int tid  = threadIdx.x;
    const int lane = tid & 31;
    const int wid  = tid >> 5;
    const int warp_m = wid & 3;
    const int warp_n = wid >> 2;
    const int m0 = blockIdx.y * 128;
    const int n0 = blockIdx.x * 128;
    const int NKT = K >> 6;

    float acc[2][8][4];
    #pragma unroll
    for (int i = 0; i < 2; i++)
        #pragma unroll
        for (int j = 0; j < 8; j++)
            #pragma unroll
            for (int t = 0; t < 4; t++) acc[i][j][t] = 0.f;

    auto load_stage = [&](int kt, int s) {
        const uint32_t sb = sbase + s * STAGE_BYTES;
        const int kofs = kt * 64;
        #pragma unroll
        for (int i = 0; i < 4; i++) {
            int f   = tid + i * 256;
            int row = f >> 3;
            int c   = f & 7;
            uint32_t sw = sw_addr(0, row, c);
            size_t ga = (size_t)(m0 + row) * K + kofs + c * 8;
            size_t gb = (size_t)(n0 + row) * K + kofs + c * 8;
            cp_async16(sb + sw,         Ah + ga);
            cp_async16(sb + 16384 + sw, Bh + gb);
        }
        CP_COMMIT();
    };

    load_stage(0, 0);

    for (int kt = 0; kt < NKT; kt++) {
        const int s = kt & 1;
        CP_WAIT0();
        __syncthreads();
        if (kt + 1 < NKT) load_stage(kt + 1, s ^ 1);

        const uint32_t sA = sbase + s * STAGE_BYTES;
        const uint32_t sB = sA + 16384;

        #pragma unroll
        for (int ks = 0; ks < 4; ks++) {
            uint32_t ah[2][4];
            {
                const int arow = warp_m * 32 + (lane & 15);
                const int achk = 2 * ks + (lane >> 4);
                #pragma unroll
                for (int mt = 0; mt < 2; mt++)
                    ldsm4(ah[mt], sw_addr(sA, arow + mt * 16, achk));
            }
            uint32_t bh[4][4];
            {
                const int brow_base = warp_n * 64 + ((lane & 16) ? 8 : 0) + (lane & 7);
                const int bchk = 2 * ks + ((lane >> 3) & 1);
                #pragma unroll
                for (int p = 0; p < 4; p++)
                    ldsm4(bh[p], sw_addr(sB, brow_base + p * 16, bchk));
            }
            #pragma unroll
            for (int mt = 0; mt < 2; mt++)
                #pragma unroll
                for (int p = 0; p < 4; p++)
                    #pragma unroll
                    for (int hlf = 0; hlf < 2; hlf++)
                        mma16816(acc[mt][p * 2 + hlf], ah[mt],
                                 bh[p][hlf*2], bh[p][hlf*2+1]);
        }
        __syncthreads();
    }

    const int row0 = m0 + warp_m * 32 + (lane >> 2);
    const int col0 = n0 + warp_n * 64 + (lane & 3) * 2;
    #pragma unroll
    for (int mt = 0; mt < 2; mt++)
        #pragma unroll
        for (int nt = 0; nt < 8; nt++) {
            const int c = col0 + nt * 8;
            const float b0 = bias[c], b1 = bias[c + 1];
            const int r0 = row0 + mt * 16;
            float v00 = acc[mt][nt][0] + b0, v01 = acc[mt][nt][1] + b1;
            float v10 = acc[mt][nt][2] + b0, v11 = acc[mt][nt][3] + b1;
            if (HOUT) {
                *reinterpret_cast<uint32_t*>(Chi + (size_t)r0 * N + c) =
                    pack2(__float2half_rn(v00), __float2half_rn(v01));
                *reinterpret_cast<uint32_t*>(Chi + (size_t)(r0 + 8) * N + c) =
                    pack2(__float2half_rn(v10), __float2half_rn(v11));
            } else {
                *reinterpret_cast<float2*>(C + (size_t)r0 * N + c)       = float2{v00, v01};
                *reinterpret_cast<float2*>(C + (size_t)(r0 + 8) * N + c) = float2{v10, v11};
            }
        }
}

// ---------------- tensor-core window attention (pure fp16) -----------------
// Block = (window, head), 4 warps; warp = 16-row m-tile. S in fragments,
// softmax in-register, P->fp16, O = P@V. Single-precision-plane everywhere.
#define QK_STRIDE 40
#define VT_STRIDE 72
#define OFF_QH 0
#define OFF_KH 2560
#define OFF_VH 5120
#define SM_HALVES 7424

__global__ void __launch_bounds__(128) attn_mma_kernel(
    const __half* __restrict__ qvh, const float* __restrict__ comb,
    __half* __restrict__ out_hi)
{
    const int b = blockIdx.x;
    const int h = blockIdx.y;
    const int tid  = threadIdx.x;
    const int lane = tid & 31;
    const int wid  = tid >> 5;

    __shared__ __align__(16) __half sm[SM_HALVES];

    for (int i = tid; i < SM_HALVES / 8; i += 128)
        reinterpret_cast<uint4*>(sm)[i] = uint4{0, 0, 0, 0};
    __syncthreads();

    // load Q/K row-major (stride 40), V transposed Vt[d][m] (stride 72)
    for (int i = tid; i < NTOK * 4; i += 128) {
        int n  = i >> 2;
        int c8 = (i & 3) << 3;
        size_t base = (size_t)(b * NTOK + n) * QKV_N + h * HDIM + c8;
        uint4 qh8 = *reinterpret_cast<const uint4*>(qvh + base);
        uint4 kh8 = *reinterpret_cast<const uint4*>(qvh + base + DIMC);
        uint4 vh8 = *reinterpret_cast<const uint4*>(qvh + base + 2 * DIMC);
        *reinterpret_cast<uint4*>(sm + OFF_QH + n * QK_STRIDE + c8) = qh8;
        *reinterpret_cast<uint4*>(sm + OFF_KH + n * QK_STRIDE + c8) = kh8;
        const __half* vh = reinterpret_cast<const __half*>(&vh8);
        #pragma unroll
        for (int j = 0; j < 8; j++)
            sm[OFF_VH + (c8 + j) * VT_STRIDE + n] = vh[j];
    }
    __syncthreads();

    const uint32_t uQH = smem_to_u32(sm + OFF_QH);
    const uint32_t uKH = smem_to_u32(sm + OFF_KH);
    const uint32_t uVH = smem_to_u32(sm + OFF_VH);

    // ---- S = Q @ K^T ----
    float acc[8][4];
    #pragma unroll
    for (int nt = 0; nt < 8; nt++)
        #pragma unroll
        for (int t = 0; t < 4; t++) acc[nt][t] = 0.f;

    #pragma unroll
    for (int ks = 0; ks < 2; ks++) {
        uint32_t aqh[4];
        const int arow = wid * 16 + (lane & 15);
        const int achk = 2 * ks + (lane >> 4);
        ldsm4(aqh, uQH + arow * (QK_STRIDE * 2) + achk * 16);
        #pragma unroll
        for (int p = 0; p < 4; p++) {
            uint32_t bkh[4];
            const int brow = p * 16 + ((lane & 16) ? 8 : 0) + (lane & 7);
            const int bchk = 2 * ks + ((lane >> 3) & 1);
            ldsm4(bkh, uKH + brow * (QK_STRIDE * 2) + bchk * 16);
            #pragma unroll
            for (int hlf = 0; hlf < 2; hlf++)
                mma16816(acc[p * 2 + hlf], aqh, bkh[hlf*2], bkh[hlf*2+1]);
        }
    }

    // ---- scale + combined(bias+mask), softmax in fragments ----
    const float scale = 0.17677669529663687f;
    const float* cb = comb + ((size_t)((b & (NWIN - 1)) * NHEAD + h)) * 4096;
    const int r0 = wid * 16 + (lane >> 2);
    const int r1 = r0 + 8;
    const int cbase = 2 * (lane & 3);
    #pragma unroll
    for (int nt = 0; nt < 8; nt++) {
        float2 c0 = *reinterpret_cast<const float2*>(cb + r0 * 64 + nt * 8 + cbase);
        float2 c1 = *reinterpret_cast<const float2*>(cb + r1 * 64 + nt * 8 + cbase);
        acc[nt][0] = acc[nt][0] * scale + c0.x;
        acc[nt][1] = acc[nt][1] * scale + c0.y;
        acc[nt][2] = acc[nt][2] * scale + c1.x;
        acc[nt][3] = acc[nt][3] * scale + c1.y;
    }
    float mx0 = -1e30f, mx1 = -1e30f;
    #pragma unroll
    for (int nt = 0; nt < 8; nt++) {
        mx0 = fmaxf(mx0, fmaxf(acc[nt][0], acc[nt][1]));
        mx1 = fmaxf(mx1, fmaxf(acc[nt][2], acc[nt][3]));
    }
    mx0 = fmaxf(mx0, __shfl_xor_sync(0xffffffff, mx0, 1));
    mx0 = fmaxf(mx0, __shfl_xor_sync(0xffffffff, mx0, 2));
    mx1 = fmaxf(mx1, __shfl_xor_sync(0xffffffff, mx1, 1));
    mx1 = fmaxf(mx1, __shfl_xor_sync(0xffffffff, mx1, 2));
    float sum0 = 0.f, sum1 = 0.f;
    #pragma unroll
    for (int nt = 0; nt < 8; nt++) {
        acc[nt][0] = __expf(acc[nt][0] - mx0);
        acc[nt][1] = __expf(acc[nt][1] - mx0);
        acc[nt][2] = __expf(acc[nt][2] - mx1);
        acc[nt][3] = __expf(acc[nt][3] - mx1);
        sum0 += acc[nt][0] + acc[nt][1];
        sum1 += acc[nt][2] + acc[nt][3];
    }
    sum0 += __shfl_xor_sync(0xffffffff, sum0, 1);
    sum0 += __shfl_xor_sync(0xffffffff, sum0, 2);
    sum1 += __shfl_xor_sync(0xffffffff, sum1, 1);
    sum1 += __shfl_xor_sync(0xffffffff, sum1, 2);
    const float sinv0 = 1.f / sum0;
    const float sinv1 = 1.f / sum1;

    // ---- P fragments (fp16) from S accumulators ----
    uint32_t aph[4][4];
    #pragma unroll
    for (int kk = 0; kk < 4; kk++) {
        const int n0t = 2 * kk, n1t = 2 * kk + 1;
        aph[kk][0] = pack2(__float2half_rn(acc[n0t][0]), __float2half_rn(acc[n0t][1]));
        aph[kk][1] = pack2(__float2half_rn(acc[n0t][2]), __float2half_rn(acc[n0t][3]));
        aph[kk][2] = pack2(__float2half_rn(acc[n1t][0]), __float2half_rn(acc[n1t][1]));
        aph[kk][3] = pack2(__float2half_rn(acc[n1t][2]), __float2half_rn(acc[n1t][3]));
    }

    // ---- O = P @ V ----
    float oacc[4][4];
    #pragma unroll
    for (int nt = 0; nt < 4; nt++)
        #pragma unroll
        for (int t = 0; t < 4; t++) oacc[nt][t] = 0.f;

    #pragma unroll
    for (int ks = 0; ks < 4; ks++) {
        #pragma unroll
        for (int p = 0; p < 2; p++) {
            uint32_t bvh[4];
            const int brow = p * 16 + ((lane & 16) ? 8 : 0) + (lane & 7);
            const int bchk = 2 * ks + ((lane >> 3) & 1);
            ldsm4(bvh, uVH + brow * (VT_STRIDE * 2) + bchk * 16);
            #pragma unroll
            for (int hlf = 0; hlf < 2; hlf++)
                mma16816(oacc[p * 2 + hlf], aph[ks], bvh[hlf*2], bvh[hlf*2+1]);
        }
    }

    // ---- normalize + store (rows < 49 only) ----
    #pragma unroll
    for (int nt = 0; nt < 4; nt++) {
        const int d = nt * 8 + cbase;
        if (r0 < NTOK) {
            size_t base = (size_t)(b * NTOK + r0) * DIMC + h * HDIM + d;
            *reinterpret_cast<uint32_t*>(out_hi + base) =
                pack2(__float2half_rn(oacc[nt][0] * sinv0),
                      __float2half_rn(oacc[nt][1] * sinv0));
        }
        if (r1 < NTOK) {
            size_t base = (size_t)(b * NTOK + r1) * DIMC + h * HDIM + d;
            *reinterpret_cast<uint32_t*>(out_hi + base) =
                pack2(__float2half_rn(oacc[nt][2] * sinv1),
                      __float2half_rn(oacc[nt][3] * sinv1));
        }
    }
}

// ---------------- launcher ----------------
extern "C" void kernel_launch(void* const* d_in, const int* in_sizes, int n_in,
                              void* d_out, int out_size)
{
    const float* x          = (const float*)d_in[0];
    const float* mask       = (const float*)d_in[1];
    const float* qkv_w      = (const float*)d_in[2];
    const float* qkv_b      = (const float*)d_in[3];
    const float* proj_w     = (const float*)d_in[4];
    const float* proj_b     = (const float*)d_in[5];
    const float* bias_table = (const float*)d_in[6];
    const int*   rel_idx    = (const int*)d_in[7];
    float* out = (float*)d_out;

    __half *qvh, *xhi, *ahi, *wqh, *wph;
    float* comb;
    cudaGetSymbolAddress((void**)&qvh, g_qvh);
    cudaGetSymbolAddress((void**)&xhi, g_xhi);
    cudaGetSymbolAddress((void**)&ahi, g_ahi);
    cudaGetSymbolAddress((void**)&wqh, g_wq_h);
    cudaGetSymbolAddress((void**)&wph, g_wp_h);
    cudaGetSymbolAddress((void**)&comb, g_comb);

    cudaFuncSetAttribute(gemm1_kernel<true>,  cudaFuncAttributeMaxDynamicSharedMemorySize, GEMM_SMEM);
    cudaFuncSetAttribute(gemm1_kernel<false>, cudaFuncAttributeMaxDynamicSharedMemorySize, GEMM_SMEM);

    size_t n4 = (size_t)M_TOTAL * DIMC / 4;
    convert_h_kernel<<<(unsigned)((n4 + 255) / 256), 256>>>(x, xhi, n4);
    wh_t_kernel<<<(QKV_N * DIMC + 255) / 256, 256>>>(qkv_w, wqh, DIMC, QKV_N);
    wh_t_kernel<<<(DIMC * DIMC + 255) / 256, 256>>>(proj_w, wph, DIMC, DIMC);
    combined_kernel<<<dim3(NWIN, NHEAD), 256>>>(bias_table, rel_idx, mask, comb);

    // 1) QKV projection -> fp16
    dim3 g1(QKV_N / 128, M_TOTAL / 128);
    gemm1_kernel<true><<<g1, 256, GEMM_SMEM>>>(xhi, wqh, qkv_b,
                                               nullptr, qvh,
                                               M_TOTAL, QKV_N, DIMC);

    // 2) tensor-core window attention (pure fp16) -> fp16
    dim3 g2(NB, NHEAD);
    attn_mma_kernel<<<g2, 128>>>(qvh, comb, ahi);

    // 3) output projection -> fp32
    dim3 g3(DIMC / 128, M_TOTAL / 128);
    gemm1_kernel<false><<<g3, 256, GEMM_SMEM>>>(ahi, wph, proj_b,
                                                out, nullptr,
                                                M_TOTAL, DIMC, DIMC);
}

// round 14
// speedup vs baseline: 3.2501x; 1.0164x over previous
#include <cuda_runtime.h>
#include <cuda_fp16.h>
#include <cstdint>

// ---------------- problem constants ----------------
#define NB      2048
#define NTOK    49
#define DIMC    512
#define QKV_N   1536
#define NHEAD   16
#define HDIM    32
#define NWIN    64
#define M_TOTAL (NB * NTOK)   // 100352

// ---------------- scratch (no allocs allowed) ----------------
__device__ __half g_qvh[(size_t)M_TOTAL * QKV_N];   // qkv fp16
__device__ __half g_xhi[(size_t)M_TOTAL * DIMC];
__device__ __half g_ahi[(size_t)M_TOTAL * DIMC];
__device__ __half g_wq_h[(size_t)QKV_N * DIMC];
__device__ __half g_wp_h[(size_t)DIMC * DIMC];
__device__ __half g_comb[(size_t)NWIN * NHEAD * 64 * 64];  // bias+mask fp16, pad -60000

// ---------------- helpers ----------------
__device__ __forceinline__ uint32_t smem_to_u32(const void* p) {
    uint32_t a;
    asm("{ .reg .u64 t; cvta.to.shared.u64 t, %1; cvt.u32.u64 %0, t; }" : "=r"(a) : "l"(p));
    return a;
}
__device__ __forceinline__ void cp_async16(uint32_t saddr, const void* gaddr) {
    asm volatile("cp.async.cg.shared.global [%0], [%1], 16;" :: "r"(saddr), "l"(gaddr));
}
#define CP_COMMIT() asm volatile("cp.async.commit_group;")
#define CP_WAIT0()  asm volatile("cp.async.wait_group 0;")

__device__ __forceinline__ void ldsm4(uint32_t* r, uint32_t addr) {
    asm volatile("ldmatrix.sync.aligned.m8n8.x4.shared.b16 {%0,%1,%2,%3}, [%4];"
                 : "=r"(r[0]), "=r"(r[1]), "=r"(r[2]), "=r"(r[3]) : "r"(addr));
}
__device__ __forceinline__ void ldsm4t(uint32_t* r, uint32_t addr) {
    asm volatile("ldmatrix.sync.aligned.m8n8.x4.trans.shared.b16 {%0,%1,%2,%3}, [%4];"
                 : "=r"(r[0]), "=r"(r[1]), "=r"(r[2]), "=r"(r[3]) : "r"(addr));
}
__device__ __forceinline__ void mma16816(float* d, const uint32_t* a,
                                         uint32_t b0, uint32_t b1) {
    asm volatile(
        "mma.sync.aligned.m16n8k16.row.col.f32.f16.f16.f32 "
        "{%0,%1,%2,%3}, {%4,%5,%6,%7}, {%8,%9}, {%0,%1,%2,%3};"
        : "+f"(d[0]), "+f"(d[1]), "+f"(d[2]), "+f"(d[3])
        : "r"(a[0]), "r"(a[1]), "r"(a[2]), "r"(a[3]), "r"(b0), "r"(b1));
}
__device__ __forceinline__ uint32_t pack2(__half a, __half b) {
    __half2 t = __halves2half2(a, b);
    return *reinterpret_cast<uint32_t*>(&t);
}

// ---------------- conversion kernels ----------------
__global__ void __launch_bounds__(256) convert_h_kernel(
    const float* __restrict__ src, __half* __restrict__ hi, size_t n4)
{
    size_t i = (size_t)blockIdx.x * 256 + threadIdx.x;
    if (i >= n4) return;
    float4 v = reinterpret_cast<const float4*>(src)[i];
    uint2 uh{pack2(__float2half_rn(v.x), __float2half_rn(v.y)),
             pack2(__float2half_rn(v.z), __float2half_rn(v.w))};
    reinterpret_cast<uint2*>(hi)[i] = uh;
}

__global__ void __launch_bounds__(256) wh_t_kernel(
    const float* __restrict__ w, __half* __restrict__ hi, int K, int N)
{
    int idx = blockIdx.x * 256 + threadIdx.x;
    if (idx >= N * K) return;
    int n = idx / K, k = idx - n * K;
    hi[idx] = __float2half_rn(w[(size_t)k * N + n]);
}

// combined[w][h][64][64] = fp16(bias + mask), padded with -60000
__global__ void __launch_bounds__(256) combined_kernel(
    const float* __restrict__ bias_table, const int* __restrict__ rel_idx,
    const float* __restrict__ mask, __half* __restrict__ comb)
{
    const int w = blockIdx.x, h = blockIdx.y;
    __half* dst = comb + ((size_t)(w * NHEAD + h)) * 4096;
    for (int i = threadIdx.x; i < 4096; i += 256) {
        int n = i >> 6, m = i & 63;
        float v = -60000.f;
        if (n < NTOK && m < NTOK)
            v = bias_table[rel_idx[n * NTOK + m] * NHEAD + h]
              + mask[((size_t)w * NTOK + n) * NTOK + m];
        dst[i] = __float2half_rn(v);
    }
}

// ---------------- mma.sync plain fp16 GEMM: C = A @ B^T + bias -------------
#define STAGE_BYTES 32768
#define GEMM_SMEM   (2 * STAGE_BYTES)

__device__ __forceinline__ uint32_t sw_addr(uint32_t base, int row, int chunk) {
    return base + row * 128 + ((chunk ^ (row & 7)) << 4);
}

template<bool HOUT>
__global__ void __launch_bounds__(256, 2) gemm1_kernel(
    const __half* __restrict__ Ah, const __half* __restrict__ Bh,
    const float* __restrict__ bias, float* __restrict__ C,
    __half* __restrict__ Chi,
    int M, int N, int K)
{
    extern __shared__ char smem[];
    const uint32_t sbase = smem_to_u32(smem);
    const int tid  = threadIdx.x;
    const int lane = tid & 31;
    const int wid  = tid >> 5;
    const int warp_m = wid & 3;
    const int warp_n = wid >> 2;
    const int m0 = blockIdx.y * 128;
    const int n0 = blockIdx.x * 128;
    const int NKT = K >> 6;

    float acc[2][8][4];
    #pragma unroll
    for (int i = 0; i < 2; i++)
        #pragma unroll
        for (int j = 0; j < 8; j++)
            #pragma unroll
            for (int t = 0; t < 4; t++) acc[i][j][t] = 0.f;

    auto load_stage = [&](int kt, int s) {
        const uint32_t sb = sbase + s * STAGE_BYTES;
        const int kofs = kt * 64;
        #pragma unroll
        for (int i = 0; i < 4; i++) {
            int f   = tid + i * 256;
            int row = f >> 3;
            int c   = f & 7;
            uint32_t sw = sw_addr(0, row, c);
            size_t ga = (size_t)(m0 + row) * K + kofs + c * 8;
            size_t gb = (size_t)(n0 + row) * K + kofs + c * 8;
            cp_async16(sb + sw,         Ah + ga);
            cp_async16(sb + 16384 + sw, Bh + gb);
        }
        CP_COMMIT();
    };

    load_stage(0, 0);

    for (int kt = 0; kt < NKT; kt++) {
        const int s = kt & 1;
        CP_WAIT0();
        __syncthreads();
        if (kt + 1 < NKT) load_stage(kt + 1, s ^ 1);

        const uint32_t sA = sbase + s * STAGE_BYTES;
        const uint32_t sB = sA + 16384;

        #pragma unroll
        for (int ks = 0; ks < 4; ks++) {
            uint32_t ah[2][4];
            {
                const int arow = warp_m * 32 + (lane & 15);
                const int achk = 2 * ks + (lane >> 4);
                #pragma unroll
                for (int mt = 0; mt < 2; mt++)
                    ldsm4(ah[mt], sw_addr(sA, arow + mt * 16, achk));
            }
            uint32_t bh[4][4];
            {
                const int brow_base = warp_n * 64 + ((lane & 16) ? 8 : 0) + (lane & 7);
                const int bchk = 2 * ks + ((lane >> 3) & 1);
                #pragma unroll
                for (int p = 0; p < 4; p++)
                    ldsm4(bh[p], sw_addr(sB, brow_base + p * 16, bchk));
            }
            #pragma unroll
            for (int mt = 0; mt < 2; mt++)
                #pragma unroll
                for (int p = 0; p < 4; p++)
                    #pragma unroll
                    for (int hlf = 0; hlf < 2; hlf++)
                        mma16816(acc[mt][p * 2 + hlf], ah[mt],
                                 bh[p][hlf*2], bh[p][hlf*2+1]);
        }
        __syncthreads();
    }

    const int row0 = m0 + warp_m * 32 + (lane >> 2);
    const int col0 = n0 + warp_n * 64 + (lane & 3) * 2;
    #pragma unroll
    for (int mt = 0; mt < 2; mt++)
        #pragma unroll
        for (int nt = 0; nt < 8; nt++) {
            const int c = col0 + nt * 8;
            const float b0 = bias[c], b1 = bias[c + 1];
            const int r0 = row0 + mt * 16;
            float v00 = acc[mt][nt][0] + b0, v01 = acc[mt][nt][1] + b1;
            float v10 = acc[mt][nt][2] + b0, v11 = acc[mt][nt][3] + b1;
            if (HOUT) {
                *reinterpret_cast<uint32_t*>(Chi + (size_t)r0 * N + c) =
                    pack2(__float2half_rn(v00), __float2half_rn(v01));
                *reinterpret_cast<uint32_t*>(Chi + (size_t)(r0 + 8) * N + c) =
                    pack2(__float2half_rn(v10), __float2half_rn(v11));
            } else {
                *reinterpret_cast<float2*>(C + (size_t)r0 * N + c)       = float2{v00, v01};
                *reinterpret_cast<float2*>(C + (size_t)(r0 + 8) * N + c) = float2{v10, v11};
            }
        }
}

// ---------------- tensor-core window attention (pure fp16) -----------------
// Q/K/V all row-major stride 40; V consumed via ldmatrix.trans.
#define QK_STRIDE 40
#define OFF_QH 0
#define OFF_KH 2560
#define OFF_VH 5120
#define SM_HALVES 7680

__global__ void __launch_bounds__(128) attn_mma_kernel(
    const __half* __restrict__ qvh, const __half* __restrict__ comb,
    __half* __restrict__ out_hi)
{
    const int b = blockIdx.x;
    const int h = blockIdx.y;
    const int tid  = threadIdx.x;
    const int lane = tid & 31;
    const int wid  = tid >> 5;

    __shared__ __align__(16) __half sm[SM_HALVES];

    for (int i = tid; i < SM_HALVES / 8; i += 128)
        reinterpret_cast<uint4*>(sm)[i] = uint4{0, 0, 0, 0};
    __syncthreads();

    // load Q/K/V row-major (stride 40 halves)
    for (int i = tid; i < NTOK * 4; i += 128) {
        int n  = i >> 2;
        int c8 = (i & 3) << 3;
        size_t base = (size_t)(b * NTOK + n) * QKV_N + h * HDIM + c8;
        uint4 qh8 = *reinterpret_cast<const uint4*>(qvh + base);
        uint4 kh8 = *reinterpret_cast<const uint4*>(qvh + base + DIMC);
        uint4 vh8 = *reinterpret_cast<const uint4*>(qvh + base + 2 * DIMC);
        *reinterpret_cast<uint4*>(sm + OFF_QH + n * QK_STRIDE + c8) = qh8;
        *reinterpret_cast<uint4*>(sm + OFF_KH + n * QK_STRIDE + c8) = kh8;
        *reinterpret_cast<uint4*>(sm + OFF_VH + n * QK_STRIDE + c8) = vh8;
    }
    __syncthreads();

    const uint32_t uQH = smem_to_u32(sm + OFF_QH);
    const uint32_t uKH = smem_to_u32(sm + OFF_KH);
    const uint32_t uVH = smem_to_u32(sm + OFF_VH);

    // ---- S = Q @ K^T ----
    float acc[8][4];
    #pragma unroll
    for (int nt = 0; nt < 8; nt++)
        #pragma unroll
        for (int t = 0; t < 4; t++) acc[nt][t] = 0.f;

    #pragma unroll
    for (int ks = 0; ks < 2; ks++) {
        uint32_t aqh[4];
        const int arow = wid * 16 + (lane & 15);
        const int achk = 2 * ks + (lane >> 4);
        ldsm4(aqh, uQH + arow * (QK_STRIDE * 2) + achk * 16);
        #pragma unroll
        for (int p = 0; p < 4; p++) {
            uint32_t bkh[4];
            const int brow = p * 16 + ((lane & 16) ? 8 : 0) + (lane & 7);
            const int bchk = 2 * ks + ((lane >> 3) & 1);
            ldsm4(bkh, uKH + brow * (QK_STRIDE * 2) + bchk * 16);
            #pragma unroll
            for (int hlf = 0; hlf < 2; hlf++)
                mma16816(acc[p * 2 + hlf], aqh, bkh[hlf*2], bkh[hlf*2+1]);
        }
    }

    // ---- scale + combined(bias+mask fp16), softmax in fragments ----
    const float scale = 0.17677669529663687f;
    const __half* cb = comb + ((size_t)((b & (NWIN - 1)) * NHEAD + h)) * 4096;
    const int r0 = wid * 16 + (lane >> 2);
    const int r1 = r0 + 8;
    const int cbase = 2 * (lane & 3);
    #pragma unroll
    for (int nt = 0; nt < 8; nt++) {
        uint32_t u0 = *reinterpret_cast<const uint32_t*>(cb + r0 * 64 + nt * 8 + cbase);
        uint32_t u1 = *reinterpret_cast<const uint32_t*>(cb + r1 * 64 + nt * 8 + cbase);
        float2 c0 = __half22float2(*reinterpret_cast<__half2*>(&u0));
        float2 c1 = __half22float2(*reinterpret_cast<__half2*>(&u1));
        acc[nt][0] = acc[nt][0] * scale + c0.x;
        acc[nt][1] = acc[nt][1] * scale + c0.y;
        acc[nt][2] = acc[nt][2] * scale + c1.x;
        acc[nt][3] = acc[nt][3] * scale + c1.y;
    }
    float mx0 = -1e30f, mx1 = -1e30f;
    #pragma unroll
    for (int nt = 0; nt < 8; nt++) {
        mx0 = fmaxf(mx0, fmaxf(acc[nt][0], acc[nt][1]));
        mx1 = fmaxf(mx1, fmaxf(acc[nt][2], acc[nt][3]));
    }
    mx0 = fmaxf(mx0, __shfl_xor_sync(0xffffffff, mx0, 1));
    mx0 = fmaxf(mx0, __shfl_xor_sync(0xffffffff, mx0, 2));
    mx1 = fmaxf(mx1, __shfl_xor_sync(0xffffffff, mx1, 1));
    mx1 = fmaxf(mx1, __shfl_xor_sync(0xffffffff, mx1, 2));
    float sum0 = 0.f, sum1 = 0.f;
    #pragma unroll
    for (int nt = 0; nt < 8; nt++) {
        acc[nt][0] = __expf(acc[nt][0] - mx0);
        acc[nt][1] = __expf(acc[nt][1] - mx0);
        acc[nt][2] = __expf(acc[nt][2] - mx1);
        acc[nt][3] = __expf(acc[nt][3] - mx1);
        sum0 += acc[nt][0] + acc[nt][1];
        sum1 += acc[nt][2] + acc[nt][3];
    }
    sum0 += __shfl_xor_sync(0xffffffff, sum0, 1);
    sum0 += __shfl_xor_sync(0xffffffff, sum0, 2);
    sum1 += __shfl_xor_sync(0xffffffff, sum1, 1);
    sum1 += __shfl_xor_sync(0xffffffff, sum1, 2);
    const float sinv0 = 1.f / sum0;
    const float sinv1 = 1.f / sum1;

    // ---- P fragments (fp16) ----
    uint32_t aph[4][4];
    #pragma unroll
    for (int kk = 0; kk < 4; kk++) {
        const int n0t = 2 * kk, n1t = 2 * kk + 1;
        aph[kk][0] = pack2(__float2half_rn(acc[n0t][0]), __float2half_rn(acc[n0t][1]));
        aph[kk][1] = pack2(__float2half_rn(acc[n0t][2]), __float2half_rn(acc[n0t][3]));
        aph[kk][2] = pack2(__float2half_rn(acc[n1t][0]), __float2half_rn(acc[n1t][1]));
        aph[kk][3] = pack2(__float2half_rn(acc[n1t][2]), __float2half_rn(acc[n1t][3]));
    }

    // ---- O = P @ V  (V row-major, ldmatrix.trans) ----
    float oacc[4][4];
    #pragma unroll
    for (int nt = 0; nt < 4; nt++)
        #pragma unroll
        for (int t = 0; t < 4; t++) oacc[nt][t] = 0.f;

    #pragma unroll
    for (int ks = 0; ks < 4; ks++) {
        const int krow = ks * 16 + ((lane & 8) ? 8 : 0) + (lane & 7);
        #pragma unroll
        for (int p = 0; p < 2; p++) {
            uint32_t bvh[4];
            const int ncol = p * 16 + ((lane & 16) ? 8 : 0);
            ldsm4t(bvh, uVH + krow * (QK_STRIDE * 2) + ncol * 2);
            #pragma unroll
            for (int hlf = 0; hlf < 2; hlf++)
                mma16816(oacc[p * 2 + hlf], aph[ks], bvh[hlf*2], bvh[hlf*2+1]);
        }
    }

    // ---- normalize + store (rows < 49 only) ----
    #pragma unroll
    for (int nt = 0; nt < 4; nt++) {
        const int d = nt * 8 + cbase;
        if (r0 < NTOK) {
            size_t base = (size_t)(b * NTOK + r0) * DIMC + h * HDIM + d;
            *reinterpret_cast<uint32_t*>(out_hi + base) =
                pack2(__float2half_rn(oacc[nt][0] * sinv0),
                      __float2half_rn(oacc[nt][1] * sinv0));
        }
        if (r1 < NTOK) {
            size_t base = (size_t)(b * NTOK + r1) * DIMC + h * HDIM + d;
            *reinterpret_cast<uint32_t*>(out_hi + base) =
                pack2(__float2half_rn(oacc[nt][2] * sinv1),
                      __float2half_rn(oacc[nt][3] * sinv1));
        }
    }
}

// ---------------- launcher ----------------
extern "C" void kernel_launch(void* const* d_in, const int* in_sizes, int n_in,
                              void* d_out, int out_size)
{
    const float* x          = (const float*)d_in[0];
    const float* mask       = (const float*)d_in[1];
    const float* qkv_w      = (const float*)d_in[2];
    const float* qkv_b      = (const float*)d_in[3];
    const float* proj_w     = (const float*)d_in[4];
    const float* proj_b     = (const float*)d_in[5];
    const float* bias_table = (const float*)d_in[6];
    const int*   rel_idx    = (const int*)d_in[7];
    float* out = (float*)d_out;

    __half *qvh, *xhi, *ahi, *wqh, *wph, *comb;
    cudaGetSymbolAddress((void**)&qvh, g_qvh);
    cudaGetSymbolAddress((void**)&xhi, g_xhi);
    cudaGetSymbolAddress((void**)&ahi, g_ahi);
    cudaGetSymbolAddress((void**)&wqh, g_wq_h);
    cudaGetSymbolAddress((void**)&wph, g_wp_h);
    cudaGetSymbolAddress((void**)&comb, g_comb);

    cudaFuncSetAttribute(gemm1_kernel<true>,  cudaFuncAttributeMaxDynamicSharedMemorySize, GEMM_SMEM);
    cudaFuncSetAttribute(gemm1_kernel<false>, cudaFuncAttributeMaxDynamicSharedMemorySize, GEMM_SMEM);

    size_t n4 = (size_t)M_TOTAL * DIMC / 4;
    convert_h_kernel<<<(unsigned)((n4 + 255) / 256), 256>>>(x, xhi, n4);
    wh_t_kernel<<<(QKV_N * DIMC + 255) / 256, 256>>>(qkv_w, wqh, DIMC, QKV_N);
    wh_t_kernel<<<(DIMC * DIMC + 255) / 256, 256>>>(proj_w, wph, DIMC, DIMC);
    combined_kernel<<<dim3(NWIN, NHEAD), 256>>>(bias_table, rel_idx, mask, comb);

    // 1) QKV projection -> fp16
    dim3 g1(QKV_N / 128, M_TOTAL / 128);
    gemm1_kernel<true><<<g1, 256, GEMM_SMEM>>>(xhi, wqh, qkv_b,
                                               nullptr, qvh,
                                               M_TOTAL, QKV_N, DIMC);

    // 2) tensor-core window attention (pure fp16) -> fp16
    dim3 g2(NB, NHEAD);
    attn_mma_kernel<<<g2, 128>>>(qvh, comb, ahi);

    // 3) output projection -> fp32
    dim3 g3(DIMC / 128, M_TOTAL / 128);
    gemm1_kernel<false><<<g3, 256, GEMM_SMEM>>>(ahi, wph, proj_b,
                                                out, nullptr,
                                                M_TOTAL, DIMC, DIMC);
}

// round 15
// speedup vs baseline: 3.3173x; 1.0207x over previous
#include <cuda_runtime.h>
#include <cuda_fp16.h>
#include <cstdint>

// ---------------- problem constants ----------------
#define NB      2048
#define NTOK    49
#define DIMC    512
#define QKV_N   1536
#define NHEAD   16
#define HDIM    32
#define NWIN    64
#define M_TOTAL (NB * NTOK)   // 100352

// ---------------- scratch (no allocs allowed) ----------------
__device__ __half g_qvh[(size_t)M_TOTAL * QKV_N];   // qkv fp16
__device__ __half g_xhi[(size_t)M_TOTAL * DIMC];
__device__ __half g_ahi[(size_t)M_TOTAL * DIMC];
__device__ __half g_wq_h[(size_t)QKV_N * DIMC];
__device__ __half g_wp_h[(size_t)DIMC * DIMC];
__device__ __half g_comb[(size_t)NWIN * NHEAD * 64 * 64];  // bias+mask fp16, pad -60000

// ---------------- helpers ----------------
__device__ __forceinline__ uint32_t smem_to_u32(const void* p) {
    uint32_t a;
    asm("{ .reg .u64 t; cvta.to.shared.u64 t, %1; cvt.u32.u64 %0, t; }" : "=r"(a) : "l"(p));
    return a;
}
__device__ __forceinline__ void cp_async16(uint32_t saddr, const void* gaddr) {
    asm volatile("cp.async.cg.shared.global [%0], [%1], 16;" :: "r"(saddr), "l"(gaddr));
}
#define CP_COMMIT() asm volatile("cp.async.commit_group;")
#define CP_WAIT0()  asm volatile("cp.async.wait_group 0;")
#define CP_WAIT1()  asm volatile("cp.async.wait_group 1;")

__device__ __forceinline__ void ldsm4(uint32_t* r, uint32_t addr) {
    asm volatile("ldmatrix.sync.aligned.m8n8.x4.shared.b16 {%0,%1,%2,%3}, [%4];"
                 : "=r"(r[0]), "=r"(r[1]), "=r"(r[2]), "=r"(r[3]) : "r"(addr));
}
__device__ __forceinline__ void ldsm4t(uint32_t* r, uint32_t addr) {
    asm volatile("ldmatrix.sync.aligned.m8n8.x4.trans.shared.b16 {%0,%1,%2,%3}, [%4];"
                 : "=r"(r[0]), "=r"(r[1]), "=r"(r[2]), "=r"(r[3]) : "r"(addr));
}
__device__ __forceinline__ void mma16816(float* d, const uint32_t* a,
                                         uint32_t b0, uint32_t b1) {
    asm volatile(
        "mma.sync.aligned.m16n8k16.row.col.f32.f16.f16.f32 "
        "{%0,%1,%2,%3}, {%4,%5,%6,%7}, {%8,%9}, {%0,%1,%2,%3};"
        : "+f"(d[0]), "+f"(d[1]), "+f"(d[2]), "+f"(d[3])
        : "r"(a[0]), "r"(a[1]), "r"(a[2]), "r"(a[3]), "r"(b0), "r"(b1));
}
__device__ __forceinline__ uint32_t pack2(__half a, __half b) {
    __half2 t = __halves2half2(a, b);
    return *reinterpret_cast<uint32_t*>(&t);
}

// ---------------- conversion kernels ----------------
__global__ void __launch_bounds__(256) convert_h_kernel(
    const float* __restrict__ src, __half* __restrict__ hi, size_t n4)
{
    size_t i = (size_t)blockIdx.x * 256 + threadIdx.x;
    if (i >= n4) return;
    float4 v = reinterpret_cast<const float4*>(src)[i];
    uint2 uh{pack2(__float2half_rn(v.x), __float2half_rn(v.y)),
             pack2(__float2half_rn(v.z), __float2half_rn(v.w))};
    reinterpret_cast<uint2*>(hi)[i] = uh;
}

__global__ void __launch_bounds__(256) wh_t_kernel(
    const float* __restrict__ w, __half* __restrict__ hi, int K, int N)
{
    int idx = blockIdx.x * 256 + threadIdx.x;
    if (idx >= N * K) return;
    int n = idx / K, k = idx - n * K;
    hi[idx] = __float2half_rn(w[(size_t)k * N + n]);
}

// combined[w][h][64][64] = fp16(bias + mask), padded with -60000
__global__ void __launch_bounds__(256) combined_kernel(
    const float* __restrict__ bias_table, const int* __restrict__ rel_idx,
    const float* __restrict__ mask, __half* __restrict__ comb)
{
    const int w = blockIdx.x, h = blockIdx.y;
    __half* dst = comb + ((size_t)(w * NHEAD + h)) * 4096;
    for (int i = threadIdx.x; i < 4096; i += 256) {
        int n = i >> 6, m = i & 63;
        float v = -60000.f;
        if (n < NTOK && m < NTOK)
            v = bias_table[rel_idx[n * NTOK + m] * NHEAD + h]
              + mask[((size_t)w * NTOK + n) * NTOK + m];
        dst[i] = __float2half_rn(v);
    }
}

// ---------------- mma.sync plain fp16 GEMM: C = A @ B^T + bias -------------
#define STAGE_BYTES 32768
#define GEMM_SMEM   (2 * STAGE_BYTES)

__device__ __forceinline__ uint32_t sw_addr(uint32_t base, int row, int chunk) {
    return base + row * 128 + ((chunk ^ (row & 7)) << 4);
}

template<bool HOUT>
__global__ void __launch_bounds__(256, 2) gemm1_kernel(
    const __half* __restrict__ Ah, const __half* __restrict__ Bh,
    const float* __restrict__ bias, float* __restrict__ C,
    __half* __restrict__ Chi,
    int M, int N, int K)
{
    extern __shared__ char smem[];
    const uint32_t sbase = smem_to_u32(smem);
    const int tid  = threadIdx.x;
    const int lane = tid & 31;
    const int wid  = tid >> 5;
    const int warp_m = wid & 3;
    const int warp_n = wid >> 2;
    const int m0 = blockIdx.y * 128;
    const int n0 = blockIdx.x * 128;
    const int NKT = K >> 6;

    float acc[2][8][4];
    #pragma unroll
    for (int i = 0; i < 2; i++)
        #pragma unroll
        for (int j = 0; j < 8; j++)
            #pragma unroll
            for (int t = 0; t < 4; t++) acc[i][j][t] = 0.f;

    auto load_stage = [&](int kt, int s) {
        const uint32_t sb = sbase + s * STAGE_BYTES;
        const int kofs = kt * 64;
        #pragma unroll
        for (int i = 0; i < 4; i++) {
            int f   = tid + i * 256;
            int row = f >> 3;
            int c   = f & 7;
            uint32_t sw = sw_addr(0, row, c);
            size_t ga = (size_t)(m0 + row) * K + kofs + c * 8;
            size_t gb = (size_t)(n0 + row) * K + kofs + c * 8;
            cp_async16(sb + sw,         Ah + ga);
            cp_async16(sb + 16384 + sw, Bh + gb);
        }
        CP_COMMIT();
    };

    load_stage(0, 0);

    for (int kt = 0; kt < NKT; kt++) {
        const int s = kt & 1;
        CP_WAIT0();
        __syncthreads();
        if (kt + 1 < NKT) load_stage(kt + 1, s ^ 1);

        const uint32_t sA = sbase + s * STAGE_BYTES;
        const uint32_t sB = sA + 16384;

        #pragma unroll
        for (int ks = 0; ks < 4; ks++) {
            uint32_t ah[2][4];
            {
                const int arow = warp_m * 32 + (lane & 15);
                const int achk = 2 * ks + (lane >> 4);
                #pragma unroll
                for (int mt = 0; mt < 2; mt++)
                    ldsm4(ah[mt], sw_addr(sA, arow + mt * 16, achk));
            }
            uint32_t bh[4][4];
            {
                const int brow_base = warp_n * 64 + ((lane & 16) ? 8 : 0) + (lane & 7);
                const int bchk = 2 * ks + ((lane >> 3) & 1);
                #pragma unroll
                for (int p = 0; p < 4; p++)
                    ldsm4(bh[p], sw_addr(sB, brow_base + p * 16, bchk));
            }
            #pragma unroll
            for (int mt = 0; mt < 2; mt++)
                #pragma unroll
                for (int p = 0; p < 4; p++)
                    #pragma unroll
                    for (int hlf = 0; hlf < 2; hlf++)
                        mma16816(acc[mt][p * 2 + hlf], ah[mt],
                                 bh[p][hlf*2], bh[p][hlf*2+1]);
        }
        __syncthreads();
    }

    const int row0 = m0 + warp_m * 32 + (lane >> 2);
    const int col0 = n0 + warp_n * 64 + (lane & 3) * 2;
    #pragma unroll
    for (int mt = 0; mt < 2; mt++)
        #pragma unroll
        for (int nt = 0; nt < 8; nt++) {
            const int c = col0 + nt * 8;
            const float b0 = bias[c], b1 = bias[c + 1];
            const int r0 = row0 + mt * 16;
            float v00 = acc[mt][nt][0] + b0, v01 = acc[mt][nt][1] + b1;
            float v10 = acc[mt][nt][2] + b0, v11 = acc[mt][nt][3] + b1;
            if (HOUT) {
                *reinterpret_cast<uint32_t*>(Chi + (size_t)r0 * N + c) =
                    pack2(__float2half_rn(v00), __float2half_rn(v01));
                *reinterpret_cast<uint32_t*>(Chi + (size_t)(r0 + 8) * N + c) =
                    pack2(__float2half_rn(v10), __float2half_rn(v11));
            } else {
                *reinterpret_cast<float2*>(C + (size_t)r0 * N + c)       = float2{v00, v01};
                *reinterpret_cast<float2*>(C + (size_t)(r0 + 8) * N + c) = float2{v10, v11};
            }
        }
}

// ---------------- batched tensor-core window attention ---------------------
// Block = (win w, head h); loops over 32 batch replicas (b = 64*it + w).
// comb tile cached in smem once; Q/K/V double-buffered via cp.async.
#define AQ_STRIDE 40                     // halves per row
#define A_TENSOR  2560                   // 64 rows * 40 halves
#define A_STAGE   7680                   // Q+K+V
#define A_COMB    4096                   // comb halves
#define A_SM_HALVES (A_COMB + 2 * A_STAGE)   // 19456 halves = 38912 B
#define NITER     (NB / NWIN)            // 32

__global__ void __launch_bounds__(128) attn_mma_kernel(
    const __half* __restrict__ qvh, const __half* __restrict__ comb,
    __half* __restrict__ out_hi)
{
    const int w = blockIdx.x;
    const int h = blockIdx.y;
    const int tid  = threadIdx.x;
    const int lane = tid & 31;
    const int wid  = tid >> 5;

    __shared__ __align__(16) __half sm[A_SM_HALVES];

    // comb tile -> smem; zero the QKV pad rows (49..63) of both stages
    {
        const __half* cbg = comb + ((size_t)(w * NHEAD + h)) * 4096;
        for (int i = tid; i < A_COMB / 8; i += 128)
            reinterpret_cast<uint4*>(sm)[i] =
                reinterpret_cast<const uint4*>(cbg)[i];
        // pad rows: 2 stages * 3 tensors * 15 rows * 40 halves
        for (int i = tid; i < 2 * 3 * 15 * 5; i += 128) {
            int q8  = i % 5;                    // 5 x uint4 per 40-half row
            int row = (i / 5) % 15;
            int t   = (i / 75) % 3;
            int s   = i / 225;
            uint32_t off = A_COMB + s * A_STAGE + t * A_TENSOR
                         + (49 + row) * AQ_STRIDE + q8 * 8;
            *reinterpret_cast<uint4*>(sm + off) = uint4{0, 0, 0, 0};
        }
    }
    __syncthreads();

    auto load_win = [&](int it, int s) {
        const int b = 64 * it + w;
        const uint32_t sb = smem_to_u32(sm + A_COMB + s * A_STAGE);
        for (int i = tid; i < NTOK * 4; i += 128) {
            int n = i >> 2;
            int c = i & 3;                      // 16B chunk within 64B row
            const __half* src = qvh + (size_t)(b * NTOK + n) * QKV_N
                              + h * HDIM + c * 8;
            uint32_t dst = sb + (n * AQ_STRIDE + c * 8) * 2;
            cp_async16(dst,                  src);
            cp_async16(dst + A_TENSOR * 2,   src + DIMC);
            cp_async16(dst + 2 * A_TENSOR * 2, src + 2 * DIMC);
        }
        CP_COMMIT();
    };

    load_win(0, 0);

    const float scale = 0.17677669529663687f;
    const int r0 = wid * 16 + (lane >> 2);
    const int r1 = r0 + 8;
    const int cbase = 2 * (lane & 3);

    for (int it = 0; it < NITER; it++) {
        const int s = it & 1;
        if (it + 1 < NITER) { load_win(it + 1, s ^ 1); CP_WAIT1(); }
        else                { CP_WAIT0(); }
        __syncthreads();

        const uint32_t uQH = smem_to_u32(sm + A_COMB + s * A_STAGE);
        const uint32_t uKH = uQH + A_TENSOR * 2;
        const uint32_t uVH = uQH + 2 * A_TENSOR * 2;
        const int b = 64 * it + w;

        // ---- S = Q @ K^T ----
        float acc[8][4];
        #pragma unroll
        for (int nt = 0; nt < 8; nt++)
            #pragma unroll
            for (int t = 0; t < 4; t++) acc[nt][t] = 0.f;

        #pragma unroll
        for (int ks = 0; ks < 2; ks++) {
            uint32_t aqh[4];
            const int arow = wid * 16 + (lane & 15);
            const int achk = 2 * ks + (lane >> 4);
            ldsm4(aqh, uQH + (arow * AQ_STRIDE + achk * 8) * 2);
            #pragma unroll
            for (int p = 0; p < 4; p++) {
                uint32_t bkh[4];
                const int brow = p * 16 + ((lane & 16) ? 8 : 0) + (lane & 7);
                const int bchk = 2 * ks + ((lane >> 3) & 1);
                ldsm4(bkh, uKH + (brow * AQ_STRIDE + bchk * 8) * 2);
                #pragma unroll
                for (int hlf = 0; hlf < 2; hlf++)
                    mma16816(acc[p * 2 + hlf], aqh, bkh[hlf*2], bkh[hlf*2+1]);
            }
        }

        // ---- scale + comb (smem), softmax in fragments ----
        #pragma unroll
        for (int nt = 0; nt < 8; nt++) {
            uint32_t u0 = *reinterpret_cast<const uint32_t*>(sm + r0 * 64 + nt * 8 + cbase);
            uint32_t u1 = *reinterpret_cast<const uint32_t*>(sm + r1 * 64 + nt * 8 + cbase);
            float2 c0 = __half22float2(*reinterpret_cast<__half2*>(&u0));
            float2 c1 = __half22float2(*reinterpret_cast<__half2*>(&u1));
            acc[nt][0] = acc[nt][0] * scale + c0.x;
            acc[nt][1] = acc[nt][1] * scale + c0.y;
            acc[nt][2] = acc[nt][2] * scale + c1.x;
            acc[nt][3] = acc[nt][3] * scale + c1.y;
        }
        float mx0 = -1e30f, mx1 = -1e30f;
        #pragma unroll
        for (int nt = 0; nt < 8; nt++) {
            mx0 = fmaxf(mx0, fmaxf(acc[nt][0], acc[nt][1]));
            mx1 = fmaxf(mx1, fmaxf(acc[nt][2], acc[nt][3]));
        }
        mx0 = fmaxf(mx0, __shfl_xor_sync(0xffffffff, mx0, 1));
        mx0 = fmaxf(mx0, __shfl_xor_sync(0xffffffff, mx0, 2));
        mx1 = fmaxf(mx1, __shfl_xor_sync(0xffffffff, mx1, 1));
        mx1 = fmaxf(mx1, __shfl_xor_sync(0xffffffff, mx1, 2));
        float sum0 = 0.f, sum1 = 0.f;
        #pragma unroll
        for (int nt = 0; nt < 8; nt++) {
            acc[nt][0] = __expf(acc[nt][0] - mx0);
            acc[nt][1] = __expf(acc[nt][1] - mx0);
            acc[nt][2] = __expf(acc[nt][2] - mx1);
            acc[nt][3] = __expf(acc[nt][3] - mx1);
            sum0 += acc[nt][0] + acc[nt][1];
            sum1 += acc[nt][2] + acc[nt][3];
        }
        sum0 += __shfl_xor_sync(0xffffffff, sum0, 1);
        sum0 += __shfl_xor_sync(0xffffffff, sum0, 2);
        sum1 += __shfl_xor_sync(0xffffffff, sum1, 1);
        sum1 += __shfl_xor_sync(0xffffffff, sum1, 2);
        const float sinv0 = 1.f / sum0;
        const float sinv1 = 1.f / sum1;

        // ---- P fragments (fp16) ----
        uint32_t aph[4][4];
        #pragma unroll
        for (int kk = 0; kk < 4; kk++) {
            const int n0t = 2 * kk, n1t = 2 * kk + 1;
            aph[kk][0] = pack2(__float2half_rn(acc[n0t][0]), __float2half_rn(acc[n0t][1]));
            aph[kk][1] = pack2(__float2half_rn(acc[n0t][2]), __float2half_rn(acc[n0t][3]));
            aph[kk][2] = pack2(__float2half_rn(acc[n1t][0]), __float2half_rn(acc[n1t][1]));
            aph[kk][3] = pack2(__float2half_rn(acc[n1t][2]), __float2half_rn(acc[n1t][3]));
        }

        // ---- O = P @ V (V row-major, ldmatrix.trans) ----
        float oacc[4][4];
        #pragma unroll
        for (int nt = 0; nt < 4; nt++)
            #pragma unroll
            for (int t = 0; t < 4; t++) oacc[nt][t] = 0.f;

        #pragma unroll
        for (int ks = 0; ks < 4; ks++) {
            const int krow = ks * 16 + ((lane & 8) ? 8 : 0) + (lane & 7);
            #pragma unroll
            for (int p = 0; p < 2; p++) {
                uint32_t bvh[4];
                const int ncol = p * 16 + ((lane & 16) ? 8 : 0);
                ldsm4t(bvh, uVH + (krow * AQ_STRIDE + ncol) * 2);
                #pragma unroll
                for (int hlf = 0; hlf < 2; hlf++)
                    mma16816(oacc[p * 2 + hlf], aph[ks], bvh[hlf*2], bvh[hlf*2+1]);
            }
        }

        // ---- normalize + store (rows < 49 only) ----
        #pragma unroll
        for (int nt = 0; nt < 4; nt++) {
            const int d = nt * 8 + cbase;
            if (r0 < NTOK) {
                size_t base = (size_t)(b * NTOK + r0) * DIMC + h * HDIM + d;
                *reinterpret_cast<uint32_t*>(out_hi + base) =
                    pack2(__float2half_rn(oacc[nt][0] * sinv0),
                          __float2half_rn(oacc[nt][1] * sinv0));
            }
            if (r1 < NTOK) {
                size_t base = (size_t)(b * NTOK + r1) * DIMC + h * HDIM + d;
                *reinterpret_cast<uint32_t*>(out_hi + base) =
                    pack2(__float2half_rn(oacc[nt][2] * sinv1),
                          __float2half_rn(oacc[nt][3] * sinv1));
            }
        }
        __syncthreads();   // protect stage s before it's refilled at it+2
    }
}

// ---------------- launcher ----------------
extern "C" void kernel_launch(void* const* d_in, const int* in_sizes, int n_in,
                              void* d_out, int out_size)
{
    const float* x          = (const float*)d_in[0];
    const float* mask       = (const float*)d_in[1];
    const float* qkv_w      = (const float*)d_in[2];
    const float* qkv_b      = (const float*)d_in[3];
    const float* proj_w     = (const float*)d_in[4];
    const float* proj_b     = (const float*)d_in[5];
    const float* bias_table = (const float*)d_in[6];
    const int*   rel_idx    = (const int*)d_in[7];
    float* out = (float*)d_out;

    __half *qvh, *xhi, *ahi, *wqh, *wph, *comb;
    cudaGetSymbolAddress((void**)&qvh, g_qvh);
    cudaGetSymbolAddress((void**)&xhi, g_xhi);
    cudaGetSymbolAddress((void**)&ahi, g_ahi);
    cudaGetSymbolAddress((void**)&wqh, g_wq_h);
    cudaGetSymbolAddress((void**)&wph, g_wp_h);
    cudaGetSymbolAddress((void**)&comb, g_comb);

    cudaFuncSetAttribute(gemm1_kernel<true>,  cudaFuncAttributeMaxDynamicSharedMemorySize, GEMM_SMEM);
    cudaFuncSetAttribute(gemm1_kernel<false>, cudaFuncAttributeMaxDynamicSharedMemorySize, GEMM_SMEM);

    size_t n4 = (size_t)M_TOTAL * DIMC / 4;
    convert_h_kernel<<<(unsigned)((n4 + 255) / 256), 256>>>(x, xhi, n4);
    wh_t_kernel<<<(QKV_N * DIMC + 255) / 256, 256>>>(qkv_w, wqh, DIMC, QKV_N);
    wh_t_kernel<<<(DIMC * DIMC + 255) / 256, 256>>>(proj_w, wph, DIMC, DIMC);
    combined_kernel<<<dim3(NWIN, NHEAD), 256>>>(bias_table, rel_idx, mask, comb);

    // 1) QKV projection -> fp16
    dim3 g1(QKV_N / 128, M_TOTAL / 128);
    gemm1_kernel<true><<<g1, 256, GEMM_SMEM>>>(xhi, wqh, qkv_b,
                                               nullptr, qvh,
                                               M_TOTAL, QKV_N, DIMC);

    // 2) batched tensor-core window attention -> fp16
    dim3 g2(NWIN, NHEAD);
    attn_mma_kernel<<<g2, 128>>>(qvh, comb, ahi);

    // 3) output projection -> fp32
    dim3 g3(DIMC / 128, M_TOTAL / 128);
    gemm1_kernel<false><<<g3, 256, GEMM_SMEM>>>(ahi, wph, proj_b,
                                                out, nullptr,
                                                M_TOTAL, DIMC, DIMC);
}

// round 16
// speedup vs baseline: 3.3683x; 1.0154x over previous
#include <cuda_runtime.h>
#include <cuda_fp16.h>
#include <cstdint>

// ---------------- problem constants ----------------
#define NB      2048
#define NTOK    49
#define DIMC    512
#define QKV_N   1536
#define NHEAD   16
#define HDIM    32
#define NWIN    64
#define M_TOTAL (NB * NTOK)   // 100352

// ---------------- scratch (no allocs allowed) ----------------
__device__ __half g_qvh[(size_t)M_TOTAL * QKV_N];   // qkv fp16
__device__ __half g_xhi[(size_t)M_TOTAL * DIMC];
__device__ __half g_ahi[(size_t)M_TOTAL * DIMC];
__device__ __half g_wq_h[(size_t)QKV_N * DIMC];
__device__ __half g_wp_h[(size_t)DIMC * DIMC];
__device__ __half g_comb[(size_t)NWIN * NHEAD * 64 * 64];  // bias+mask fp16, pad -60000

// ---------------- helpers ----------------
__device__ __forceinline__ uint32_t smem_to_u32(const void* p) {
    uint32_t a;
    asm("{ .reg .u64 t; cvta.to.shared.u64 t, %1; cvt.u32.u64 %0, t; }" : "=r"(a) : "l"(p));
    return a;
}
__device__ __forceinline__ void cp_async16(uint32_t saddr, const void* gaddr) {
    asm volatile("cp.async.cg.shared.global [%0], [%1], 16;" :: "r"(saddr), "l"(gaddr));
}
#define CP_COMMIT() asm volatile("cp.async.commit_group;")
#define CP_WAIT0()  asm volatile("cp.async.wait_group 0;")
#define CP_WAIT1()  asm volatile("cp.async.wait_group 1;")

__device__ __forceinline__ void ldsm4(uint32_t* r, uint32_t addr) {
    asm volatile("ldmatrix.sync.aligned.m8n8.x4.shared.b16 {%0,%1,%2,%3}, [%4];"
                 : "=r"(r[0]), "=r"(r[1]), "=r"(r[2]), "=r"(r[3]) : "r"(addr));
}
__device__ __forceinline__ void ldsm4t(uint32_t* r, uint32_t addr) {
    asm volatile("ldmatrix.sync.aligned.m8n8.x4.trans.shared.b16 {%0,%1,%2,%3}, [%4];"
                 : "=r"(r[0]), "=r"(r[1]), "=r"(r[2]), "=r"(r[3]) : "r"(addr));
}
__device__ __forceinline__ void mma16816(float* d, const uint32_t* a,
                                         uint32_t b0, uint32_t b1) {
    asm volatile(
        "mma.sync.aligned.m16n8k16.row.col.f32.f16.f16.f32 "
        "{%0,%1,%2,%3}, {%4,%5,%6,%7}, {%8,%9}, {%0,%1,%2,%3};"
        : "+f"(d[0]), "+f"(d[1]), "+f"(d[2]), "+f"(d[3])
        : "r"(a[0]), "r"(a[1]), "r"(a[2]), "r"(a[3]), "r"(b0), "r"(b1));
}
__device__ __forceinline__ uint32_t pack2(__half a, __half b) {
    __half2 t = __halves2half2(a, b);
    return *reinterpret_cast<uint32_t*>(&t);
}

// ---------------- conversion kernels ----------------
__global__ void __launch_bounds__(256) convert_h_kernel(
    const float* __restrict__ src, __half* __restrict__ hi, size_t n4)
{
    size_t i = (size_t)blockIdx.x * 256 + threadIdx.x;
    if (i >= n4) return;
    float4 v = reinterpret_cast<const float4*>(src)[i];
    uint2 uh{pack2(__float2half_rn(v.x), __float2half_rn(v.y)),
             pack2(__float2half_rn(v.z), __float2half_rn(v.w))};
    reinterpret_cast<uint2*>(hi)[i] = uh;
}

__global__ void __launch_bounds__(256) wh_t_kernel(
    const float* __restrict__ w, __half* __restrict__ hi, int K, int N)
{
    int idx = blockIdx.x * 256 + threadIdx.x;
    if (idx >= N * K) return;
    int n = idx / K, k = idx - n * K;
    hi[idx] = __float2half_rn(w[(size_t)k * N + n]);
}

// combined[w][h][64][64] = fp16(bias + mask), padded with -60000
__global__ void __launch_bounds__(256) combined_kernel(
    const float* __restrict__ bias_table, const int* __restrict__ rel_idx,
    const float* __restrict__ mask, __half* __restrict__ comb)
{
    const int w = blockIdx.x, h = blockIdx.y;
    __half* dst = comb + ((size_t)(w * NHEAD + h)) * 4096;
    for (int i = threadIdx.x; i < 4096; i += 256) {
        int n = i >> 6, m = i & 63;
        float v = -60000.f;
        if (n < NTOK && m < NTOK)
            v = bias_table[rel_idx[n * NTOK + m] * NHEAD + h]
              + mask[((size_t)w * NTOK + n) * NTOK + m];
        dst[i] = __float2half_rn(v);
    }
}

// ---------------- mma.sync plain fp16 GEMM: C = A @ B^T + bias -------------
#define STAGE_BYTES 32768
#define GEMM_SMEM   (2 * STAGE_BYTES)

__device__ __forceinline__ uint32_t sw_addr(uint32_t base, int row, int chunk) {
    return base + row * 128 + ((chunk ^ (row & 7)) << 4);
}

template<bool HOUT>
__global__ void __launch_bounds__(256, 2) gemm1_kernel(
    const __half* __restrict__ Ah, const __half* __restrict__ Bh,
    const float* __restrict__ bias, float* __restrict__ C,
    __half* __restrict__ Chi,
    int M, int N, int K)
{
    extern __shared__ char smem[];
    const uint32_t sbase = smem_to_u32(smem);
    const int tid  = threadIdx.x;
    const int lane = tid & 31;
    const int wid  = tid >> 5;
    const int warp_m = wid & 3;
    const int warp_n = wid >> 2;
    const int m0 = blockIdx.y * 128;
    const int n0 = blockIdx.x * 128;
    const int NKT = K >> 6;

    float acc[2][8][4];
    #pragma unroll
    for (int i = 0; i < 2; i++)
        #pragma unroll
        for (int j = 0; j < 8; j++)
            #pragma unroll
            for (int t = 0; t < 4; t++) acc[i][j][t] = 0.f;

    auto load_stage = [&](int kt, int s) {
        const uint32_t sb = sbase + s * STAGE_BYTES;
        const int kofs = kt * 64;
        #pragma unroll
        for (int i = 0; i < 4; i++) {
            int f   = tid + i * 256;
            int row = f >> 3;
            int c   = f & 7;
            uint32_t sw = sw_addr(0, row, c);
            size_t ga = (size_t)(m0 + row) * K + kofs + c * 8;
            size_t gb = (size_t)(n0 + row) * K + kofs + c * 8;
            cp_async16(sb + sw,         Ah + ga);
            cp_async16(sb + 16384 + sw, Bh + gb);
        }
        CP_COMMIT();
    };

    load_stage(0, 0);

    for (int kt = 0; kt < NKT; kt++) {
        const int s = kt & 1;
        CP_WAIT0();
        __syncthreads();
        if (kt + 1 < NKT) load_stage(kt + 1, s ^ 1);

        const uint32_t sA = sbase + s * STAGE_BYTES;
        const uint32_t sB = sA + 16384;

        #pragma unroll
        for (int ks = 0; ks < 4; ks++) {
            uint32_t ah[2][4];
            {
                const int arow = warp_m * 32 + (lane & 15);
                const int achk = 2 * ks + (lane >> 4);
                #pragma unroll
                for (int mt = 0; mt < 2; mt++)
                    ldsm4(ah[mt], sw_addr(sA, arow + mt * 16, achk));
            }
            uint32_t bh[4][4];
            {
                const int brow_base = warp_n * 64 + ((lane & 16) ? 8 : 0) + (lane & 7);
                const int bchk = 2 * ks + ((lane >> 3) & 1);
                #pragma unroll
                for (int p = 0; p < 4; p++)
                    ldsm4(bh[p], sw_addr(sB, brow_base + p * 16, bchk));
            }
            #pragma unroll
            for (int mt = 0; mt < 2; mt++)
                #pragma unroll
                for (int p = 0; p < 4; p++)
                    #pragma unroll
                    for (int hlf = 0; hlf < 2; hlf++)
                        mma16816(acc[mt][p * 2 + hlf], ah[mt],
                                 bh[p][hlf*2], bh[p][hlf*2+1]);
        }
        __syncthreads();
    }

    const int row0 = m0 + warp_m * 32 + (lane >> 2);
    const int col0 = n0 + warp_n * 64 + (lane & 3) * 2;
    #pragma unroll
    for (int mt = 0; mt < 2; mt++)
        #pragma unroll
        for (int nt = 0; nt < 8; nt++) {
            const int c = col0 + nt * 8;
            const float b0 = bias[c], b1 = bias[c + 1];
            const int r0 = row0 + mt * 16;
            float v00 = acc[mt][nt][0] + b0, v01 = acc[mt][nt][1] + b1;
            float v10 = acc[mt][nt][2] + b0, v11 = acc[mt][nt][3] + b1;
            if (HOUT) {
                *reinterpret_cast<uint32_t*>(Chi + (size_t)r0 * N + c) =
                    pack2(__float2half_rn(v00), __float2half_rn(v01));
                *reinterpret_cast<uint32_t*>(Chi + (size_t)(r0 + 8) * N + c) =
                    pack2(__float2half_rn(v10), __float2half_rn(v11));
            } else {
                *reinterpret_cast<float2*>(C + (size_t)r0 * N + c)       = float2{v00, v01};
                *reinterpret_cast<float2*>(C + (size_t)(r0 + 8) * N + c) = float2{v10, v11};
            }
        }
}

// ---------------- batched tensor-core window attention ---------------------
// Block = (win w, head h, z-slice); each handles NITER_PER batch replicas.
// comb tile cached in smem; Q/K/V double-buffered via cp.async.
#define AQ_STRIDE 40                     // halves per row
#define A_TENSOR  2560                   // 64 rows * 40 halves
#define A_STAGE   7680                   // Q+K+V
#define A_COMB    4096                   // comb halves
#define A_SM_HALVES (A_COMB + 2 * A_STAGE)   // 19456 halves = 38912 B
#define NZ        4
#define NITER_PER (NB / NWIN / NZ)       // 8

__global__ void __launch_bounds__(128) attn_mma_kernel(
    const __half* __restrict__ qvh, const __half* __restrict__ comb,
    __half* __restrict__ out_hi)
{
    const int w = blockIdx.x;
    const int h = blockIdx.y;
    const int z = blockIdx.z;
    const int tid  = threadIdx.x;
    const int lane = tid & 31;
    const int wid  = tid >> 5;

    __shared__ __align__(16) __half sm[A_SM_HALVES];

    // comb tile -> smem; zero the QKV pad rows (49..63) of both stages
    {
        const __half* cbg = comb + ((size_t)(w * NHEAD + h)) * 4096;
        for (int i = tid; i < A_COMB / 8; i += 128)
            reinterpret_cast<uint4*>(sm)[i] =
                reinterpret_cast<const uint4*>(cbg)[i];
        for (int i = tid; i < 2 * 3 * 15 * 5; i += 128) {
            int q8  = i % 5;
            int row = (i / 5) % 15;
            int t   = (i / 75) % 3;
            int s   = i / 225;
            uint32_t off = A_COMB + s * A_STAGE + t * A_TENSOR
                         + (49 + row) * AQ_STRIDE + q8 * 8;
            *reinterpret_cast<uint4*>(sm + off) = uint4{0, 0, 0, 0};
        }
    }
    __syncthreads();

    auto load_win = [&](int it, int s) {
        const int b = 64 * (z * NITER_PER + it) + w;
        const uint32_t sb = smem_to_u32(sm + A_COMB + s * A_STAGE);
        for (int i = tid; i < NTOK * 4; i += 128) {
            int n = i >> 2;
            int c = i & 3;
            const __half* src = qvh + (size_t)(b * NTOK + n) * QKV_N
                              + h * HDIM + c * 8;
            uint32_t dst = sb + (n * AQ_STRIDE + c * 8) * 2;
            cp_async16(dst,                    src);
            cp_async16(dst + A_TENSOR * 2,     src + DIMC);
            cp_async16(dst + 2 * A_TENSOR * 2, src + 2 * DIMC);
        }
        CP_COMMIT();
    };

    load_win(0, 0);

    const float scale = 0.17677669529663687f;
    const int r0 = wid * 16 + (lane >> 2);
    const int r1 = r0 + 8;
    const int cbase = 2 * (lane & 3);

    for (int it = 0; it < NITER_PER; it++) {
        const int s = it & 1;
        if (it + 1 < NITER_PER) { load_win(it + 1, s ^ 1); CP_WAIT1(); }
        else                    { CP_WAIT0(); }
        __syncthreads();

        const uint32_t uQH = smem_to_u32(sm + A_COMB + s * A_STAGE);
        const uint32_t uKH = uQH + A_TENSOR * 2;
        const uint32_t uVH = uQH + 2 * A_TENSOR * 2;
        const int b = 64 * (z * NITER_PER + it) + w;

        // ---- S = Q @ K^T ----
        float acc[8][4];
        #pragma unroll
        for (int nt = 0; nt < 8; nt++)
            #pragma unroll
            for (int t = 0; t < 4; t++) acc[nt][t] = 0.f;

        #pragma unroll
        for (int ks = 0; ks < 2; ks++) {
            uint32_t aqh[4];
            const int arow = wid * 16 + (lane & 15);
            const int achk = 2 * ks + (lane >> 4);
            ldsm4(aqh, uQH + (arow * AQ_STRIDE + achk * 8) * 2);
            #pragma unroll
            for (int p = 0; p < 4; p++) {
                uint32_t bkh[4];
                const int brow = p * 16 + ((lane & 16) ? 8 : 0) + (lane & 7);
                const int bchk = 2 * ks + ((lane >> 3) & 1);
                ldsm4(bkh, uKH + (brow * AQ_STRIDE + bchk * 8) * 2);
                #pragma unroll
                for (int hlf = 0; hlf < 2; hlf++)
                    mma16816(acc[p * 2 + hlf], aqh, bkh[hlf*2], bkh[hlf*2+1]);
            }
        }

        // ---- scale + comb (smem), softmax in fragments ----
        #pragma unroll
        for (int nt = 0; nt < 8; nt++) {
            uint32_t u0 = *reinterpret_cast<const uint32_t*>(sm + r0 * 64 + nt * 8 + cbase);
            uint32_t u1 = *reinterpret_cast<const uint32_t*>(sm + r1 * 64 + nt * 8 + cbase);
            float2 c0 = __half22float2(*reinterpret_cast<__half2*>(&u0));
            float2 c1 = __half22float2(*reinterpret_cast<__half2*>(&u1));
            acc[nt][0] = acc[nt][0] * scale + c0.x;
            acc[nt][1] = acc[nt][1] * scale + c0.y;
            acc[nt][2] = acc[nt][2] * scale + c1.x;
            acc[nt][3] = acc[nt][3] * scale + c1.y;
        }
        float mx0 = -1e30f, mx1 = -1e30f;
        #pragma unroll
        for (int nt = 0; nt < 8; nt++) {
            mx0 = fmaxf(mx0, fmaxf(acc[nt][0], acc[nt][1]));
            mx1 = fmaxf(mx1, fmaxf(acc[nt][2], acc[nt][3]));
        }
        mx0 = fmaxf(mx0, __shfl_xor_sync(0xffffffff, mx0, 1));
        mx0 = fmaxf(mx0, __shfl_xor_sync(0xffffffff, mx0, 2));
        mx1 = fmaxf(mx1, __shfl_xor_sync(0xffffffff, mx1, 1));
        mx1 = fmaxf(mx1, __shfl_xor_sync(0xffffffff, mx1, 2));
        float sum0 = 0.f, sum1 = 0.f;
        #pragma unroll
        for (int nt = 0; nt < 8; nt++) {
            acc[nt][0] = __expf(acc[nt][0] - mx0);
            acc[nt][1] = __expf(acc[nt][1] - mx0);
            acc[nt][2] = __expf(acc[nt][2] - mx1);
            acc[nt][3] = __expf(acc[nt][3] - mx1);
            sum0 += acc[nt][0] + acc[nt][1];
            sum1 += acc[nt][2] + acc[nt][3];
        }
        sum0 += __shfl_xor_sync(0xffffffff, sum0, 1);
        sum0 += __shfl_xor_sync(0xffffffff, sum0, 2);
        sum1 += __shfl_xor_sync(0xffffffff, sum1, 1);
        sum1 += __shfl_xor_sync(0xffffffff, sum1, 2);
        const float sinv0 = 1.f / sum0;
        const float sinv1 = 1.f / sum1;

        // ---- P fragments (fp16) ----
        uint32_t aph[4][4];
        #pragma unroll
        for (int kk = 0; kk < 4; kk++) {
            const int n0t = 2 * kk, n1t = 2 * kk + 1;
            aph[kk][0] = pack2(__float2half_rn(acc[n0t][0]), __float2half_rn(acc[n0t][1]));
            aph[kk][1] = pack2(__float2half_rn(acc[n0t][2]), __float2half_rn(acc[n0t][3]));
            aph[kk][2] = pack2(__float2half_rn(acc[n1t][0]), __float2half_rn(acc[n1t][1]));
            aph[kk][3] = pack2(__float2half_rn(acc[n1t][2]), __float2half_rn(acc[n1t][3]));
        }

        // ---- O = P @ V (V row-major, ldmatrix.trans) ----
        float oacc[4][4];
        #pragma unroll
        for (int nt = 0; nt < 4; nt++)
            #pragma unroll
            for (int t = 0; t < 4; t++) oacc[nt][t] = 0.f;

        #pragma unroll
        for (int ks = 0; ks < 4; ks++) {
            const int krow = ks * 16 + ((lane & 8) ? 8 : 0) + (lane & 7);
            #pragma unroll
            for (int p = 0; p < 2; p++) {
                uint32_t bvh[4];
                const int ncol = p * 16 + ((lane & 16) ? 8 : 0);
                ldsm4t(bvh, uVH + (krow * AQ_STRIDE + ncol) * 2);
                #pragma unroll
                for (int hlf = 0; hlf < 2; hlf++)
                    mma16816(oacc[p * 2 + hlf], aph[ks], bvh[hlf*2], bvh[hlf*2+1]);
            }
        }

        // ---- normalize + store (rows < 49 only) ----
        #pragma unroll
        for (int nt = 0; nt < 4; nt++) {
            const int d = nt * 8 + cbase;
            if (r0 < NTOK) {
                size_t base = (size_t)(b * NTOK + r0) * DIMC + h * HDIM + d;
                *reinterpret_cast<uint32_t*>(out_hi + base) =
                    pack2(__float2half_rn(oacc[nt][0] * sinv0),
                          __float2half_rn(oacc[nt][1] * sinv0));
            }
            if (r1 < NTOK) {
                size_t base = (size_t)(b * NTOK + r1) * DIMC + h * HDIM + d;
                *reinterpret_cast<uint32_t*>(out_hi + base) =
                    pack2(__float2half_rn(oacc[nt][2] * sinv1),
                          __float2half_rn(oacc[nt][3] * sinv1));
            }
        }
        __syncthreads();   // protect stage s before it's refilled at it+2
    }
}

// ---------------- launcher ----------------
extern "C" void kernel_launch(void* const* d_in, const int* in_sizes, int n_in,
                              void* d_out, int out_size)
{
    const float* x          = (const float*)d_in[0];
    const float* mask       = (const float*)d_in[1];
    const float* qkv_w      = (const float*)d_in[2];
    const float* qkv_b      = (const float*)d_in[3];
    const float* proj_w     = (const float*)d_in[4];
    const float* proj_b     = (const float*)d_in[5];
    const float* bias_table = (const float*)d_in[6];
    const int*   rel_idx    = (const int*)d_in[7];
    float* out = (float*)d_out;

    __half *qvh, *xhi, *ahi, *wqh, *wph, *comb;
    cudaGetSymbolAddress((void**)&qvh, g_qvh);
    cudaGetSymbolAddress((void**)&xhi, g_xhi);
    cudaGetSymbolAddress((void**)&ahi, g_ahi);
    cudaGetSymbolAddress((void**)&wqh, g_wq_h);
    cudaGetSymbolAddress((void**)&wph, g_wp_h);
    cudaGetSymbolAddress((void**)&comb, g_comb);

    cudaFuncSetAttribute(gemm1_kernel<true>,  cudaFuncAttributeMaxDynamicSharedMemorySize, GEMM_SMEM);
    cudaFuncSetAttribute(gemm1_kernel<false>, cudaFuncAttributeMaxDynamicSharedMemorySize, GEMM_SMEM);

    size_t n4 = (size_t)M_TOTAL * DIMC / 4;
    convert_h_kernel<<<(unsigned)((n4 + 255) / 256), 256>>>(x, xhi, n4);
    wh_t_kernel<<<(QKV_N * DIMC + 255) / 256, 256>>>(qkv_w, wqh, DIMC, QKV_N);
    wh_t_kernel<<<(DIMC * DIMC + 255) / 256, 256>>>(proj_w, wph, DIMC, DIMC);
    combined_kernel<<<dim3(NWIN, NHEAD), 256>>>(bias_table, rel_idx, mask, comb);

    // 1) QKV projection -> fp16
    dim3 g1(QKV_N / 128, M_TOTAL / 128);
    gemm1_kernel<true><<<g1, 256, GEMM_SMEM>>>(xhi, wqh, qkv_b,
                                               nullptr, qvh,
                                               M_TOTAL, QKV_N, DIMC);

    // 2) batched tensor-core window attention -> fp16
    dim3 g2(NWIN, NHEAD, NZ);
    attn_mma_kernel<<<g2, 128>>>(qvh, comb, ahi);

    // 3) output projection -> fp32
    dim3 g3(DIMC / 128, M_TOTAL / 128);
    gemm1_kernel<false><<<g3, 256, GEMM_SMEM>>>(ahi, wph, proj_b,
                                                out, nullptr,
                                                M_TOTAL, DIMC, DIMC);
}